// round 1
// baseline (speedup 1.0000x reference)
#include <cuda_runtime.h>
#include <math.h>

// Problem constants
#define Bc 4
#define Sc 1024
#define Dc 1024
#define Hc 8
#define DKc 128
#define FFc 4096
#define TOK (Bc*Sc)            // 4096 token rows

// ---------------- scratch (device globals; no allocation allowed) ----------
__device__ float g_xn [TOK*Dc];            // 16 MB
__device__ float g_q  [TOK*Dc];            // 16 MB
__device__ float g_k  [TOK*Dc];            // 16 MB
__device__ float g_v  [TOK*Hc*Dc];         // 128 MB  [B,S,H*D]
__device__ float g_p  [Bc*Hc*Sc*Sc];       // 128 MB  scores/probs
__device__ float g_ctx[Bc*Hc*Sc*Dc];       // 128 MB  [B,H,S,D]
__device__ float g_x1 [TOK*Dc];            // 16 MB
__device__ float g_xn2[TOK*Dc];            // 16 MB
__device__ float g_ff [TOK*FFc];           // 64 MB

// ---------------- tiled SGEMM ----------------------------------------------
// C[z] = act( alpha * A[z] @ op(B[z]) + bias ) + resid
// A: [M,K] row-major (lda). TB=false: B is [K,N] (ldb). TB=true: B is [N,K] (ldb), used transposed.
// Batch z decomposed as zo = z/innerB, zi = z%innerB with separate strides.
#define BM 128
#define BN 128
#define BKq 16
#define TM 8
#define TN 8

template<bool TB>
__global__ void __launch_bounds__(256)
gemm_kernel(const float* __restrict__ A, const float* __restrict__ Bm,
            const float* __restrict__ bias, const float* __restrict__ resid,
            float* __restrict__ C,
            int M, int N, int K, int lda, int ldb, int ldc,
            long long sA0, long long sA1, long long sB0, long long sB1,
            long long sC0, long long sC1, int innerB,
            float alpha, int act)
{
    const int z  = blockIdx.z;
    const int zo = z / innerB, zi = z % innerB;
    A  += zo*sA0 + zi*sA1;
    Bm += zo*sB0 + zi*sB1;
    C  += zo*sC0 + zi*sC1;

    __shared__ float As[BKq][BM];
    __shared__ float Bs[BKq][BN];

    const int tid = threadIdx.x;
    const int m0 = blockIdx.y * BM;
    const int n0 = blockIdx.x * BN;
    const int ty = tid >> 4;     // 0..15
    const int tx = tid & 15;     // 0..15

    float acc[TM][TN] = {};

    for (int k0 = 0; k0 < K; k0 += BKq) {
        // ---- load A tile (128 x 16), transposed into As[k][m] ----
        {
            int f = tid;
            #pragma unroll
            for (int r = 0; r < 2; r++, f += 256) {
                int row = f >> 2;
                int c4  = (f & 3) * 4;
                float4 v = *(const float4*)(A + (long long)(m0 + row) * lda + k0 + c4);
                As[c4+0][row] = v.x; As[c4+1][row] = v.y;
                As[c4+2][row] = v.z; As[c4+3][row] = v.w;
            }
        }
        // ---- load B tile into Bs[k][n] ----
        if (TB) {
            // B is [N,K]; tile rows n0..n0+127, cols k0..k0+15
            int f = tid;
            #pragma unroll
            for (int r = 0; r < 2; r++, f += 256) {
                int row = f >> 2;            // n within tile
                int c4  = (f & 3) * 4;       // k within tile
                float4 v = *(const float4*)(Bm + (long long)(n0 + row) * ldb + k0 + c4);
                Bs[c4+0][row] = v.x; Bs[c4+1][row] = v.y;
                Bs[c4+2][row] = v.z; Bs[c4+3][row] = v.w;
            }
        } else {
            // B is [K,N]; tile rows k0..k0+15, cols n0..n0+127
            int f = tid;
            #pragma unroll
            for (int r = 0; r < 2; r++, f += 256) {
                int row = f >> 5;            // k within tile (0..15)
                int c4  = (f & 31) * 4;      // n within tile
                float4 v = *(const float4*)(Bm + (long long)(k0 + row) * ldb + n0 + c4);
                *(float4*)&Bs[row][c4] = v;
            }
        }
        __syncthreads();

        // ---- compute ----
        #pragma unroll
        for (int kk = 0; kk < BKq; kk++) {
            float a[TM], b[TN];
            *(float4*)&a[0] = *(const float4*)&As[kk][ty*TM];
            *(float4*)&a[4] = *(const float4*)&As[kk][ty*TM + 4];
            *(float4*)&b[0] = *(const float4*)&Bs[kk][tx*TN];
            *(float4*)&b[4] = *(const float4*)&Bs[kk][tx*TN + 4];
            #pragma unroll
            for (int i = 0; i < TM; i++)
                #pragma unroll
                for (int j = 0; j < TN; j++)
                    acc[i][j] = fmaf(a[i], b[j], acc[i][j]);
        }
        __syncthreads();
    }

    // ---- epilogue ----
    float bj[TN];
    #pragma unroll
    for (int j = 0; j < TN; j++)
        bj[j] = bias ? bias[n0 + tx*TN + j] : 0.0f;

    #pragma unroll
    for (int i = 0; i < TM; i++) {
        int m = m0 + ty*TM + i;
        float*       crow = C + (long long)m * ldc + n0 + tx*TN;
        const float* rrow = resid ? (resid + (long long)m * ldc + n0 + tx*TN) : nullptr;
        float outv[TN];
        #pragma unroll
        for (int j = 0; j < TN; j++) {
            float vv = acc[i][j] * alpha + bj[j];
            if (act == 1)   // exact GELU
                vv = 0.5f * vv * (1.0f + erff(vv * 0.70710678118654752f));
            if (rrow) vv += rrow[j];
            outv[j] = vv;
        }
        *(float4*)&crow[0] = *(float4*)&outv[0];
        *(float4*)&crow[4] = *(float4*)&outv[4];
    }
}

// ---------------- layernorm: one block per row of 1024 ---------------------
__global__ void __launch_bounds__(256)
ln_kernel(const float* __restrict__ x, const float* __restrict__ g,
          const float* __restrict__ b, float* __restrict__ out)
{
    const long long row = blockIdx.x;
    const float* xr = x + row * Dc;
    const int tid = threadIdx.x;

    float4 v = *(const float4*)&xr[tid * 4];
    float s  = v.x + v.y + v.z + v.w;
    float ss = v.x*v.x + v.y*v.y + v.z*v.z + v.w*v.w;

    __shared__ float shs[8], shq[8];
    #pragma unroll
    for (int o = 16; o; o >>= 1) {
        s  += __shfl_xor_sync(0xffffffffu, s,  o);
        ss += __shfl_xor_sync(0xffffffffu, ss, o);
    }
    if ((tid & 31) == 0) { shs[tid >> 5] = s; shq[tid >> 5] = ss; }
    __syncthreads();
    float st = 0.f, qt = 0.f;
    #pragma unroll
    for (int i = 0; i < 8; i++) { st += shs[i]; qt += shq[i]; }

    const float m   = st * (1.0f / Dc);
    const float var = qt * (1.0f / Dc) - m * m;
    const float inv = rsqrtf(var + 1e-5f);

    float4 gv = *(const float4*)&g[tid * 4];
    float4 bv = *(const float4*)&b[tid * 4];
    float4 o4;
    o4.x = (v.x - m) * inv * gv.x + bv.x;
    o4.y = (v.y - m) * inv * gv.y + bv.y;
    o4.z = (v.z - m) * inv * gv.z + bv.z;
    o4.w = (v.w - m) * inv * gv.w + bv.w;
    *(float4*)&out[row * Dc + tid * 4] = o4;
}

// ---------------- softmax over rows of length 1024 --------------------------
__global__ void __launch_bounds__(256)
softmax_kernel(float* __restrict__ p)
{
    const long long row = blockIdx.x;
    float* r = p + row * 1024;
    const int tid = threadIdx.x;

    float4 v = *(const float4*)&r[tid * 4];
    float mx = fmaxf(fmaxf(v.x, v.y), fmaxf(v.z, v.w));

    __shared__ float sh[8];
    #pragma unroll
    for (int o = 16; o; o >>= 1) mx = fmaxf(mx, __shfl_xor_sync(0xffffffffu, mx, o));
    if ((tid & 31) == 0) sh[tid >> 5] = mx;
    __syncthreads();
    float m = sh[0];
    #pragma unroll
    for (int i = 1; i < 8; i++) m = fmaxf(m, sh[i]);
    __syncthreads();

    v.x = __expf(v.x - m); v.y = __expf(v.y - m);
    v.z = __expf(v.z - m); v.w = __expf(v.w - m);
    float s = v.x + v.y + v.z + v.w;
    #pragma unroll
    for (int o = 16; o; o >>= 1) s += __shfl_xor_sync(0xffffffffu, s, o);
    if ((tid & 31) == 0) sh[tid >> 5] = s;
    __syncthreads();
    float tot = 0.f;
    #pragma unroll
    for (int i = 0; i < 8; i++) tot += sh[i];

    const float inv = 1.0f / tot;
    v.x *= inv; v.y *= inv; v.z *= inv; v.w *= inv;
    *(float4*)&r[tid * 4] = v;
}

// ---------------- head-sum + residual ---------------------------------------
// attn_out_flat[o] = sum_{h<8} ctx_flat[o*8 + h]   (exact index algebra of the
// reference's reshape(S,B,D,H).sum(-1) on the contiguous [B,H,S,D] tensor)
__global__ void __launch_bounds__(256)
headsum_kernel(const float* __restrict__ ctx, const float* __restrict__ x,
               float* __restrict__ x1)
{
    const long long o = (long long)blockIdx.x * blockDim.x + threadIdx.x;
    const float4* c = (const float4*)(ctx + o * 8);
    float4 a = c[0], b = c[1];
    x1[o] = x[o] + (a.x + a.y + a.z + a.w + b.x + b.y + b.z + b.w);
}

// ---------------- launcher ---------------------------------------------------
extern "C" void kernel_launch(void* const* d_in, const int* in_sizes, int n_in,
                              void* d_out, int out_size)
{
    (void)in_sizes; (void)n_in; (void)out_size;
    const float* x   = (const float*)d_in[0];
    // d_in[1] = mask (unused in infer path)
    const float* g1  = (const float*)d_in[2];
    const float* b1  = (const float*)d_in[3];
    const float* Wq  = (const float*)d_in[4];
    const float* bq  = (const float*)d_in[5];
    const float* Wk  = (const float*)d_in[6];
    const float* bk  = (const float*)d_in[7];
    const float* Wv  = (const float*)d_in[8];
    const float* bv  = (const float*)d_in[9];
    const float* g2  = (const float*)d_in[10];
    const float* b2  = (const float*)d_in[11];
    const float* W1  = (const float*)d_in[12];
    const float* bw1 = (const float*)d_in[13];
    const float* W2  = (const float*)d_in[14];
    const float* bw2 = (const float*)d_in[15];
    float* out = (float*)d_out;

    float *xn, *q, *k, *v, *p, *ctx, *x1, *xn2, *ff;
    cudaGetSymbolAddress((void**)&xn,  g_xn);
    cudaGetSymbolAddress((void**)&q,   g_q);
    cudaGetSymbolAddress((void**)&k,   g_k);
    cudaGetSymbolAddress((void**)&v,   g_v);
    cudaGetSymbolAddress((void**)&p,   g_p);
    cudaGetSymbolAddress((void**)&ctx, g_ctx);
    cudaGetSymbolAddress((void**)&x1,  g_x1);
    cudaGetSymbolAddress((void**)&xn2, g_xn2);
    cudaGetSymbolAddress((void**)&ff,  g_ff);

    const float inv_sqrt_dk = 0.08838834764831845f;  // 1/sqrt(128)

    // 1. LN1
    ln_kernel<<<TOK, 256>>>(x, g1, b1, xn);

    // 2-4. QKV projections (M=4096, K=1024)
    gemm_kernel<false><<<dim3(Dc/BN,  TOK/BM, 1), 256>>>(
        xn, Wq, bq, nullptr, q, TOK, Dc, Dc, Dc, Dc, Dc,
        0,0,0,0,0,0, 1, 1.0f, 0);
    gemm_kernel<false><<<dim3(Dc/BN,  TOK/BM, 1), 256>>>(
        xn, Wk, bk, nullptr, k, TOK, Dc, Dc, Dc, Dc, Dc,
        0,0,0,0,0,0, 1, 1.0f, 0);
    gemm_kernel<false><<<dim3(Hc*Dc/BN, TOK/BM, 1), 256>>>(
        xn, Wv, bv, nullptr, v, TOK, Hc*Dc, Dc, Dc, Hc*Dc, Hc*Dc,
        0,0,0,0,0,0, 1, 1.0f, 0);

    // 5. scores = (q @ k^T) / sqrt(DK), batched over (b,h)
    gemm_kernel<true><<<dim3(Sc/BN, Sc/BM, Bc*Hc), 256>>>(
        q, k, nullptr, nullptr, p, Sc, Sc, DKc, Dc, Dc, Sc,
        (long long)Sc*Dc, DKc,
        (long long)Sc*Dc, DKc,
        (long long)Hc*Sc*Sc, (long long)Sc*Sc,
        Hc, inv_sqrt_dk, 0);

    // 6. softmax
    softmax_kernel<<<Bc*Hc*Sc, 256>>>(p);

    // 7. ctx = p @ v_bh  (v_bh[k,d] = v[b, k, h*D + d], ldb = H*D)
    gemm_kernel<false><<<dim3(Dc/BN, Sc/BM, Bc*Hc), 256>>>(
        p, v, nullptr, nullptr, ctx, Sc, Dc, Sc, Sc, Hc*Dc, Dc,
        (long long)Hc*Sc*Sc, (long long)Sc*Sc,
        (long long)Sc*Hc*Dc, (long long)Dc,
        (long long)Hc*Sc*Dc, (long long)Sc*Dc,
        Hc, 1.0f, 0);

    // 8. x1 = x + head-sum(ctx)
    headsum_kernel<<<(TOK*Dc)/256, 256>>>(ctx, x, x1);

    // 9. LN2
    ln_kernel<<<TOK, 256>>>(x1, g2, b2, xn2);

    // 10. ff = gelu(xn2 @ W1 + bw1)
    gemm_kernel<false><<<dim3(FFc/BN, TOK/BM, 1), 256>>>(
        xn2, W1, bw1, nullptr, ff, TOK, FFc, Dc, Dc, FFc, FFc,
        0,0,0,0,0,0, 1, 1.0f, 1);

    // 11. out = ff @ W2 + bw2 + x1
    gemm_kernel<false><<<dim3(Dc/BN, TOK/BM, 1), 256>>>(
        ff, W2, bw2, x1, out, TOK, Dc, FFc, FFc, Dc, Dc,
        0,0,0,0,0,0, 1, 1.0f, 0);
}

// round 2
// speedup vs baseline: 1.0034x; 1.0034x over previous
#include <cuda_runtime.h>
#include <math.h>

// Problem constants
#define Bc 4
#define Sc 1024
#define Dc 1024
#define Hc 8
#define DKc 128
#define FFc 4096
#define TOK (Bc*Sc)            // 4096 token rows

// ---------------- scratch (device globals; no allocation allowed) ----------
__device__ float g_xn [TOK*Dc];            // 16 MB
__device__ float g_q  [TOK*Dc];            // 16 MB
__device__ float g_k  [TOK*Dc];            // 16 MB
__device__ float g_v  [TOK*Hc*Dc];         // 128 MB  [B,S,H*D]
__device__ float g_p  [Bc*Hc*Sc*Sc];       // 128 MB  scores/probs
__device__ float g_ctx[Bc*Hc*Sc*Dc];       // 128 MB  [B,H,S,D]
__device__ float g_x1 [TOK*Dc];            // 16 MB
__device__ float g_xn2[TOK*Dc];            // 16 MB
__device__ float g_ff [TOK*FFc];           // 64 MB

// ---------------- tiled SGEMM ----------------------------------------------
// C[z] = act( alpha * A[z] @ op(B[z]) + bias ) + resid
// A: [M,K] row-major (lda). TB=false: B is [K,N] (ldb). TB=true: B is [N,K] (ldb), used transposed.
// Batch z decomposed as zo = z/innerB, zi = z%innerB with separate strides.
#define BM 128
#define BN 128
#define BKq 16
#define TM 8
#define TN 8

template<bool TB>
__global__ void __launch_bounds__(256)
gemm_kernel(const float* __restrict__ A, const float* __restrict__ Bm,
            const float* __restrict__ bias, const float* __restrict__ resid,
            float* __restrict__ C,
            int M, int N, int K, int lda, int ldb, int ldc,
            long long sA0, long long sA1, long long sB0, long long sB1,
            long long sC0, long long sC1, int innerB,
            float alpha, int act)
{
    const int z  = blockIdx.z;
    const int zo = z / innerB, zi = z % innerB;
    A  += zo*sA0 + zi*sA1;
    Bm += zo*sB0 + zi*sB1;
    C  += zo*sC0 + zi*sC1;

    __shared__ float As[BKq][BM];
    __shared__ float Bs[BKq][BN];

    const int tid = threadIdx.x;
    const int m0 = blockIdx.y * BM;
    const int n0 = blockIdx.x * BN;
    const int ty = tid >> 4;     // 0..15
    const int tx = tid & 15;     // 0..15

    float acc[TM][TN] = {};

    for (int k0 = 0; k0 < K; k0 += BKq) {
        // ---- load A tile (128 x 16), transposed into As[k][m] ----
        {
            int f = tid;
            #pragma unroll
            for (int r = 0; r < 2; r++, f += 256) {
                int row = f >> 2;
                int c4  = (f & 3) * 4;
                float4 v = *(const float4*)(A + (long long)(m0 + row) * lda + k0 + c4);
                As[c4+0][row] = v.x; As[c4+1][row] = v.y;
                As[c4+2][row] = v.z; As[c4+3][row] = v.w;
            }
        }
        // ---- load B tile into Bs[k][n] ----
        if (TB) {
            // B is [N,K]; tile rows n0..n0+127, cols k0..k0+15
            int f = tid;
            #pragma unroll
            for (int r = 0; r < 2; r++, f += 256) {
                int row = f >> 2;            // n within tile
                int c4  = (f & 3) * 4;       // k within tile
                float4 v = *(const float4*)(Bm + (long long)(n0 + row) * ldb + k0 + c4);
                Bs[c4+0][row] = v.x; Bs[c4+1][row] = v.y;
                Bs[c4+2][row] = v.z; Bs[c4+3][row] = v.w;
            }
        } else {
            // B is [K,N]; tile rows k0..k0+15, cols n0..n0+127
            int f = tid;
            #pragma unroll
            for (int r = 0; r < 2; r++, f += 256) {
                int row = f >> 5;            // k within tile (0..15)
                int c4  = (f & 31) * 4;      // n within tile
                float4 v = *(const float4*)(Bm + (long long)(k0 + row) * ldb + n0 + c4);
                *(float4*)&Bs[row][c4] = v;
            }
        }
        __syncthreads();

        // ---- compute ----
        #pragma unroll
        for (int kk = 0; kk < BKq; kk++) {
            float a[TM], b[TN];
            *(float4*)&a[0] = *(const float4*)&As[kk][ty*TM];
            *(float4*)&a[4] = *(const float4*)&As[kk][ty*TM + 4];
            *(float4*)&b[0] = *(const float4*)&Bs[kk][tx*TN];
            *(float4*)&b[4] = *(const float4*)&Bs[kk][tx*TN + 4];
            #pragma unroll
            for (int i = 0; i < TM; i++)
                #pragma unroll
                for (int j = 0; j < TN; j++)
                    acc[i][j] = fmaf(a[i], b[j], acc[i][j]);
        }
        __syncthreads();
    }

    // ---- epilogue ----
    float bj[TN];
    #pragma unroll
    for (int j = 0; j < TN; j++)
        bj[j] = bias ? bias[n0 + tx*TN + j] : 0.0f;

    #pragma unroll
    for (int i = 0; i < TM; i++) {
        int m = m0 + ty*TM + i;
        float*       crow = C + (long long)m * ldc + n0 + tx*TN;
        const float* rrow = resid ? (resid + (long long)m * ldc + n0 + tx*TN) : nullptr;
        float outv[TN];
        #pragma unroll
        for (int j = 0; j < TN; j++) {
            float vv = acc[i][j] * alpha + bj[j];
            if (act == 1)   // exact GELU
                vv = 0.5f * vv * (1.0f + erff(vv * 0.70710678118654752f));
            if (rrow) vv += rrow[j];
            outv[j] = vv;
        }
        *(float4*)&crow[0] = *(float4*)&outv[0];
        *(float4*)&crow[4] = *(float4*)&outv[4];
    }
}

// ---------------- layernorm: one block per row of 1024 ---------------------
__global__ void __launch_bounds__(256)
ln_kernel(const float* __restrict__ x, const float* __restrict__ g,
          const float* __restrict__ b, float* __restrict__ out)
{
    const long long row = blockIdx.x;
    const float* xr = x + row * Dc;
    const int tid = threadIdx.x;

    float4 v = *(const float4*)&xr[tid * 4];
    float s  = v.x + v.y + v.z + v.w;
    float ss = v.x*v.x + v.y*v.y + v.z*v.z + v.w*v.w;

    __shared__ float shs[8], shq[8];
    #pragma unroll
    for (int o = 16; o; o >>= 1) {
        s  += __shfl_xor_sync(0xffffffffu, s,  o);
        ss += __shfl_xor_sync(0xffffffffu, ss, o);
    }
    if ((tid & 31) == 0) { shs[tid >> 5] = s; shq[tid >> 5] = ss; }
    __syncthreads();
    float st = 0.f, qt = 0.f;
    #pragma unroll
    for (int i = 0; i < 8; i++) { st += shs[i]; qt += shq[i]; }

    const float m   = st * (1.0f / Dc);
    const float var = qt * (1.0f / Dc) - m * m;
    const float inv = rsqrtf(var + 1e-5f);

    float4 gv = *(const float4*)&g[tid * 4];
    float4 bv = *(const float4*)&b[tid * 4];
    float4 o4;
    o4.x = (v.x - m) * inv * gv.x + bv.x;
    o4.y = (v.y - m) * inv * gv.y + bv.y;
    o4.z = (v.z - m) * inv * gv.z + bv.z;
    o4.w = (v.w - m) * inv * gv.w + bv.w;
    *(float4*)&out[row * Dc + tid * 4] = o4;
}

// ---------------- softmax over rows of length 1024 --------------------------
__global__ void __launch_bounds__(256)
softmax_kernel(float* __restrict__ p)
{
    const long long row = blockIdx.x;
    float* r = p + row * 1024;
    const int tid = threadIdx.x;

    float4 v = *(const float4*)&r[tid * 4];
    float mx = fmaxf(fmaxf(v.x, v.y), fmaxf(v.z, v.w));

    __shared__ float sh[8];
    #pragma unroll
    for (int o = 16; o; o >>= 1) mx = fmaxf(mx, __shfl_xor_sync(0xffffffffu, mx, o));
    if ((tid & 31) == 0) sh[tid >> 5] = mx;
    __syncthreads();
    float m = sh[0];
    #pragma unroll
    for (int i = 1; i < 8; i++) m = fmaxf(m, sh[i]);
    __syncthreads();

    v.x = __expf(v.x - m); v.y = __expf(v.y - m);
    v.z = __expf(v.z - m); v.w = __expf(v.w - m);
    float s = v.x + v.y + v.z + v.w;
    #pragma unroll
    for (int o = 16; o; o >>= 1) s += __shfl_xor_sync(0xffffffffu, s, o);
    if ((tid & 31) == 0) sh[tid >> 5] = s;
    __syncthreads();
    float tot = 0.f;
    #pragma unroll
    for (int i = 0; i < 8; i++) tot += sh[i];

    const float inv = 1.0f / tot;
    v.x *= inv; v.y *= inv; v.z *= inv; v.w *= inv;
    *(float4*)&r[tid * 4] = v;
}

// ---------------- head-sum + residual ---------------------------------------
// attn_out_flat[o] = sum_{h<8} ctx_flat[o*8 + h]   (exact index algebra of the
// reference's reshape(S,B,D,H).sum(-1) on the contiguous [B,H,S,D] tensor)
__global__ void __launch_bounds__(256)
headsum_kernel(const float* __restrict__ ctx, const float* __restrict__ x,
               float* __restrict__ x1)
{
    const long long o = (long long)blockIdx.x * blockDim.x + threadIdx.x;
    const float4* c = (const float4*)(ctx + o * 8);
    float4 a = c[0], b = c[1];
    x1[o] = x[o] + (a.x + a.y + a.z + a.w + b.x + b.y + b.z + b.w);
}

// ---------------- launcher ---------------------------------------------------
extern "C" void kernel_launch(void* const* d_in, const int* in_sizes, int n_in,
                              void* d_out, int out_size)
{
    (void)in_sizes; (void)n_in; (void)out_size;
    const float* x   = (const float*)d_in[0];
    // d_in[1] = mask (unused in infer path)
    const float* g1  = (const float*)d_in[2];
    const float* b1  = (const float*)d_in[3];
    const float* Wq  = (const float*)d_in[4];
    const float* bq  = (const float*)d_in[5];
    const float* Wk  = (const float*)d_in[6];
    const float* bk  = (const float*)d_in[7];
    const float* Wv  = (const float*)d_in[8];
    const float* bv  = (const float*)d_in[9];
    const float* g2  = (const float*)d_in[10];
    const float* b2  = (const float*)d_in[11];
    const float* W1  = (const float*)d_in[12];
    const float* bw1 = (const float*)d_in[13];
    const float* W2  = (const float*)d_in[14];
    const float* bw2 = (const float*)d_in[15];
    float* out = (float*)d_out;

    float *xn, *q, *k, *v, *p, *ctx, *x1, *xn2, *ff;
    cudaGetSymbolAddress((void**)&xn,  g_xn);
    cudaGetSymbolAddress((void**)&q,   g_q);
    cudaGetSymbolAddress((void**)&k,   g_k);
    cudaGetSymbolAddress((void**)&v,   g_v);
    cudaGetSymbolAddress((void**)&p,   g_p);
    cudaGetSymbolAddress((void**)&ctx, g_ctx);
    cudaGetSymbolAddress((void**)&x1,  g_x1);
    cudaGetSymbolAddress((void**)&xn2, g_xn2);
    cudaGetSymbolAddress((void**)&ff,  g_ff);

    const float inv_sqrt_dk = 0.08838834764831845f;  // 1/sqrt(128)

    // 1. LN1
    ln_kernel<<<TOK, 256>>>(x, g1, b1, xn);

    // 2-4. QKV projections (M=4096, K=1024)
    gemm_kernel<false><<<dim3(Dc/BN,  TOK/BM, 1), 256>>>(
        xn, Wq, bq, nullptr, q, TOK, Dc, Dc, Dc, Dc, Dc,
        0,0,0,0,0,0, 1, 1.0f, 0);
    gemm_kernel<false><<<dim3(Dc/BN,  TOK/BM, 1), 256>>>(
        xn, Wk, bk, nullptr, k, TOK, Dc, Dc, Dc, Dc, Dc,
        0,0,0,0,0,0, 1, 1.0f, 0);
    gemm_kernel<false><<<dim3(Hc*Dc/BN, TOK/BM, 1), 256>>>(
        xn, Wv, bv, nullptr, v, TOK, Hc*Dc, Dc, Dc, Hc*Dc, Hc*Dc,
        0,0,0,0,0,0, 1, 1.0f, 0);

    // 5. scores = (q @ k^T) / sqrt(DK), batched over (b,h)
    gemm_kernel<true><<<dim3(Sc/BN, Sc/BM, Bc*Hc), 256>>>(
        q, k, nullptr, nullptr, p, Sc, Sc, DKc, Dc, Dc, Sc,
        (long long)Sc*Dc, DKc,
        (long long)Sc*Dc, DKc,
        (long long)Hc*Sc*Sc, (long long)Sc*Sc,
        Hc, inv_sqrt_dk, 0);

    // 6. softmax
    softmax_kernel<<<Bc*Hc*Sc, 256>>>(p);

    // 7. ctx = p @ v_bh  (v_bh[k,d] = v[b, k, h*D + d], ldb = H*D)
    gemm_kernel<false><<<dim3(Dc/BN, Sc/BM, Bc*Hc), 256>>>(
        p, v, nullptr, nullptr, ctx, Sc, Dc, Sc, Sc, Hc*Dc, Dc,
        (long long)Hc*Sc*Sc, (long long)Sc*Sc,
        (long long)Sc*Hc*Dc, (long long)Dc,
        (long long)Hc*Sc*Dc, (long long)Sc*Dc,
        Hc, 1.0f, 0);

    // 8. x1 = x + head-sum(ctx)
    headsum_kernel<<<(TOK*Dc)/256, 256>>>(ctx, x, x1);

    // 9. LN2
    ln_kernel<<<TOK, 256>>>(x1, g2, b2, xn2);

    // 10. ff = gelu(xn2 @ W1 + bw1)
    gemm_kernel<false><<<dim3(FFc/BN, TOK/BM, 1), 256>>>(
        xn2, W1, bw1, nullptr, ff, TOK, FFc, Dc, Dc, FFc, FFc,
        0,0,0,0,0,0, 1, 1.0f, 1);

    // 11. out = ff @ W2 + bw2 + x1
    gemm_kernel<false><<<dim3(Dc/BN, TOK/BM, 1), 256>>>(
        ff, W2, bw2, x1, out, TOK, Dc, FFc, FFc, Dc, Dc,
        0,0,0,0,0,0, 1, 1.0f, 0);
}

// round 4
// speedup vs baseline: 2.6854x; 2.6763x over previous
#include <cuda_runtime.h>
#include <cuda_bf16.h>
#include <cstdint>
#include <math.h>

#define Bc 4
#define Sc 1024
#define Dc 1024
#define Hc 8
#define DKc 128
#define FFc 4096
#define TOK (Bc*Sc)
typedef __nv_bfloat16 bf16;

// ---- scratch ----
__device__ bf16 g_xn_h [TOK*Dc], g_xn_l [TOK*Dc];
__device__ bf16 g_xn2_h[TOK*Dc], g_xn2_l[TOK*Dc];
__device__ bf16 g_WqT_h[Dc*Dc], g_WqT_l[Dc*Dc];
__device__ bf16 g_WkT_h[Dc*Dc], g_WkT_l[Dc*Dc];
__device__ bf16 g_WvT_h[(size_t)Hc*Dc*Dc], g_WvT_l[(size_t)Hc*Dc*Dc];
__device__ bf16 g_W1T_h[(size_t)FFc*Dc],   g_W1T_l[(size_t)FFc*Dc];
__device__ bf16 g_W2T_h[(size_t)Dc*FFc],   g_W2T_l[(size_t)Dc*FFc];
__device__ bf16 g_q_h[TOK*Dc], g_q_l[TOK*Dc];
__device__ bf16 g_k_h[TOK*Dc], g_k_l[TOK*Dc];
__device__ float g_v[(size_t)TOK*Hc*Dc];
__device__ bf16 g_vT_h[(size_t)Bc*Hc*Dc*Sc], g_vT_l[(size_t)Bc*Hc*Dc*Sc];
__device__ float g_p[(size_t)Bc*Hc*Sc*Sc];
__device__ bf16 g_p_h[(size_t)Bc*Hc*Sc*Sc], g_p_l[(size_t)Bc*Hc*Sc*Sc];
__device__ float g_ctx[(size_t)Bc*Hc*Sc*Dc];
__device__ float g_x1[TOK*Dc];
__device__ bf16 g_ff_h[(size_t)TOK*FFc], g_ff_l[(size_t)TOK*FFc];

// ---- helpers ----
__device__ __forceinline__ uint32_t smem_u32(const void* p) {
    uint32_t a;
    asm("{ .reg .u64 t; cvta.to.shared.u64 t, %1; cvt.u32.u64 %0, t; }" : "=r"(a) : "l"(p));
    return a;
}
#define CP16(dst, src) asm volatile("cp.async.cg.shared.global [%0], [%1], 16;" :: "r"(dst), "l"(src))
#define CP_COMMIT()    asm volatile("cp.async.commit_group;" ::: "memory")
#define CP_WAIT1()     asm volatile("cp.async.wait_group 1;" ::: "memory")

__device__ __forceinline__ void ldsm_x4(uint32_t& a0, uint32_t& a1, uint32_t& a2, uint32_t& a3, uint32_t addr) {
    asm volatile("ldmatrix.sync.aligned.m8n8.x4.shared.b16 {%0,%1,%2,%3}, [%4];"
                 : "=r"(a0), "=r"(a1), "=r"(a2), "=r"(a3) : "r"(addr));
}
__device__ __forceinline__ void ldsm_x2(uint32_t& b0, uint32_t& b1, uint32_t addr) {
    asm volatile("ldmatrix.sync.aligned.m8n8.x2.shared.b16 {%0,%1}, [%2];"
                 : "=r"(b0), "=r"(b1) : "r"(addr));
}
__device__ __forceinline__ void mma16816(float* c, uint32_t a0, uint32_t a1, uint32_t a2, uint32_t a3,
                                         uint32_t b0, uint32_t b1) {
    asm volatile("mma.sync.aligned.m16n8k16.row.col.f32.bf16.bf16.f32 "
                 "{%0,%1,%2,%3},{%4,%5,%6,%7},{%8,%9},{%0,%1,%2,%3};"
                 : "+f"(c[0]), "+f"(c[1]), "+f"(c[2]), "+f"(c[3])
                 : "r"(a0), "r"(a1), "r"(a2), "r"(a3), "r"(b0), "r"(b1));
}
__device__ __forceinline__ void split2(float x, bf16& h, bf16& l) {
    h = __float2bfloat16_rn(x);
    l = __float2bfloat16_rn(x - __bfloat162float(h));
}
__device__ __forceinline__ float gelu_exact(float v) {
    return 0.5f * v * (1.0f + erff(v * 0.70710678118654752f));
}

// ---- HMMA bf16x3 GEMM: 128x128 CTA tile, K-chunk 32, 3-stage cp.async ----
// A[M,K] (hi/lo) @ B[N,K]^T (hi/lo). Smem per stage: Ah|Al|Bh|Bl each 128x32 bf16 (8KB).
#define STAGE_B 32768
#define GSMEM   (3*STAGE_B)

template<int ACT, int OUTMODE>
__global__ void __launch_bounds__(256, 1)
gemm_hmma(const bf16* __restrict__ Ah, const bf16* __restrict__ Al,
          const bf16* __restrict__ Bh, const bf16* __restrict__ Bl,
          const float* __restrict__ bias, const float* __restrict__ resid,
          float* __restrict__ C, bf16* __restrict__ Ch, bf16* __restrict__ Cl,
          int K, int lda, int ldb, int ldc,
          long long sA0, long long sA1, long long sB0, long long sB1,
          long long sC0, long long sC1, int innerB, float alpha)
{
    extern __shared__ char smem[];
    const uint32_t smb = smem_u32(smem);
    const int tid = threadIdx.x, lane = tid & 31, wid = tid >> 5;
    const int z = blockIdx.z, zo = z / innerB, zi = z - zo * innerB;
    const long long aoff = zo * sA0 + zi * sA1;
    const long long boff = zo * sB0 + zi * sB1;
    const long long coff = zo * sC0 + zi * sC1;
    const int m0 = blockIdx.y * 128, n0 = blockIdx.x * 128;
    const int wm = (wid & 1) * 64, wn = (wid >> 1) * 32;

    const int row = tid >> 2;          // 0..63 (per rep +64)
    const int cch = tid & 3;           // 16B chunk within 64B row

    float acc[4][4][4];
    #pragma unroll
    for (int i = 0; i < 4; i++)
        #pragma unroll
        for (int j = 0; j < 4; j++)
            #pragma unroll
            for (int t = 0; t < 4; t++) acc[i][j][t] = 0.f;

    const int nck = K >> 5;

    // loader: chunk kk -> stage s
    auto load_chunk = [&](int kk, int s) {
        const int k0 = kk << 5;
        const uint32_t st = smb + s * STAGE_B;
        #pragma unroll
        for (int rep = 0; rep < 2; rep++) {
            const int r = row + rep * 64;
            const uint32_t so = r * 64 + ((cch ^ (r & 3)) << 4);
            const size_t ga = (size_t)aoff + (size_t)(m0 + r) * lda + k0 + cch * 8;
            CP16(st + so,         Ah + ga);
            CP16(st + 8192 + so,  Al + ga);
            const size_t gb = (size_t)boff + (size_t)(n0 + r) * ldb + k0 + cch * 8;
            CP16(st + 16384 + so, Bh + gb);
            CP16(st + 24576 + so, Bl + gb);
        }
        CP_COMMIT();
    };

    load_chunk(0, 0);
    load_chunk(1, 1);

    for (int kk = 0; kk < nck; kk++) {
        CP_WAIT1();
        __syncthreads();
        if (kk + 2 < nck) load_chunk(kk + 2, (kk + 2) % 3);
        else CP_COMMIT();

        const uint32_t st = smb + (kk % 3) * STAGE_B;
        #pragma unroll
        for (int ks = 0; ks < 2; ks++) {
            uint32_t ah[4][4], al[4][4], bh[4][2], bl[4][2];
            #pragma unroll
            for (int mf = 0; mf < 4; mf++) {
                const int r = wm + mf * 16 + (lane & 15);
                const int ch = ks * 2 + (lane >> 4);
                const uint32_t ad = st + r * 64 + ((ch ^ (r & 3)) << 4);
                ldsm_x4(ah[mf][0], ah[mf][1], ah[mf][2], ah[mf][3], ad);
                ldsm_x4(al[mf][0], al[mf][1], al[mf][2], al[mf][3], ad + 8192);
            }
            #pragma unroll
            for (int nf = 0; nf < 4; nf++) {
                const int r = wn + nf * 8 + (lane & 7);
                const int ch = ks * 2 + ((lane >> 3) & 1);
                const uint32_t bd = st + 16384 + r * 64 + ((ch ^ (r & 3)) << 4);
                ldsm_x2(bh[nf][0], bh[nf][1], bd);
                ldsm_x2(bl[nf][0], bl[nf][1], bd + 8192);
            }
            #pragma unroll
            for (int mf = 0; mf < 4; mf++)
                #pragma unroll
                for (int nf = 0; nf < 4; nf++)
                    mma16816(acc[mf][nf], ah[mf][0], ah[mf][1], ah[mf][2], ah[mf][3], bh[nf][0], bh[nf][1]);
            #pragma unroll
            for (int mf = 0; mf < 4; mf++)
                #pragma unroll
                for (int nf = 0; nf < 4; nf++)
                    mma16816(acc[mf][nf], ah[mf][0], ah[mf][1], ah[mf][2], ah[mf][3], bl[nf][0], bl[nf][1]);
            #pragma unroll
            for (int mf = 0; mf < 4; mf++)
                #pragma unroll
                for (int nf = 0; nf < 4; nf++)
                    mma16816(acc[mf][nf], al[mf][0], al[mf][1], al[mf][2], al[mf][3], bh[nf][0], bh[nf][1]);
        }
        __syncthreads();
    }

    // ---- epilogue ----
    #pragma unroll
    for (int mf = 0; mf < 4; mf++) {
        const int r0 = m0 + wm + mf * 16 + (lane >> 2);
        const int r1 = r0 + 8;
        #pragma unroll
        for (int nf = 0; nf < 4; nf++) {
            const int col = n0 + wn + nf * 8 + (lane & 3) * 2;
            float b0 = 0.f, b1 = 0.f;
            if (bias) { b0 = __ldg(bias + col); b1 = __ldg(bias + col + 1); }
            float v0 = acc[mf][nf][0] * alpha + b0;
            float v1 = acc[mf][nf][1] * alpha + b1;
            float v2 = acc[mf][nf][2] * alpha + b0;
            float v3 = acc[mf][nf][3] * alpha + b1;
            if (ACT == 1) {
                v0 = gelu_exact(v0); v1 = gelu_exact(v1);
                v2 = gelu_exact(v2); v3 = gelu_exact(v3);
            }
            const size_t i0 = (size_t)coff + (size_t)r0 * ldc + col;
            const size_t i1 = (size_t)coff + (size_t)r1 * ldc + col;
            if (OUTMODE == 0) {
                if (resid) {
                    float2 q0 = *(const float2*)(resid + i0);
                    float2 q1 = *(const float2*)(resid + i1);
                    v0 += q0.x; v1 += q0.y; v2 += q1.x; v3 += q1.y;
                }
                *(float2*)(C + i0) = make_float2(v0, v1);
                *(float2*)(C + i1) = make_float2(v2, v3);
            } else {
                bf16 h[4], l[4];
                split2(v0, h[0], l[0]); split2(v1, h[1], l[1]);
                split2(v2, h[2], l[2]); split2(v3, h[3], l[3]);
                *(uint32_t*)(Ch + i0) = *(uint32_t*)&h[0];
                *(uint32_t*)(Ch + i1) = *(uint32_t*)&h[2];
                *(uint32_t*)(Cl + i0) = *(uint32_t*)&l[0];
                *(uint32_t*)(Cl + i1) = *(uint32_t*)&l[2];
            }
        }
    }
}

// ---- layernorm -> split ----
__global__ void __launch_bounds__(256)
ln_split(const float* __restrict__ x, const float* __restrict__ g,
         const float* __restrict__ b, bf16* __restrict__ oh, bf16* __restrict__ ol)
{
    const long long row = blockIdx.x;
    const int tid = threadIdx.x;
    float4 v = *(const float4*)(x + row * Dc + tid * 4);
    float s = v.x+v.y+v.z+v.w, ss = v.x*v.x+v.y*v.y+v.z*v.z+v.w*v.w;
    __shared__ float shs[8], shq[8];
    #pragma unroll
    for (int o = 16; o; o >>= 1) { s += __shfl_xor_sync(~0u,s,o); ss += __shfl_xor_sync(~0u,ss,o); }
    if ((tid & 31) == 0) { shs[tid>>5] = s; shq[tid>>5] = ss; }
    __syncthreads();
    float st=0.f, qt=0.f;
    #pragma unroll
    for (int i = 0; i < 8; i++) { st += shs[i]; qt += shq[i]; }
    const float m = st * (1.f/Dc), inv = rsqrtf(qt*(1.f/Dc) - m*m + 1e-5f);
    float4 gv = *(const float4*)(g + tid*4);
    float4 bv = *(const float4*)(b + tid*4);
    float o0=(v.x-m)*inv*gv.x+bv.x, o1=(v.y-m)*inv*gv.y+bv.y;
    float o2=(v.z-m)*inv*gv.z+bv.z, o3=(v.w-m)*inv*gv.w+bv.w;
    bf16 hb[4], lb[4];
    split2(o0,hb[0],lb[0]); split2(o1,hb[1],lb[1]); split2(o2,hb[2],lb[2]); split2(o3,hb[3],lb[3]);
    *(uint2*)(oh + row*Dc + tid*4) = *(uint2*)hb;
    *(uint2*)(ol + row*Dc + tid*4) = *(uint2*)lb;
}

// ---- softmax -> split ----
__global__ void __launch_bounds__(256)
softmax_split(const float* __restrict__ p, bf16* __restrict__ oh, bf16* __restrict__ ol)
{
    const long long row = blockIdx.x;
    const int tid = threadIdx.x;
    float4 v = *(const float4*)(p + row * 1024 + tid * 4);
    float mx = fmaxf(fmaxf(v.x,v.y), fmaxf(v.z,v.w));
    __shared__ float sh[8];
    #pragma unroll
    for (int o = 16; o; o >>= 1) mx = fmaxf(mx, __shfl_xor_sync(~0u,mx,o));
    if ((tid & 31) == 0) sh[tid>>5] = mx;
    __syncthreads();
    float m = sh[0];
    #pragma unroll
    for (int i = 1; i < 8; i++) m = fmaxf(m, sh[i]);
    __syncthreads();
    v.x=__expf(v.x-m); v.y=__expf(v.y-m); v.z=__expf(v.z-m); v.w=__expf(v.w-m);
    float s = v.x+v.y+v.z+v.w;
    #pragma unroll
    for (int o = 16; o; o >>= 1) s += __shfl_xor_sync(~0u,s,o);
    if ((tid & 31) == 0) sh[tid>>5] = s;
    __syncthreads();
    float tot = 0.f;
    #pragma unroll
    for (int i = 0; i < 8; i++) tot += sh[i];
    const float inv = 1.f / tot;
    bf16 hb[4], lb[4];
    split2(v.x*inv,hb[0],lb[0]); split2(v.y*inv,hb[1],lb[1]);
    split2(v.z*inv,hb[2],lb[2]); split2(v.w*inv,hb[3],lb[3]);
    *(uint2*)(oh + row*1024 + tid*4) = *(uint2*)hb;
    *(uint2*)(ol + row*1024 + tid*4) = *(uint2*)lb;
}

// ---- batched transpose + split ----
__global__ void __launch_bounds__(256)
transpose_split(const float* __restrict__ in, bf16* __restrict__ oh, bf16* __restrict__ ol,
                int ldin, int ldo, long long zi0, long long zi1, int innerZ, long long zos)
{
    __shared__ float t[32][33];
    const int z = blockIdx.z;
    const long long base = (long long)(z / innerZ) * zi0 + (long long)(z % innerZ) * zi1;
    const int c0 = blockIdx.x * 32, r0 = blockIdx.y * 32;
    const int tx = threadIdx.x, ty = threadIdx.y;
    #pragma unroll
    for (int i = 0; i < 4; i++)
        t[ty + i*8][tx] = in[base + (size_t)(r0 + ty + i*8) * ldin + c0 + tx];
    __syncthreads();
    #pragma unroll
    for (int i = 0; i < 4; i++) {
        bf16 h, l;
        split2(t[tx][ty + i*8], h, l);
        size_t idx = (size_t)z * zos + (size_t)(c0 + ty + i*8) * ldo + r0 + tx;
        oh[idx] = h; ol[idx] = l;
    }
}

__global__ void __launch_bounds__(256)
headsum(const float* __restrict__ ctx, const float* __restrict__ x, float* __restrict__ x1)
{
    const long long o = (long long)blockIdx.x * blockDim.x + threadIdx.x;
    const float4* c = (const float4*)(ctx + o * 8);
    float4 a = c[0], b = c[1];
    x1[o] = x[o] + (a.x+a.y+a.z+a.w + b.x+b.y+b.z+b.w);
}

#define SYM(p, s) cudaGetSymbolAddress((void**)&p, s)

extern "C" void kernel_launch(void* const* d_in, const int* in_sizes, int n_in,
                              void* d_out, int out_size)
{
    (void)in_sizes; (void)n_in; (void)out_size;
    const float* x   = (const float*)d_in[0];
    const float* g1  = (const float*)d_in[2];
    const float* b1  = (const float*)d_in[3];
    const float* Wq  = (const float*)d_in[4];
    const float* bq  = (const float*)d_in[5];
    const float* Wk  = (const float*)d_in[6];
    const float* bk  = (const float*)d_in[7];
    const float* Wv  = (const float*)d_in[8];
    const float* bv  = (const float*)d_in[9];
    const float* g2  = (const float*)d_in[10];
    const float* b2  = (const float*)d_in[11];
    const float* W1  = (const float*)d_in[12];
    const float* bw1 = (const float*)d_in[13];
    const float* W2  = (const float*)d_in[14];
    const float* bw2 = (const float*)d_in[15];
    float* out = (float*)d_out;

    bf16 *xnh,*xnl,*xn2h,*xn2l,*wqh,*wql,*wkh,*wkl,*wvh,*wvl,*w1h,*w1l,*w2h,*w2l;
    bf16 *qh,*ql,*kh,*kl,*vth,*vtl,*ph,*pl,*ffh,*ffl;
    float *v,*p,*ctx,*x1;
    SYM(xnh,g_xn_h); SYM(xnl,g_xn_l); SYM(xn2h,g_xn2_h); SYM(xn2l,g_xn2_l);
    SYM(wqh,g_WqT_h); SYM(wql,g_WqT_l); SYM(wkh,g_WkT_h); SYM(wkl,g_WkT_l);
    SYM(wvh,g_WvT_h); SYM(wvl,g_WvT_l); SYM(w1h,g_W1T_h); SYM(w1l,g_W1T_l);
    SYM(w2h,g_W2T_h); SYM(w2l,g_W2T_l);
    SYM(qh,g_q_h); SYM(ql,g_q_l); SYM(kh,g_k_h); SYM(kl,g_k_l);
    SYM(vth,g_vT_h); SYM(vtl,g_vT_l); SYM(ph,g_p_h); SYM(pl,g_p_l);
    SYM(ffh,g_ff_h); SYM(ffl,g_ff_l);
    SYM(v,g_v); SYM(p,g_p); SYM(ctx,g_ctx); SYM(x1,g_x1);

    cudaFuncSetAttribute(gemm_hmma<0,0>, cudaFuncAttributeMaxDynamicSharedMemorySize, GSMEM);
    cudaFuncSetAttribute(gemm_hmma<0,1>, cudaFuncAttributeMaxDynamicSharedMemorySize, GSMEM);
    cudaFuncSetAttribute(gemm_hmma<1,1>, cudaFuncAttributeMaxDynamicSharedMemorySize, GSMEM);

    const dim3 tb(32, 8);
    transpose_split<<<dim3(Dc/32,  Dc/32, 1), tb>>>(Wq, wqh, wql, Dc,    Dc,  0,0,1,0);
    transpose_split<<<dim3(Dc/32,  Dc/32, 1), tb>>>(Wk, wkh, wkl, Dc,    Dc,  0,0,1,0);
    transpose_split<<<dim3(Hc*Dc/32, Dc/32, 1), tb>>>(Wv, wvh, wvl, Hc*Dc, Dc, 0,0,1,0);
    transpose_split<<<dim3(FFc/32, Dc/32, 1), tb>>>(W1, w1h, w1l, FFc,   Dc,  0,0,1,0);
    transpose_split<<<dim3(Dc/32, FFc/32, 1), tb>>>(W2, w2h, w2l, Dc,    FFc, 0,0,1,0);

    ln_split<<<TOK, 256>>>(x, g1, b1, xnh, xnl);

    gemm_hmma<0,1><<<dim3(Dc/128, TOK/128, 1), 256, GSMEM>>>(
        xnh, xnl, wqh, wql, bq, nullptr, nullptr, qh, ql,
        Dc, Dc, Dc, Dc, 0,0,0,0,0,0, 1, 1.0f);
    gemm_hmma<0,1><<<dim3(Dc/128, TOK/128, 1), 256, GSMEM>>>(
        xnh, xnl, wkh, wkl, bk, nullptr, nullptr, kh, kl,
        Dc, Dc, Dc, Dc, 0,0,0,0,0,0, 1, 1.0f);
    gemm_hmma<0,0><<<dim3(Hc*Dc/128, TOK/128, 1), 256, GSMEM>>>(
        xnh, xnl, wvh, wvl, bv, nullptr, v, nullptr, nullptr,
        Dc, Dc, Dc, Hc*Dc, 0,0,0,0,0,0, 1, 1.0f);

    transpose_split<<<dim3(Dc/32, Sc/32, Bc*Hc), tb>>>(
        v, vth, vtl, Hc*Dc, Sc,
        (long long)Sc*Hc*Dc, (long long)Dc, Hc, (long long)Dc*Sc);

    gemm_hmma<0,0><<<dim3(Sc/128, Sc/128, Bc*Hc), 256, GSMEM>>>(
        qh, ql, kh, kl, nullptr, nullptr, p, nullptr, nullptr,
        DKc, Dc, Dc, Sc,
        (long long)Sc*Dc, (long long)DKc,
        (long long)Sc*Dc, (long long)DKc,
        (long long)Hc*Sc*Sc, (long long)Sc*Sc, Hc, 0.08838834764831845f);

    softmax_split<<<Bc*Hc*Sc, 256>>>(p, ph, pl);

    gemm_hmma<0,0><<<dim3(Dc/128, Sc/128, Bc*Hc), 256, GSMEM>>>(
        ph, pl, vth, vtl, nullptr, nullptr, ctx, nullptr, nullptr,
        Sc, Sc, Sc, Dc,
        (long long)Hc*Sc*Sc, (long long)Sc*Sc,
        (long long)Hc*Dc*Sc, (long long)Dc*Sc,
        (long long)Hc*Sc*Dc, (long long)Sc*Dc, Hc, 1.0f);

    headsum<<<(TOK*Dc)/256, 256>>>(ctx, x, x1);
    ln_split<<<TOK, 256>>>(x1, g2, b2, xn2h, xn2l);

    gemm_hmma<1,1><<<dim3(FFc/128, TOK/128, 1), 256, GSMEM>>>(
        xn2h, xn2l, w1h, w1l, bw1, nullptr, nullptr, ffh, ffl,
        Dc, Dc, Dc, FFc, 0,0,0,0,0,0, 1, 1.0f);

    gemm_hmma<0,0><<<dim3(Dc/128, TOK/128, 1), 256, GSMEM>>>(
        ffh, ffl, w2h, w2l, bw2, x1, out, nullptr, nullptr,
        FFc, FFc, FFc, Dc, 0,0,0,0,0,0, 1, 1.0f);
}

// round 5
// speedup vs baseline: 5.1775x; 1.9280x over previous
#include <cuda_runtime.h>
#include <cuda_bf16.h>
#include <cstdint>
#include <math.h>

#define Bc 4
#define Sc 1024
#define Dc 1024
#define Hc 8
#define DKc 128
#define FFc 4096
#define TOK (Bc*Sc)
typedef __nv_bfloat16 bf16;

// ---- scratch ----
__device__ __align__(16) bf16 g_xn_h [TOK*Dc], g_xn_l [TOK*Dc];
__device__ __align__(16) bf16 g_xn2_h[TOK*Dc], g_xn2_l[TOK*Dc];
__device__ __align__(16) bf16 g_wqkv_h[(size_t)3*Dc*Dc], g_wqkv_l[(size_t)3*Dc*Dc];
__device__ __align__(16) float g_bqkv[3*Dc];
__device__ __align__(16) bf16 g_W1T_h[(size_t)FFc*Dc], g_W1T_l[(size_t)FFc*Dc];
__device__ __align__(16) bf16 g_W2T_h[(size_t)Dc*FFc], g_W2T_l[(size_t)Dc*FFc];
__device__ __align__(16) bf16 g_qkv_h[(size_t)3*TOK*Dc], g_qkv_l[(size_t)3*TOK*Dc];
__device__ __align__(16) bf16 g_vfT_h[(size_t)Bc*Hc*DKc*Sc], g_vfT_l[(size_t)Bc*Hc*DKc*Sc];
__device__ __align__(16) float g_p[(size_t)Bc*Hc*Sc*Sc];
__device__ __align__(16) bf16 g_p_h[(size_t)Bc*Hc*Sc*Sc], g_p_l[(size_t)Bc*Hc*Sc*Sc];
__device__ __align__(16) float g_x1[TOK*Dc];
__device__ __align__(16) bf16 g_ff_h[(size_t)TOK*FFc], g_ff_l[(size_t)TOK*FFc];

// ---- helpers ----
__device__ __forceinline__ uint32_t smem_u32(const void* p) {
    uint32_t a;
    asm("{ .reg .u64 t; cvta.to.shared.u64 t, %1; cvt.u32.u64 %0, t; }" : "=r"(a) : "l"(p));
    return a;
}
#define CP16(dst, src) asm volatile("cp.async.cg.shared.global [%0], [%1], 16;" :: "r"(dst), "l"(src))
#define CP_COMMIT()    asm volatile("cp.async.commit_group;" ::: "memory")
#define CP_WAIT1()     asm volatile("cp.async.wait_group 1;" ::: "memory")

__device__ __forceinline__ void ldsm_x4(uint32_t& a0, uint32_t& a1, uint32_t& a2, uint32_t& a3, uint32_t addr) {
    asm volatile("ldmatrix.sync.aligned.m8n8.x4.shared.b16 {%0,%1,%2,%3}, [%4];"
                 : "=r"(a0), "=r"(a1), "=r"(a2), "=r"(a3) : "r"(addr));
}
__device__ __forceinline__ void ldsm_x2(uint32_t& b0, uint32_t& b1, uint32_t addr) {
    asm volatile("ldmatrix.sync.aligned.m8n8.x2.shared.b16 {%0,%1}, [%2];"
                 : "=r"(b0), "=r"(b1) : "r"(addr));
}
__device__ __forceinline__ void mma16816(float* c, uint32_t a0, uint32_t a1, uint32_t a2, uint32_t a3,
                                         uint32_t b0, uint32_t b1) {
    asm volatile("mma.sync.aligned.m16n8k16.row.col.f32.bf16.bf16.f32 "
                 "{%0,%1,%2,%3},{%4,%5,%6,%7},{%8,%9},{%0,%1,%2,%3};"
                 : "+f"(c[0]), "+f"(c[1]), "+f"(c[2]), "+f"(c[3])
                 : "r"(a0), "r"(a1), "r"(a2), "r"(a3), "r"(b0), "r"(b1));
}
__device__ __forceinline__ void split2(float x, bf16& h, bf16& l) {
    h = __float2bfloat16_rn(x);
    l = __float2bfloat16_rn(x - __bfloat162float(h));
}
__device__ __forceinline__ float gelu_exact(float v) {
    return 0.5f * v * (1.0f + erff(v * 0.70710678118654752f));
}

// ---- HMMA bf16x3 GEMM: 128x128 CTA tile, K-chunk 32, 3-stage cp.async ----
#define STAGE_B 32768
#define GSMEM   (3*STAGE_B)

template<int ACT, int OUTMODE>
__global__ void __launch_bounds__(256, 1)
gemm_hmma(const bf16* __restrict__ Ah, const bf16* __restrict__ Al,
          const bf16* __restrict__ Bh, const bf16* __restrict__ Bl,
          const float* __restrict__ bias, const float* __restrict__ resid,
          float* __restrict__ C, bf16* __restrict__ Ch, bf16* __restrict__ Cl,
          int K, int lda, int ldb, int ldc,
          long long sA0, long long sA1, long long sB0, long long sB1,
          long long sC0, long long sC1, int innerB, float alpha, long long biasStride)
{
    extern __shared__ char smem[];
    const uint32_t smb = smem_u32(smem);
    const int tid = threadIdx.x, lane = tid & 31, wid = tid >> 5;
    const int z = blockIdx.z, zo = z / innerB, zi = z - zo * innerB;
    const long long aoff = zo * sA0 + zi * sA1;
    const long long boff = zo * sB0 + zi * sB1;
    const long long coff = zo * sC0 + zi * sC1;
    if (bias) bias += (long long)z * biasStride;
    const int m0 = blockIdx.y * 128, n0 = blockIdx.x * 128;
    const int wm = (wid & 1) * 64, wn = (wid >> 1) * 32;

    const int row = tid >> 2;
    const int cch = tid & 3;

    float acc[4][4][4];
    #pragma unroll
    for (int i = 0; i < 4; i++)
        #pragma unroll
        for (int j = 0; j < 4; j++)
            #pragma unroll
            for (int t = 0; t < 4; t++) acc[i][j][t] = 0.f;

    const int nck = K >> 5;

    auto load_chunk = [&](int kk, int s) {
        const int k0 = kk << 5;
        const uint32_t st = smb + s * STAGE_B;
        #pragma unroll
        for (int rep = 0; rep < 2; rep++) {
            const int r = row + rep * 64;
            const uint32_t so = r * 64 + ((cch ^ (r & 3)) << 4);
            const size_t ga = (size_t)aoff + (size_t)(m0 + r) * lda + k0 + cch * 8;
            CP16(st + so,         Ah + ga);
            CP16(st + 8192 + so,  Al + ga);
            const size_t gb = (size_t)boff + (size_t)(n0 + r) * ldb + k0 + cch * 8;
            CP16(st + 16384 + so, Bh + gb);
            CP16(st + 24576 + so, Bl + gb);
        }
        CP_COMMIT();
    };

    load_chunk(0, 0);
    load_chunk(1, 1);

    for (int kk = 0; kk < nck; kk++) {
        CP_WAIT1();
        __syncthreads();
        if (kk + 2 < nck) load_chunk(kk + 2, (kk + 2) % 3);
        else CP_COMMIT();

        const uint32_t st = smb + (kk % 3) * STAGE_B;
        #pragma unroll
        for (int ks = 0; ks < 2; ks++) {
            uint32_t ah[4][4], al[4][4], bh[4][2], bl[4][2];
            #pragma unroll
            for (int mf = 0; mf < 4; mf++) {
                const int r = wm + mf * 16 + (lane & 15);
                const int ch = ks * 2 + (lane >> 4);
                const uint32_t ad = st + r * 64 + ((ch ^ (r & 3)) << 4);
                ldsm_x4(ah[mf][0], ah[mf][1], ah[mf][2], ah[mf][3], ad);
                ldsm_x4(al[mf][0], al[mf][1], al[mf][2], al[mf][3], ad + 8192);
            }
            #pragma unroll
            for (int nf = 0; nf < 4; nf++) {
                const int r = wn + nf * 8 + (lane & 7);
                const int ch = ks * 2 + ((lane >> 3) & 1);
                const uint32_t bd = st + 16384 + r * 64 + ((ch ^ (r & 3)) << 4);
                ldsm_x2(bh[nf][0], bh[nf][1], bd);
                ldsm_x2(bl[nf][0], bl[nf][1], bd + 8192);
            }
            #pragma unroll
            for (int mf = 0; mf < 4; mf++)
                #pragma unroll
                for (int nf = 0; nf < 4; nf++)
                    mma16816(acc[mf][nf], ah[mf][0], ah[mf][1], ah[mf][2], ah[mf][3], bh[nf][0], bh[nf][1]);
            #pragma unroll
            for (int mf = 0; mf < 4; mf++)
                #pragma unroll
                for (int nf = 0; nf < 4; nf++)
                    mma16816(acc[mf][nf], ah[mf][0], ah[mf][1], ah[mf][2], ah[mf][3], bl[nf][0], bl[nf][1]);
            #pragma unroll
            for (int mf = 0; mf < 4; mf++)
                #pragma unroll
                for (int nf = 0; nf < 4; nf++)
                    mma16816(acc[mf][nf], al[mf][0], al[mf][1], al[mf][2], al[mf][3], bh[nf][0], bh[nf][1]);
        }
        __syncthreads();
    }

    // ---- epilogue ----
    #pragma unroll
    for (int mf = 0; mf < 4; mf++) {
        const int r0 = m0 + wm + mf * 16 + (lane >> 2);
        const int r1 = r0 + 8;
        #pragma unroll
        for (int nf = 0; nf < 4; nf++) {
            const int col = n0 + wn + nf * 8 + (lane & 3) * 2;
            float b0 = 0.f, b1 = 0.f;
            if (bias) { b0 = __ldg(bias + col); b1 = __ldg(bias + col + 1); }
            float v0 = acc[mf][nf][0] * alpha + b0;
            float v1 = acc[mf][nf][1] * alpha + b1;
            float v2 = acc[mf][nf][2] * alpha + b0;
            float v3 = acc[mf][nf][3] * alpha + b1;
            if (ACT == 1) {
                v0 = gelu_exact(v0); v1 = gelu_exact(v1);
                v2 = gelu_exact(v2); v3 = gelu_exact(v3);
            }
            const size_t i0 = (size_t)coff + (size_t)r0 * ldc + col;
            const size_t i1 = (size_t)coff + (size_t)r1 * ldc + col;
            if (OUTMODE == 0) {
                if (resid) {
                    float2 q0 = *(const float2*)(resid + i0);
                    float2 q1 = *(const float2*)(resid + i1);
                    v0 += q0.x; v1 += q0.y; v2 += q1.x; v3 += q1.y;
                }
                *(float2*)(C + i0) = make_float2(v0, v1);
                *(float2*)(C + i1) = make_float2(v2, v3);
            } else {
                bf16 h[4], l[4];
                split2(v0, h[0], l[0]); split2(v1, h[1], l[1]);
                split2(v2, h[2], l[2]); split2(v3, h[3], l[3]);
                *(uint32_t*)(Ch + i0) = *(uint32_t*)&h[0];
                *(uint32_t*)(Ch + i1) = *(uint32_t*)&h[2];
                *(uint32_t*)(Cl + i0) = *(uint32_t*)&l[0];
                *(uint32_t*)(Cl + i1) = *(uint32_t*)&l[2];
            }
        }
    }
}

// ---- layernorm -> split ----
__global__ void __launch_bounds__(256)
ln_split(const float* __restrict__ x, const float* __restrict__ g,
         const float* __restrict__ b, bf16* __restrict__ oh, bf16* __restrict__ ol)
{
    const long long row = blockIdx.x;
    const int tid = threadIdx.x;
    float4 v = *(const float4*)(x + row * Dc + tid * 4);
    float s = v.x+v.y+v.z+v.w, ss = v.x*v.x+v.y*v.y+v.z*v.z+v.w*v.w;
    __shared__ float shs[8], shq[8];
    #pragma unroll
    for (int o = 16; o; o >>= 1) { s += __shfl_xor_sync(~0u,s,o); ss += __shfl_xor_sync(~0u,ss,o); }
    if ((tid & 31) == 0) { shs[tid>>5] = s; shq[tid>>5] = ss; }
    __syncthreads();
    float st=0.f, qt=0.f;
    #pragma unroll
    for (int i = 0; i < 8; i++) { st += shs[i]; qt += shq[i]; }
    const float m = st * (1.f/Dc), inv = rsqrtf(qt*(1.f/Dc) - m*m + 1e-5f);
    float4 gv = *(const float4*)(g + tid*4);
    float4 bv = *(const float4*)(b + tid*4);
    float o0=(v.x-m)*inv*gv.x+bv.x, o1=(v.y-m)*inv*gv.y+bv.y;
    float o2=(v.z-m)*inv*gv.z+bv.z, o3=(v.w-m)*inv*gv.w+bv.w;
    bf16 hb[4], lb[4];
    split2(o0,hb[0],lb[0]); split2(o1,hb[1],lb[1]); split2(o2,hb[2],lb[2]); split2(o3,hb[3],lb[3]);
    *(uint2*)(oh + row*Dc + tid*4) = *(uint2*)hb;
    *(uint2*)(ol + row*Dc + tid*4) = *(uint2*)lb;
}

// ---- softmax -> split ----
__global__ void __launch_bounds__(256)
softmax_split(const float* __restrict__ p, bf16* __restrict__ oh, bf16* __restrict__ ol)
{
    const long long row = blockIdx.x;
    const int tid = threadIdx.x;
    float4 v = *(const float4*)(p + row * 1024 + tid * 4);
    float mx = fmaxf(fmaxf(v.x,v.y), fmaxf(v.z,v.w));
    __shared__ float sh[8];
    #pragma unroll
    for (int o = 16; o; o >>= 1) mx = fmaxf(mx, __shfl_xor_sync(~0u,mx,o));
    if ((tid & 31) == 0) sh[tid>>5] = mx;
    __syncthreads();
    float m = sh[0];
    #pragma unroll
    for (int i = 1; i < 8; i++) m = fmaxf(m, sh[i]);
    __syncthreads();
    v.x=__expf(v.x-m); v.y=__expf(v.y-m); v.z=__expf(v.z-m); v.w=__expf(v.w-m);
    float s = v.x+v.y+v.z+v.w;
    #pragma unroll
    for (int o = 16; o; o >>= 1) s += __shfl_xor_sync(~0u,s,o);
    if ((tid & 31) == 0) sh[tid>>5] = s;
    __syncthreads();
    float tot = 0.f;
    #pragma unroll
    for (int i = 0; i < 8; i++) tot += sh[i];
    const float inv = 1.f / tot;
    bf16 hb[4], lb[4];
    split2(v.x*inv,hb[0],lb[0]); split2(v.y*inv,hb[1],lb[1]);
    split2(v.z*inv,hb[2],lb[2]); split2(v.w*inv,hb[3],lb[3]);
    *(uint2*)(oh + row*1024 + tid*4) = *(uint2*)hb;
    *(uint2*)(ol + row*1024 + tid*4) = *(uint2*)lb;
}

// ---- fp32 transpose + split: out[c][r] = split(in[r][c]) ----
__global__ void __launch_bounds__(256)
transpose_split(const float* __restrict__ in, bf16* __restrict__ oh, bf16* __restrict__ ol,
                int ldin, int ldo)
{
    __shared__ float t[32][33];
    const int c0 = blockIdx.x * 32, r0 = blockIdx.y * 32;
    const int tx = threadIdx.x, ty = threadIdx.y;
    #pragma unroll
    for (int i = 0; i < 4; i++)
        t[ty + i*8][tx] = in[(size_t)(r0 + ty + i*8) * ldin + c0 + tx];
    __syncthreads();
    #pragma unroll
    for (int i = 0; i < 4; i++) {
        bf16 h, l;
        split2(t[tx][ty + i*8], h, l);
        size_t idx = (size_t)(c0 + ty + i*8) * ldo + r0 + tx;
        oh[idx] = h; ol[idx] = l;
    }
}

// ---- fold Wv [1024 x 8192] -> WvfT [1024(nf) x 1024(k)] with split ----
__global__ void __launch_bounds__(256)
fold_wv(const float* __restrict__ Wv, bf16* __restrict__ oh, bf16* __restrict__ ol)
{
    __shared__ float sf[32][33];
    const int k0 = blockIdx.x * 32, nf0 = blockIdx.y * 32;
    const int tx = threadIdx.x, ty = threadIdx.y;
    #pragma unroll
    for (int rep = 0; rep < 4; rep++) {
        const int row = ty + rep * 8;
        const float* src = Wv + (size_t)(k0 + row) * (Hc*Dc) + (size_t)(nf0 + tx) * 8;
        float4 a = *(const float4*)src;
        float4 b = *(const float4*)(src + 4);
        sf[row][tx] = a.x + a.y + a.z + a.w + b.x + b.y + b.z + b.w;
    }
    __syncthreads();
    #pragma unroll
    for (int rep = 0; rep < 4; rep++) {
        const int nf = ty + rep * 8;
        bf16 h, l;
        split2(sf[tx][nf], h, l);
        size_t idx = (size_t)(nf0 + nf) * Dc + k0 + tx;
        oh[idx] = h; ol[idx] = l;
    }
}

// ---- bias prep: bqkv = [bq | bk | fold8(bv)] ----
__global__ void prep_bias(const float* __restrict__ bq, const float* __restrict__ bk,
                          const float* __restrict__ bv, float* __restrict__ bqkv)
{
    const int i = blockIdx.x * blockDim.x + threadIdx.x;   // 0..1023
    bqkv[i] = bq[i];
    bqkv[Dc + i] = bk[i];
    const float* s = bv + (size_t)i * 8;
    float t = 0.f;
    #pragma unroll
    for (int j = 0; j < 8; j++) t += s[j];
    bqkv[2*Dc + i] = t;
}

// ---- bf16-pair batched transpose: out[z][c][r] = in[base(z) + r*ldin + c] ----
__global__ void __launch_bounds__(256)
transpose_bf16_pair(const bf16* __restrict__ ih, const bf16* __restrict__ il,
                    bf16* __restrict__ oh, bf16* __restrict__ ol,
                    int ldin, int ldo, long long zi0, long long zi1, int innerZ, long long zos)
{
    __shared__ bf16 th[32][33], tl[32][33];
    const int z = blockIdx.z;
    const long long base = (long long)(z / innerZ) * zi0 + (long long)(z % innerZ) * zi1;
    const int c0 = blockIdx.x * 32, r0 = blockIdx.y * 32;
    const int tx = threadIdx.x, ty = threadIdx.y;
    #pragma unroll
    for (int i = 0; i < 4; i++) {
        size_t idx = base + (size_t)(r0 + ty + i*8) * ldin + c0 + tx;
        th[ty + i*8][tx] = ih[idx];
        tl[ty + i*8][tx] = il[idx];
    }
    __syncthreads();
    #pragma unroll
    for (int i = 0; i < 4; i++) {
        size_t idx = (size_t)z * zos + (size_t)(c0 + ty + i*8) * ldo + r0 + tx;
        oh[idx] = th[tx][ty + i*8];
        ol[idx] = tl[tx][ty + i*8];
    }
}

#define SYM(p, s) cudaGetSymbolAddress((void**)&p, s)

extern "C" void kernel_launch(void* const* d_in, const int* in_sizes, int n_in,
                              void* d_out, int out_size)
{
    (void)in_sizes; (void)n_in; (void)out_size;
    const float* x   = (const float*)d_in[0];
    const float* g1  = (const float*)d_in[2];
    const float* b1  = (const float*)d_in[3];
    const float* Wq  = (const float*)d_in[4];
    const float* bq  = (const float*)d_in[5];
    const float* Wk  = (const float*)d_in[6];
    const float* bk  = (const float*)d_in[7];
    const float* Wv  = (const float*)d_in[8];
    const float* bv  = (const float*)d_in[9];
    const float* g2  = (const float*)d_in[10];
    const float* b2  = (const float*)d_in[11];
    const float* W1  = (const float*)d_in[12];
    const float* bw1 = (const float*)d_in[13];
    const float* W2  = (const float*)d_in[14];
    const float* bw2 = (const float*)d_in[15];
    float* out = (float*)d_out;

    bf16 *xnh,*xnl,*xn2h,*xn2l,*wqkvh,*wqkvl,*w1h,*w1l,*w2h,*w2l;
    bf16 *qkvh,*qkvl,*vfth,*vftl,*ph,*pl,*ffh,*ffl;
    float *bqkv,*p,*x1;
    SYM(xnh,g_xn_h); SYM(xnl,g_xn_l); SYM(xn2h,g_xn2_h); SYM(xn2l,g_xn2_l);
    SYM(wqkvh,g_wqkv_h); SYM(wqkvl,g_wqkv_l); SYM(bqkv,g_bqkv);
    SYM(w1h,g_W1T_h); SYM(w1l,g_W1T_l); SYM(w2h,g_W2T_h); SYM(w2l,g_W2T_l);
    SYM(qkvh,g_qkv_h); SYM(qkvl,g_qkv_l);
    SYM(vfth,g_vfT_h); SYM(vftl,g_vfT_l);
    SYM(ph,g_p_h); SYM(pl,g_p_l);
    SYM(ffh,g_ff_h); SYM(ffl,g_ff_l);
    SYM(p,g_p); SYM(x1,g_x1);

    cudaFuncSetAttribute(gemm_hmma<0,0>, cudaFuncAttributeMaxDynamicSharedMemorySize, GSMEM);
    cudaFuncSetAttribute(gemm_hmma<0,1>, cudaFuncAttributeMaxDynamicSharedMemorySize, GSMEM);
    cudaFuncSetAttribute(gemm_hmma<1,1>, cudaFuncAttributeMaxDynamicSharedMemorySize, GSMEM);

    const dim3 tb(32, 8);
    const size_t DD = (size_t)Dc*Dc;

    // weight prep
    prep_bias<<<4, 256>>>(bq, bk, bv, bqkv);
    transpose_split<<<dim3(Dc/32, Dc/32), tb>>>(Wq, wqkvh,      wqkvl,      Dc, Dc);
    transpose_split<<<dim3(Dc/32, Dc/32), tb>>>(Wk, wqkvh+DD,   wqkvl+DD,   Dc, Dc);
    fold_wv<<<dim3(32, 32), tb>>>(Wv, wqkvh+2*DD, wqkvl+2*DD);
    transpose_split<<<dim3(FFc/32, Dc/32), tb>>>(W1, w1h, w1l, FFc, Dc);
    transpose_split<<<dim3(Dc/32, FFc/32), tb>>>(W2, w2h, w2l, Dc,  FFc);

    // LN1
    ln_split<<<TOK, 256>>>(x, g1, b1, xnh, xnl);

    // QKV(folded) fused: z=3, out split bf16 [3][TOK][Dc]
    gemm_hmma<0,1><<<dim3(Dc/128, TOK/128, 3), 256, GSMEM>>>(
        xnh, xnl, wqkvh, wqkvl, bqkv, nullptr, nullptr, qkvh, qkvl,
        Dc, Dc, Dc, Dc,
        0, 0, (long long)DD, 0, (long long)TOK*Dc, 0, 1, 1.0f, (long long)Dc);

    // vfold transpose per (b,h): [b, s, h*128+d8] -> [(b,h), d8, s]
    transpose_bf16_pair<<<dim3(DKc/32, Sc/32, Bc*Hc), tb>>>(
        qkvh + (size_t)2*TOK*Dc, qkvl + (size_t)2*TOK*Dc, vfth, vftl,
        Dc, Sc, (long long)Sc*Dc, (long long)DKc, Hc, (long long)DKc*Sc);

    // scores = q @ k^T / sqrt(DK)
    gemm_hmma<0,0><<<dim3(Sc/128, Sc/128, Bc*Hc), 256, GSMEM>>>(
        qkvh, qkvl, qkvh + (size_t)TOK*Dc, qkvl + (size_t)TOK*Dc,
        nullptr, nullptr, p, nullptr, nullptr,
        DKc, Dc, Dc, Sc,
        (long long)Sc*Dc, (long long)DKc,
        (long long)Sc*Dc, (long long)DKc,
        (long long)Hc*Sc*Sc, (long long)Sc*Sc, Hc, 0.08838834764831845f, 0);

    softmax_split<<<Bc*Hc*Sc, 256>>>(p, ph, pl);

    // x1 = x + p @ vfT   (attn flat == out flat; resid fused)
    gemm_hmma<0,0><<<dim3(1, Sc/128, Bc*Hc), 256, GSMEM>>>(
        ph, pl, vfth, vftl, nullptr, x, x1, nullptr, nullptr,
        Sc, Sc, Sc, DKc,
        (long long)Sc*Sc, 0,
        (long long)DKc*Sc, 0,
        (long long)Sc*DKc, 0, 1, 1.0f, 0);

    // LN2
    ln_split<<<TOK, 256>>>(x1, g2, b2, xn2h, xn2l);

    // ff = gelu(xn2 @ W1 + bw1)
    gemm_hmma<1,1><<<dim3(FFc/128, TOK/128, 1), 256, GSMEM>>>(
        xn2h, xn2l, w1h, w1l, bw1, nullptr, nullptr, ffh, ffl,
        Dc, Dc, Dc, FFc, 0,0,0,0,0,0, 1, 1.0f, 0);

    // out = ff @ W2 + bw2 + x1
    gemm_hmma<0,0><<<dim3(Dc/128, TOK/128, 1), 256, GSMEM>>>(
        ffh, ffl, w2h, w2l, bw2, x1, out, nullptr, nullptr,
        FFc, FFc, FFc, Dc, 0,0,0,0,0,0, 1, 1.0f, 0);
}

// round 6
// speedup vs baseline: 8.9964x; 1.7376x over previous
#include <cuda_runtime.h>
#include <cuda_fp16.h>
#include <cstdint>
#include <math.h>

#define Bc 4
#define Sc 1024
#define Dc 1024
#define Hc 8
#define DKc 128
#define FFc 4096
#define TOK (Bc*Sc)
typedef __half h16;

// ---- scratch ----
__device__ __align__(16) h16 g_xn [TOK*Dc];
__device__ __align__(16) h16 g_xn2[TOK*Dc];
__device__ __align__(16) h16 g_wqkv[(size_t)3*Dc*Dc];
__device__ __align__(16) float g_bqkv[3*Dc];
__device__ __align__(16) h16 g_W1T[(size_t)FFc*Dc];
__device__ __align__(16) h16 g_W2T[(size_t)Dc*FFc];
__device__ __align__(16) h16 g_qkv[(size_t)3*TOK*Dc];
__device__ __align__(16) h16 g_vfT[(size_t)Bc*Hc*DKc*Sc];
__device__ __align__(16) float g_p[(size_t)Bc*Hc*Sc*Sc];
__device__ __align__(16) h16 g_ph[(size_t)Bc*Hc*Sc*Sc];
__device__ __align__(16) float g_x1[TOK*Dc];
__device__ __align__(16) h16 g_ff[(size_t)TOK*FFc];

// ---- helpers ----
__device__ __forceinline__ uint32_t smem_u32(const void* p) {
    uint32_t a;
    asm("{ .reg .u64 t; cvta.to.shared.u64 t, %1; cvt.u32.u64 %0, t; }" : "=r"(a) : "l"(p));
    return a;
}
#define CP16(dst, src) asm volatile("cp.async.cg.shared.global [%0], [%1], 16;" :: "r"(dst), "l"(src))
#define CP_COMMIT()    asm volatile("cp.async.commit_group;" ::: "memory")
#define CP_WAIT1()     asm volatile("cp.async.wait_group 1;" ::: "memory")

__device__ __forceinline__ void ldsm_x4(uint32_t& a0, uint32_t& a1, uint32_t& a2, uint32_t& a3, uint32_t addr) {
    asm volatile("ldmatrix.sync.aligned.m8n8.x4.shared.b16 {%0,%1,%2,%3}, [%4];"
                 : "=r"(a0), "=r"(a1), "=r"(a2), "=r"(a3) : "r"(addr));
}
__device__ __forceinline__ void ldsm_x2(uint32_t& b0, uint32_t& b1, uint32_t addr) {
    asm volatile("ldmatrix.sync.aligned.m8n8.x2.shared.b16 {%0,%1}, [%2];"
                 : "=r"(b0), "=r"(b1) : "r"(addr));
}
__device__ __forceinline__ void mma16816(float* c, uint32_t a0, uint32_t a1, uint32_t a2, uint32_t a3,
                                         uint32_t b0, uint32_t b1) {
    asm volatile("mma.sync.aligned.m16n8k16.row.col.f32.f16.f16.f32 "
                 "{%0,%1,%2,%3},{%4,%5,%6,%7},{%8,%9},{%0,%1,%2,%3};"
                 : "+f"(c[0]), "+f"(c[1]), "+f"(c[2]), "+f"(c[3])
                 : "r"(a0), "r"(a1), "r"(a2), "r"(a3), "r"(b0), "r"(b1));
}
__device__ __forceinline__ float gelu_exact(float v) {
    return 0.5f * v * (1.0f + erff(v * 0.70710678118654752f));
}

// ---- HMMA fp16 GEMM: 128x128 CTA tile, K-chunk 32, 3-stage cp.async ----
// A[M,K] @ B[N,K]^T, fp16 operands, fp32 accum.
// Stage layout: A 128x32 (8KB) at +0, B 128x32 (8KB) at +8192.
#define STAGE_B 16384
#define GSMEM   (3*STAGE_B)

template<int ACT, int OUTMODE>
__global__ void __launch_bounds__(256, 1)
gemm_hmma(const h16* __restrict__ Ah, const h16* __restrict__ Bh,
          const float* __restrict__ bias, const float* __restrict__ resid,
          float* __restrict__ C, h16* __restrict__ Ch,
          int K, int lda, int ldb, int ldc,
          long long sA0, long long sA1, long long sB0, long long sB1,
          long long sC0, long long sC1, int innerB, float alpha, long long biasStride)
{
    extern __shared__ char smem[];
    const uint32_t smb = smem_u32(smem);
    const int tid = threadIdx.x, lane = tid & 31, wid = tid >> 5;
    const int z = blockIdx.z, zo = z / innerB, zi = z - zo * innerB;
    const long long aoff = zo * sA0 + zi * sA1;
    const long long boff = zo * sB0 + zi * sB1;
    const long long coff = zo * sC0 + zi * sC1;
    if (bias) bias += (long long)z * biasStride;
    const int m0 = blockIdx.y * 128, n0 = blockIdx.x * 128;
    const int wm = (wid & 1) * 64, wn = (wid >> 1) * 32;

    const int row = tid >> 2;
    const int cch = tid & 3;

    float acc[4][4][4];
    #pragma unroll
    for (int i = 0; i < 4; i++)
        #pragma unroll
        for (int j = 0; j < 4; j++)
            #pragma unroll
            for (int t = 0; t < 4; t++) acc[i][j][t] = 0.f;

    const int nck = K >> 5;

    auto load_chunk = [&](int kk, int s) {
        const int k0 = kk << 5;
        const uint32_t st = smb + s * STAGE_B;
        #pragma unroll
        for (int rep = 0; rep < 2; rep++) {
            const int r = row + rep * 64;
            const uint32_t so = r * 64 + ((cch ^ (r & 3)) << 4);
            CP16(st + so,        Ah + (size_t)aoff + (size_t)(m0 + r) * lda + k0 + cch * 8);
            CP16(st + 8192 + so, Bh + (size_t)boff + (size_t)(n0 + r) * ldb + k0 + cch * 8);
        }
        CP_COMMIT();
    };

    load_chunk(0, 0);
    load_chunk(1, 1);

    for (int kk = 0; kk < nck; kk++) {
        CP_WAIT1();
        __syncthreads();
        if (kk + 2 < nck) load_chunk(kk + 2, (kk + 2) % 3);
        else CP_COMMIT();

        const uint32_t st = smb + (kk % 3) * STAGE_B;
        #pragma unroll
        for (int ks = 0; ks < 2; ks++) {
            uint32_t ah[4][4], bh[4][2];
            #pragma unroll
            for (int mf = 0; mf < 4; mf++) {
                const int r = wm + mf * 16 + (lane & 15);
                const int ch = ks * 2 + (lane >> 4);
                ldsm_x4(ah[mf][0], ah[mf][1], ah[mf][2], ah[mf][3],
                        st + r * 64 + ((ch ^ (r & 3)) << 4));
            }
            #pragma unroll
            for (int nf = 0; nf < 4; nf++) {
                const int r = wn + nf * 8 + (lane & 7);
                const int ch = ks * 2 + ((lane >> 3) & 1);
                ldsm_x2(bh[nf][0], bh[nf][1],
                        st + 8192 + r * 64 + ((ch ^ (r & 3)) << 4));
            }
            #pragma unroll
            for (int mf = 0; mf < 4; mf++)
                #pragma unroll
                for (int nf = 0; nf < 4; nf++)
                    mma16816(acc[mf][nf], ah[mf][0], ah[mf][1], ah[mf][2], ah[mf][3], bh[nf][0], bh[nf][1]);
        }
        __syncthreads();
    }

    // ---- epilogue ----
    #pragma unroll
    for (int mf = 0; mf < 4; mf++) {
        const int r0 = m0 + wm + mf * 16 + (lane >> 2);
        const int r1 = r0 + 8;
        #pragma unroll
        for (int nf = 0; nf < 4; nf++) {
            const int col = n0 + wn + nf * 8 + (lane & 3) * 2;
            float b0 = 0.f, b1 = 0.f;
            if (bias) { b0 = __ldg(bias + col); b1 = __ldg(bias + col + 1); }
            float v0 = acc[mf][nf][0] * alpha + b0;
            float v1 = acc[mf][nf][1] * alpha + b1;
            float v2 = acc[mf][nf][2] * alpha + b0;
            float v3 = acc[mf][nf][3] * alpha + b1;
            if (ACT == 1) {
                v0 = gelu_exact(v0); v1 = gelu_exact(v1);
                v2 = gelu_exact(v2); v3 = gelu_exact(v3);
            }
            const size_t i0 = (size_t)coff + (size_t)r0 * ldc + col;
            const size_t i1 = (size_t)coff + (size_t)r1 * ldc + col;
            if (OUTMODE == 0) {
                if (resid) {
                    float2 q0 = *(const float2*)(resid + i0);
                    float2 q1 = *(const float2*)(resid + i1);
                    v0 += q0.x; v1 += q0.y; v2 += q1.x; v3 += q1.y;
                }
                *(float2*)(C + i0) = make_float2(v0, v1);
                *(float2*)(C + i1) = make_float2(v2, v3);
            } else {
                __half2 p0 = __floats2half2_rn(v0, v1);
                __half2 p1 = __floats2half2_rn(v2, v3);
                *(__half2*)(Ch + i0) = p0;
                *(__half2*)(Ch + i1) = p1;
            }
        }
    }
}

// ---- layernorm -> fp16 ----
__global__ void __launch_bounds__(256)
ln_half(const float* __restrict__ x, const float* __restrict__ g,
        const float* __restrict__ b, h16* __restrict__ o)
{
    const long long row = blockIdx.x;
    const int tid = threadIdx.x;
    float4 v = *(const float4*)(x + row * Dc + tid * 4);
    float s = v.x+v.y+v.z+v.w, ss = v.x*v.x+v.y*v.y+v.z*v.z+v.w*v.w;
    __shared__ float shs[8], shq[8];
    #pragma unroll
    for (int o2 = 16; o2; o2 >>= 1) { s += __shfl_xor_sync(~0u,s,o2); ss += __shfl_xor_sync(~0u,ss,o2); }
    if ((tid & 31) == 0) { shs[tid>>5] = s; shq[tid>>5] = ss; }
    __syncthreads();
    float st=0.f, qt=0.f;
    #pragma unroll
    for (int i = 0; i < 8; i++) { st += shs[i]; qt += shq[i]; }
    const float m = st * (1.f/Dc), inv = rsqrtf(qt*(1.f/Dc) - m*m + 1e-5f);
    float4 gv = *(const float4*)(g + tid*4);
    float4 bv = *(const float4*)(b + tid*4);
    __half2 h0 = __floats2half2_rn((v.x-m)*inv*gv.x+bv.x, (v.y-m)*inv*gv.y+bv.y);
    __half2 h1 = __floats2half2_rn((v.z-m)*inv*gv.z+bv.z, (v.w-m)*inv*gv.w+bv.w);
    uint2 pk; pk.x = *(uint32_t*)&h0; pk.y = *(uint32_t*)&h1;
    *(uint2*)(o + row*Dc + tid*4) = pk;
}

// ---- softmax fp32 -> fp16 ----
__global__ void __launch_bounds__(256)
softmax_half(const float* __restrict__ p, h16* __restrict__ o)
{
    const long long row = blockIdx.x;
    const int tid = threadIdx.x;
    float4 v = *(const float4*)(p + row * 1024 + tid * 4);
    float mx = fmaxf(fmaxf(v.x,v.y), fmaxf(v.z,v.w));
    __shared__ float sh[8];
    #pragma unroll
    for (int o2 = 16; o2; o2 >>= 1) mx = fmaxf(mx, __shfl_xor_sync(~0u,mx,o2));
    if ((tid & 31) == 0) sh[tid>>5] = mx;
    __syncthreads();
    float m = sh[0];
    #pragma unroll
    for (int i = 1; i < 8; i++) m = fmaxf(m, sh[i]);
    __syncthreads();
    v.x=__expf(v.x-m); v.y=__expf(v.y-m); v.z=__expf(v.z-m); v.w=__expf(v.w-m);
    float s = v.x+v.y+v.z+v.w;
    #pragma unroll
    for (int o2 = 16; o2; o2 >>= 1) s += __shfl_xor_sync(~0u,s,o2);
    if ((tid & 31) == 0) sh[tid>>5] = s;
    __syncthreads();
    float tot = 0.f;
    #pragma unroll
    for (int i = 0; i < 8; i++) tot += sh[i];
    const float inv = 1.f / tot;
    __half2 h0 = __floats2half2_rn(v.x*inv, v.y*inv);
    __half2 h1 = __floats2half2_rn(v.z*inv, v.w*inv);
    uint2 pk; pk.x = *(uint32_t*)&h0; pk.y = *(uint32_t*)&h1;
    *(uint2*)(o + row*1024 + tid*4) = pk;
}

// ---- fp32 transpose -> fp16: out[c][r] = in[r][c] ----
__global__ void __launch_bounds__(256)
transpose_half(const float* __restrict__ in, h16* __restrict__ o, int ldin, int ldo)
{
    __shared__ float t[32][33];
    const int c0 = blockIdx.x * 32, r0 = blockIdx.y * 32;
    const int tx = threadIdx.x, ty = threadIdx.y;
    #pragma unroll
    for (int i = 0; i < 4; i++)
        t[ty + i*8][tx] = in[(size_t)(r0 + ty + i*8) * ldin + c0 + tx];
    __syncthreads();
    #pragma unroll
    for (int i = 0; i < 4; i++)
        o[(size_t)(c0 + ty + i*8) * ldo + r0 + tx] = __float2half_rn(t[tx][ty + i*8]);
}

// ---- fold Wv [1024 x 8192] -> WvfT [1024(nf) x 1024(k)] fp16 ----
__global__ void __launch_bounds__(256)
fold_wv(const float* __restrict__ Wv, h16* __restrict__ o)
{
    __shared__ float sf[32][33];
    const int k0 = blockIdx.x * 32, nf0 = blockIdx.y * 32;
    const int tx = threadIdx.x, ty = threadIdx.y;
    #pragma unroll
    for (int rep = 0; rep < 4; rep++) {
        const int row = ty + rep * 8;
        const float* src = Wv + (size_t)(k0 + row) * (Hc*Dc) + (size_t)(nf0 + tx) * 8;
        float4 a = *(const float4*)src;
        float4 b = *(const float4*)(src + 4);
        sf[row][tx] = a.x + a.y + a.z + a.w + b.x + b.y + b.z + b.w;
    }
    __syncthreads();
    #pragma unroll
    for (int rep = 0; rep < 4; rep++) {
        const int nf = ty + rep * 8;
        o[(size_t)(nf0 + nf) * Dc + k0 + tx] = __float2half_rn(sf[tx][nf]);
    }
}

// ---- bias prep: bqkv = [bq | bk | fold8(bv)] ----
__global__ void prep_bias(const float* __restrict__ bq, const float* __restrict__ bk,
                          const float* __restrict__ bv, float* __restrict__ bqkv)
{
    const int i = blockIdx.x * blockDim.x + threadIdx.x;
    bqkv[i] = bq[i];
    bqkv[Dc + i] = bk[i];
    const float* s = bv + (size_t)i * 8;
    float t = 0.f;
    #pragma unroll
    for (int j = 0; j < 8; j++) t += s[j];
    bqkv[2*Dc + i] = t;
}

// ---- fp16 batched transpose: out[z][c][r] = in[base(z) + r*ldin + c] ----
__global__ void __launch_bounds__(256)
transpose_h16(const h16* __restrict__ in, h16* __restrict__ o,
              int ldin, int ldo, long long zi0, long long zi1, int innerZ, long long zos)
{
    __shared__ h16 t[32][33];
    const int z = blockIdx.z;
    const long long base = (long long)(z / innerZ) * zi0 + (long long)(z % innerZ) * zi1;
    const int c0 = blockIdx.x * 32, r0 = blockIdx.y * 32;
    const int tx = threadIdx.x, ty = threadIdx.y;
    #pragma unroll
    for (int i = 0; i < 4; i++)
        t[ty + i*8][tx] = in[base + (size_t)(r0 + ty + i*8) * ldin + c0 + tx];
    __syncthreads();
    #pragma unroll
    for (int i = 0; i < 4; i++)
        o[(size_t)z * zos + (size_t)(c0 + ty + i*8) * ldo + r0 + tx] = t[tx][ty + i*8];
}

#define SYM(p, s) cudaGetSymbolAddress((void**)&p, s)

extern "C" void kernel_launch(void* const* d_in, const int* in_sizes, int n_in,
                              void* d_out, int out_size)
{
    (void)in_sizes; (void)n_in; (void)out_size;
    const float* x   = (const float*)d_in[0];
    const float* g1  = (const float*)d_in[2];
    const float* b1  = (const float*)d_in[3];
    const float* Wq  = (const float*)d_in[4];
    const float* bq  = (const float*)d_in[5];
    const float* Wk  = (const float*)d_in[6];
    const float* bk  = (const float*)d_in[7];
    const float* Wv  = (const float*)d_in[8];
    const float* bv  = (const float*)d_in[9];
    const float* g2  = (const float*)d_in[10];
    const float* b2  = (const float*)d_in[11];
    const float* W1  = (const float*)d_in[12];
    const float* bw1 = (const float*)d_in[13];
    const float* W2  = (const float*)d_in[14];
    const float* bw2 = (const float*)d_in[15];
    float* out = (float*)d_out;

    h16 *xn,*xn2,*wqkv,*w1t,*w2t,*qkv,*vft,*ph,*ff;
    float *bqkv,*p,*x1;
    SYM(xn,g_xn); SYM(xn2,g_xn2);
    SYM(wqkv,g_wqkv); SYM(bqkv,g_bqkv);
    SYM(w1t,g_W1T); SYM(w2t,g_W2T);
    SYM(qkv,g_qkv); SYM(vft,g_vfT);
    SYM(ph,g_ph); SYM(ff,g_ff);
    SYM(p,g_p); SYM(x1,g_x1);

    cudaFuncSetAttribute(gemm_hmma<0,0>, cudaFuncAttributeMaxDynamicSharedMemorySize, GSMEM);
    cudaFuncSetAttribute(gemm_hmma<0,1>, cudaFuncAttributeMaxDynamicSharedMemorySize, GSMEM);
    cudaFuncSetAttribute(gemm_hmma<1,1>, cudaFuncAttributeMaxDynamicSharedMemorySize, GSMEM);

    const dim3 tb(32, 8);
    const size_t DD = (size_t)Dc*Dc;

    // weight prep
    prep_bias<<<4, 256>>>(bq, bk, bv, bqkv);
    transpose_half<<<dim3(Dc/32, Dc/32), tb>>>(Wq, wqkv,      Dc, Dc);
    transpose_half<<<dim3(Dc/32, Dc/32), tb>>>(Wk, wqkv+DD,   Dc, Dc);
    fold_wv<<<dim3(32, 32), tb>>>(Wv, wqkv+2*DD);
    transpose_half<<<dim3(FFc/32, Dc/32), tb>>>(W1, w1t, FFc, Dc);
    transpose_half<<<dim3(Dc/32, FFc/32), tb>>>(W2, w2t, Dc,  FFc);

    // LN1
    ln_half<<<TOK, 256>>>(x, g1, b1, xn);

    // QKV(folded) fused: z=3 -> qkv [3][TOK][Dc] fp16
    gemm_hmma<0,1><<<dim3(Dc/128, TOK/128, 3), 256, GSMEM>>>(
        xn, wqkv, bqkv, nullptr, nullptr, qkv,
        Dc, Dc, Dc, Dc,
        0, 0, (long long)DD, 0, (long long)TOK*Dc, 0, 1, 1.0f, (long long)Dc);

    // vfold transpose per (b,h): [b, s, h*128+d8] -> [(b,h), d8, s]
    transpose_h16<<<dim3(DKc/32, Sc/32, Bc*Hc), tb>>>(
        qkv + (size_t)2*TOK*Dc, vft,
        Dc, Sc, (long long)Sc*Dc, (long long)DKc, Hc, (long long)DKc*Sc);

    // scores = q @ k^T / sqrt(DK)
    gemm_hmma<0,0><<<dim3(Sc/128, Sc/128, Bc*Hc), 256, GSMEM>>>(
        qkv, qkv + (size_t)TOK*Dc, nullptr, nullptr, p, nullptr,
        DKc, Dc, Dc, Sc,
        (long long)Sc*Dc, (long long)DKc,
        (long long)Sc*Dc, (long long)DKc,
        (long long)Hc*Sc*Sc, (long long)Sc*Sc, Hc, 0.08838834764831845f, 0);

    softmax_half<<<Bc*Hc*Sc, 256>>>(p, ph);

    // x1 = x + p @ vfT
    gemm_hmma<0,0><<<dim3(1, Sc/128, Bc*Hc), 256, GSMEM>>>(
        ph, vft, nullptr, x, x1, nullptr,
        Sc, Sc, Sc, DKc,
        (long long)Sc*Sc, 0,
        (long long)DKc*Sc, 0,
        (long long)Sc*DKc, 0, 1, 1.0f, 0);

    // LN2
    ln_half<<<TOK, 256>>>(x1, g2, b2, xn2);

    // ff = gelu(xn2 @ W1 + bw1)
    gemm_hmma<1,1><<<dim3(FFc/128, TOK/128, 1), 256, GSMEM>>>(
        xn2, w1t, bw1, nullptr, nullptr, ff,
        Dc, Dc, Dc, FFc, 0,0,0,0,0,0, 1, 1.0f, 0);

    // out = ff @ W2 + bw2 + x1
    gemm_hmma<0,0><<<dim3(Dc/128, TOK/128, 1), 256, GSMEM>>>(
        ff, w2t, bw2, x1, out, nullptr,
        FFc, FFc, FFc, Dc, 0,0,0,0,0,0, 1, 1.0f, 0);
}

// round 7
// speedup vs baseline: 10.1193x; 1.1248x over previous
#include <cuda_runtime.h>
#include <cuda_fp16.h>
#include <cstdint>
#include <math.h>

#define Bc 4
#define Sc 1024
#define Dc 1024
#define Hc 8
#define DKc 128
#define FFc 4096
#define TOK (Bc*Sc)
typedef __half h16;

// ---- scratch ----
__device__ __align__(16) h16 g_xn [TOK*Dc];
__device__ __align__(16) h16 g_xn2[TOK*Dc];
__device__ __align__(16) h16 g_wqkv[(size_t)3*Dc*Dc];
__device__ __align__(16) float g_bqkv[3*Dc];
__device__ __align__(16) h16 g_W1T[(size_t)FFc*Dc];
__device__ __align__(16) h16 g_W2T[(size_t)Dc*FFc];
__device__ __align__(16) h16 g_qkv[(size_t)3*TOK*Dc];
__device__ __align__(16) h16 g_vfT[(size_t)Bc*Hc*DKc*Sc];
__device__ __align__(16) float g_x1[TOK*Dc];
__device__ __align__(16) h16 g_ff[(size_t)TOK*FFc];

// ---- helpers ----
__device__ __forceinline__ uint32_t smem_u32(const void* p) {
    uint32_t a;
    asm("{ .reg .u64 t; cvta.to.shared.u64 t, %1; cvt.u32.u64 %0, t; }" : "=r"(a) : "l"(p));
    return a;
}
#define CP16(dst, src) asm volatile("cp.async.cg.shared.global [%0], [%1], 16;" :: "r"(dst), "l"(src))
#define CP_COMMIT()    asm volatile("cp.async.commit_group;" ::: "memory")
#define CP_WAIT1()     asm volatile("cp.async.wait_group 1;" ::: "memory")

__device__ __forceinline__ void ldsm_x4(uint32_t& a0, uint32_t& a1, uint32_t& a2, uint32_t& a3, uint32_t addr) {
    asm volatile("ldmatrix.sync.aligned.m8n8.x4.shared.b16 {%0,%1,%2,%3}, [%4];"
                 : "=r"(a0), "=r"(a1), "=r"(a2), "=r"(a3) : "r"(addr));
}
__device__ __forceinline__ void ldsm_x2(uint32_t& b0, uint32_t& b1, uint32_t addr) {
    asm volatile("ldmatrix.sync.aligned.m8n8.x2.shared.b16 {%0,%1}, [%2];"
                 : "=r"(b0), "=r"(b1) : "r"(addr));
}
__device__ __forceinline__ void mma16816(float* c, uint32_t a0, uint32_t a1, uint32_t a2, uint32_t a3,
                                         uint32_t b0, uint32_t b1) {
    asm volatile("mma.sync.aligned.m16n8k16.row.col.f32.f16.f16.f32 "
                 "{%0,%1,%2,%3},{%4,%5,%6,%7},{%8,%9},{%0,%1,%2,%3};"
                 : "+f"(c[0]), "+f"(c[1]), "+f"(c[2]), "+f"(c[3])
                 : "r"(a0), "r"(a1), "r"(a2), "r"(a3), "r"(b0), "r"(b1));
}
__device__ __forceinline__ float gelu_exact(float v) {
    return 0.5f * v * (1.0f + erff(v * 0.70710678118654752f));
}

// ---- HMMA fp16 GEMM: 128x128 CTA tile, K-chunk 32, 3-stage cp.async ----
#define STAGE_B 16384
#define GSMEM   (3*STAGE_B)

template<int ACT, int OUTMODE>
__global__ void __launch_bounds__(256, 1)
gemm_hmma(const h16* __restrict__ Ah, const h16* __restrict__ Bh,
          const float* __restrict__ bias, const float* __restrict__ resid,
          float* __restrict__ C, h16* __restrict__ Ch,
          int K, int lda, int ldb, int ldc,
          long long sA0, long long sA1, long long sB0, long long sB1,
          long long sC0, long long sC1, int innerB, float alpha, long long biasStride)
{
    extern __shared__ char smem[];
    const uint32_t smb = smem_u32(smem);
    const int tid = threadIdx.x, lane = tid & 31, wid = tid >> 5;
    const int z = blockIdx.z, zo = z / innerB, zi = z - zo * innerB;
    const long long aoff = zo * sA0 + zi * sA1;
    const long long boff = zo * sB0 + zi * sB1;
    const long long coff = zo * sC0 + zi * sC1;
    if (bias) bias += (long long)z * biasStride;
    const int m0 = blockIdx.y * 128, n0 = blockIdx.x * 128;
    const int wm = (wid & 1) * 64, wn = (wid >> 1) * 32;

    const int row = tid >> 2;
    const int cch = tid & 3;

    float acc[4][4][4];
    #pragma unroll
    for (int i = 0; i < 4; i++)
        #pragma unroll
        for (int j = 0; j < 4; j++)
            #pragma unroll
            for (int t = 0; t < 4; t++) acc[i][j][t] = 0.f;

    const int nck = K >> 5;

    auto load_chunk = [&](int kk, int s) {
        const int k0 = kk << 5;
        const uint32_t st = smb + s * STAGE_B;
        #pragma unroll
        for (int rep = 0; rep < 2; rep++) {
            const int r = row + rep * 64;
            const uint32_t so = r * 64 + ((cch ^ (r & 3)) << 4);
            CP16(st + so,        Ah + (size_t)aoff + (size_t)(m0 + r) * lda + k0 + cch * 8);
            CP16(st + 8192 + so, Bh + (size_t)boff + (size_t)(n0 + r) * ldb + k0 + cch * 8);
        }
        CP_COMMIT();
    };

    load_chunk(0, 0);
    load_chunk(1, 1);

    for (int kk = 0; kk < nck; kk++) {
        CP_WAIT1();
        __syncthreads();
        if (kk + 2 < nck) load_chunk(kk + 2, (kk + 2) % 3);
        else CP_COMMIT();

        const uint32_t st = smb + (kk % 3) * STAGE_B;
        #pragma unroll
        for (int ks = 0; ks < 2; ks++) {
            uint32_t ah[4][4], bh[4][2];
            #pragma unroll
            for (int mf = 0; mf < 4; mf++) {
                const int r = wm + mf * 16 + (lane & 15);
                const int ch = ks * 2 + (lane >> 4);
                ldsm_x4(ah[mf][0], ah[mf][1], ah[mf][2], ah[mf][3],
                        st + r * 64 + ((ch ^ (r & 3)) << 4));
            }
            #pragma unroll
            for (int nf = 0; nf < 4; nf++) {
                const int r = wn + nf * 8 + (lane & 7);
                const int ch = ks * 2 + ((lane >> 3) & 1);
                ldsm_x2(bh[nf][0], bh[nf][1],
                        st + 8192 + r * 64 + ((ch ^ (r & 3)) << 4));
            }
            #pragma unroll
            for (int mf = 0; mf < 4; mf++)
                #pragma unroll
                for (int nf = 0; nf < 4; nf++)
                    mma16816(acc[mf][nf], ah[mf][0], ah[mf][1], ah[mf][2], ah[mf][3], bh[nf][0], bh[nf][1]);
        }
        __syncthreads();
    }

    #pragma unroll
    for (int mf = 0; mf < 4; mf++) {
        const int r0 = m0 + wm + mf * 16 + (lane >> 2);
        const int r1 = r0 + 8;
        #pragma unroll
        for (int nf = 0; nf < 4; nf++) {
            const int col = n0 + wn + nf * 8 + (lane & 3) * 2;
            float b0 = 0.f, b1 = 0.f;
            if (bias) { b0 = __ldg(bias + col); b1 = __ldg(bias + col + 1); }
            float v0 = acc[mf][nf][0] * alpha + b0;
            float v1 = acc[mf][nf][1] * alpha + b1;
            float v2 = acc[mf][nf][2] * alpha + b0;
            float v3 = acc[mf][nf][3] * alpha + b1;
            if (ACT == 1) {
                v0 = gelu_exact(v0); v1 = gelu_exact(v1);
                v2 = gelu_exact(v2); v3 = gelu_exact(v3);
            }
            const size_t i0 = (size_t)coff + (size_t)r0 * ldc + col;
            const size_t i1 = (size_t)coff + (size_t)r1 * ldc + col;
            if (OUTMODE == 0) {
                if (resid) {
                    float2 q0 = *(const float2*)(resid + i0);
                    float2 q1 = *(const float2*)(resid + i1);
                    v0 += q0.x; v1 += q0.y; v2 += q1.x; v3 += q1.y;
                }
                *(float2*)(C + i0) = make_float2(v0, v1);
                *(float2*)(C + i1) = make_float2(v2, v3);
            } else {
                __half2 p0 = __floats2half2_rn(v0, v1);
                __half2 p1 = __floats2half2_rn(v2, v3);
                *(__half2*)(Ch + i0) = p0;
                *(__half2*)(Ch + i1) = p1;
            }
        }
    }
}

// ---- fused flash attention: out = softmax(q k^T / sqrt(128)) @ vfT^T + x ----
// grid (Sc/128, B*H); 8 warps, warp w owns q rows [w*16, w*16+16).
// smem: q 32KB + 3 stages x (k 32KB | v 32KB).
#define FA_STAGE 65536
#define FA_SMEM  (32768 + 3*FA_STAGE)

__global__ void __launch_bounds__(256, 1)
flash_attn(const h16* __restrict__ qg, const h16* __restrict__ kg,
           const h16* __restrict__ vfT, const float* __restrict__ x,
           float* __restrict__ x1)
{
    extern __shared__ char smem[];
    const uint32_t smb = smem_u32(smem);
    const int qt = blockIdx.x, z = blockIdx.y;
    const int b = z >> 3, h = z & 7;
    const int tid = threadIdx.x, lane = tid & 31, wid = tid >> 5;

    const size_t qkbase = (size_t)b * Sc * Dc + (size_t)h * DKc;
    const size_t vbase  = (size_t)z * DKc * Sc;

    const int row = tid >> 2;      // 0..63
    const int cch = tid & 3;

    // q tile load (group 0 includes q + kv0)
    {
        #pragma unroll
        for (int slab = 0; slab < 4; slab++)
            #pragma unroll
            for (int rep = 0; rep < 2; rep++) {
                const int r = row + rep * 64;
                const uint32_t so = slab * 8192 + r * 64 + ((cch ^ (r & 3)) << 4);
                CP16(smb + so, qg + qkbase + (size_t)(qt * 128 + r) * Dc + slab * 32 + cch * 8);
            }
    }
    auto load_kv = [&](int kt, int st) {
        const uint32_t sb = smb + 32768 + st * FA_STAGE;
        #pragma unroll
        for (int slab = 0; slab < 4; slab++)
            #pragma unroll
            for (int rep = 0; rep < 2; rep++) {
                const int r = row + rep * 64;
                const uint32_t so = slab * 8192 + r * 64 + ((cch ^ (r & 3)) << 4);
                CP16(sb + so,         kg  + qkbase + (size_t)(kt * 128 + r) * Dc + slab * 32 + cch * 8);
                CP16(sb + 32768 + so, vfT + vbase  + (size_t)r * Sc + kt * 128 + slab * 32 + cch * 8);
            }
        CP_COMMIT();
    };
    load_kv(0, 0);
    load_kv(1, 1);

    uint32_t aq[8][4];
    float acc_o[16][4];
    #pragma unroll
    for (int nf = 0; nf < 16; nf++)
        #pragma unroll
        for (int t = 0; t < 4; t++) acc_o[nf][t] = 0.f;
    float m0 = -1e30f, m1 = -1e30f, l0 = 0.f, l1 = 0.f;
    const float scale = 0.08838834764831845f;

    for (int kt = 0; kt < 8; kt++) {
        CP_WAIT1();
        __syncthreads();
        if (kt + 2 < 8) load_kv(kt + 2, (kt + 2) % 3);
        else CP_COMMIT();

        if (kt == 0) {   // q fragments (once; q arrived with group 0)
            #pragma unroll
            for (int kc = 0; kc < 8; kc++) {
                const int slab = kc >> 1, ks = kc & 1;
                const int r = wid * 16 + (lane & 15);
                const int ch = ks * 2 + (lane >> 4);
                ldsm_x4(aq[kc][0], aq[kc][1], aq[kc][2], aq[kc][3],
                        smb + slab * 8192 + r * 64 + ((ch ^ (r & 3)) << 4));
            }
        }

        const uint32_t sbk = smb + 32768 + (kt % 3) * FA_STAGE;
        const uint32_t sbv = sbk + 32768;

        // ---- S = q @ k^T ----
        float s_acc[16][4];
        #pragma unroll
        for (int nf = 0; nf < 16; nf++)
            #pragma unroll
            for (int t = 0; t < 4; t++) s_acc[nf][t] = 0.f;
        #pragma unroll
        for (int kc = 0; kc < 8; kc++) {
            const int slab = kc >> 1, ks = kc & 1;
            #pragma unroll
            for (int nf = 0; nf < 16; nf++) {
                const int r = nf * 8 + (lane & 7);
                const int ch = ks * 2 + ((lane >> 3) & 1);
                uint32_t b0, b1;
                ldsm_x2(b0, b1, sbk + slab * 8192 + r * 64 + ((ch ^ (r & 3)) << 4));
                mma16816(s_acc[nf], aq[kc][0], aq[kc][1], aq[kc][2], aq[kc][3], b0, b1);
            }
        }

        // ---- online softmax ----
        float mx0 = -1e30f, mx1 = -1e30f;
        #pragma unroll
        for (int nf = 0; nf < 16; nf++) {
            s_acc[nf][0] *= scale; s_acc[nf][1] *= scale;
            s_acc[nf][2] *= scale; s_acc[nf][3] *= scale;
            mx0 = fmaxf(mx0, fmaxf(s_acc[nf][0], s_acc[nf][1]));
            mx1 = fmaxf(mx1, fmaxf(s_acc[nf][2], s_acc[nf][3]));
        }
        mx0 = fmaxf(mx0, __shfl_xor_sync(~0u, mx0, 1));
        mx0 = fmaxf(mx0, __shfl_xor_sync(~0u, mx0, 2));
        mx1 = fmaxf(mx1, __shfl_xor_sync(~0u, mx1, 1));
        mx1 = fmaxf(mx1, __shfl_xor_sync(~0u, mx1, 2));
        const float mn0 = fmaxf(m0, mx0), mn1 = fmaxf(m1, mx1);
        const float a0 = __expf(m0 - mn0), a1 = __expf(m1 - mn1);
        m0 = mn0; m1 = mn1;

        float rs0 = 0.f, rs1 = 0.f;
        #pragma unroll
        for (int nf = 0; nf < 16; nf++) {
            s_acc[nf][0] = __expf(s_acc[nf][0] - mn0);
            s_acc[nf][1] = __expf(s_acc[nf][1] - mn0);
            s_acc[nf][2] = __expf(s_acc[nf][2] - mn1);
            s_acc[nf][3] = __expf(s_acc[nf][3] - mn1);
            rs0 += s_acc[nf][0] + s_acc[nf][1];
            rs1 += s_acc[nf][2] + s_acc[nf][3];
        }
        rs0 += __shfl_xor_sync(~0u, rs0, 1); rs0 += __shfl_xor_sync(~0u, rs0, 2);
        rs1 += __shfl_xor_sync(~0u, rs1, 1); rs1 += __shfl_xor_sync(~0u, rs1, 2);
        l0 = l0 * a0 + rs0; l1 = l1 * a1 + rs1;
        #pragma unroll
        for (int nf = 0; nf < 16; nf++) {
            acc_o[nf][0] *= a0; acc_o[nf][1] *= a0;
            acc_o[nf][2] *= a1; acc_o[nf][3] *= a1;
        }

        // ---- acc_o += P @ V  (P from registers) ----
        #pragma unroll
        for (int kc = 0; kc < 8; kc++) {
            const int slab = kc >> 1, ks = kc & 1;
            __half2 pa0 = __floats2half2_rn(s_acc[2*kc][0],   s_acc[2*kc][1]);
            __half2 pa1 = __floats2half2_rn(s_acc[2*kc][2],   s_acc[2*kc][3]);
            __half2 pa2 = __floats2half2_rn(s_acc[2*kc+1][0], s_acc[2*kc+1][1]);
            __half2 pa3 = __floats2half2_rn(s_acc[2*kc+1][2], s_acc[2*kc+1][3]);
            const uint32_t u0 = *(uint32_t*)&pa0, u1 = *(uint32_t*)&pa1;
            const uint32_t u2 = *(uint32_t*)&pa2, u3 = *(uint32_t*)&pa3;
            #pragma unroll
            for (int nf = 0; nf < 16; nf++) {
                const int r = nf * 8 + (lane & 7);
                const int ch = ks * 2 + ((lane >> 3) & 1);
                uint32_t b0, b1;
                ldsm_x2(b0, b1, sbv + slab * 8192 + r * 64 + ((ch ^ (r & 3)) << 4));
                mma16816(acc_o[nf], u0, u1, u2, u3, b0, b1);
            }
        }
        __syncthreads();
    }

    // ---- epilogue: x1 = x + acc_o / l ----
    const float inv0 = 1.f / l0, inv1 = 1.f / l1;
    const size_t zbase = (size_t)z * Sc * DKc;
    const int gr0 = qt * 128 + wid * 16 + (lane >> 2);
    #pragma unroll
    for (int nf = 0; nf < 16; nf++) {
        const int col = nf * 8 + (lane & 3) * 2;
        const size_t i0 = zbase + (size_t)gr0 * DKc + col;
        const size_t i1 = i0 + 8 * DKc;
        float2 r0 = *(const float2*)(x + i0);
        float2 r1 = *(const float2*)(x + i1);
        *(float2*)(x1 + i0) = make_float2(acc_o[nf][0] * inv0 + r0.x, acc_o[nf][1] * inv0 + r0.y);
        *(float2*)(x1 + i1) = make_float2(acc_o[nf][2] * inv1 + r1.x, acc_o[nf][3] * inv1 + r1.y);
    }
}

// ---- layernorm -> fp16 ----
__global__ void __launch_bounds__(256)
ln_half(const float* __restrict__ x, const float* __restrict__ g,
        const float* __restrict__ b, h16* __restrict__ o)
{
    const long long row = blockIdx.x;
    const int tid = threadIdx.x;
    float4 v = *(const float4*)(x + row * Dc + tid * 4);
    float s = v.x+v.y+v.z+v.w, ss = v.x*v.x+v.y*v.y+v.z*v.z+v.w*v.w;
    __shared__ float shs[8], shq[8];
    #pragma unroll
    for (int o2 = 16; o2; o2 >>= 1) { s += __shfl_xor_sync(~0u,s,o2); ss += __shfl_xor_sync(~0u,ss,o2); }
    if ((tid & 31) == 0) { shs[tid>>5] = s; shq[tid>>5] = ss; }
    __syncthreads();
    float st=0.f, qt=0.f;
    #pragma unroll
    for (int i = 0; i < 8; i++) { st += shs[i]; qt += shq[i]; }
    const float m = st * (1.f/Dc), inv = rsqrtf(qt*(1.f/Dc) - m*m + 1e-5f);
    float4 gv = *(const float4*)(g + tid*4);
    float4 bv = *(const float4*)(b + tid*4);
    __half2 h0 = __floats2half2_rn((v.x-m)*inv*gv.x+bv.x, (v.y-m)*inv*gv.y+bv.y);
    __half2 h1 = __floats2half2_rn((v.z-m)*inv*gv.z+bv.z, (v.w-m)*inv*gv.w+bv.w);
    uint2 pk; pk.x = *(uint32_t*)&h0; pk.y = *(uint32_t*)&h1;
    *(uint2*)(o + row*Dc + tid*4) = pk;
}

// ---- fp32 transpose -> fp16 ----
__global__ void __launch_bounds__(256)
transpose_half(const float* __restrict__ in, h16* __restrict__ o, int ldin, int ldo)
{
    __shared__ float t[32][33];
    const int c0 = blockIdx.x * 32, r0 = blockIdx.y * 32;
    const int tx = threadIdx.x, ty = threadIdx.y;
    #pragma unroll
    for (int i = 0; i < 4; i++)
        t[ty + i*8][tx] = in[(size_t)(r0 + ty + i*8) * ldin + c0 + tx];
    __syncthreads();
    #pragma unroll
    for (int i = 0; i < 4; i++)
        o[(size_t)(c0 + ty + i*8) * ldo + r0 + tx] = __float2half_rn(t[tx][ty + i*8]);
}

// ---- fold Wv [1024 x 8192] -> WvfT [1024(nf) x 1024(k)] fp16 ----
__global__ void __launch_bounds__(256)
fold_wv(const float* __restrict__ Wv, h16* __restrict__ o)
{
    __shared__ float sf[32][33];
    const int k0 = blockIdx.x * 32, nf0 = blockIdx.y * 32;
    const int tx = threadIdx.x, ty = threadIdx.y;
    #pragma unroll
    for (int rep = 0; rep < 4; rep++) {
        const int row = ty + rep * 8;
        const float* src = Wv + (size_t)(k0 + row) * (Hc*Dc) + (size_t)(nf0 + tx) * 8;
        float4 a = *(const float4*)src;
        float4 b = *(const float4*)(src + 4);
        sf[row][tx] = a.x + a.y + a.z + a.w + b.x + b.y + b.z + b.w;
    }
    __syncthreads();
    #pragma unroll
    for (int rep = 0; rep < 4; rep++) {
        const int nf = ty + rep * 8;
        o[(size_t)(nf0 + nf) * Dc + k0 + tx] = __float2half_rn(sf[tx][nf]);
    }
}

// ---- bias prep ----
__global__ void prep_bias(const float* __restrict__ bq, const float* __restrict__ bk,
                          const float* __restrict__ bv, float* __restrict__ bqkv)
{
    const int i = blockIdx.x * blockDim.x + threadIdx.x;
    bqkv[i] = bq[i];
    bqkv[Dc + i] = bk[i];
    const float* s = bv + (size_t)i * 8;
    float t = 0.f;
    #pragma unroll
    for (int j = 0; j < 8; j++) t += s[j];
    bqkv[2*Dc + i] = t;
}

// ---- fp16 batched transpose ----
__global__ void __launch_bounds__(256)
transpose_h16(const h16* __restrict__ in, h16* __restrict__ o,
              int ldin, int ldo, long long zi0, long long zi1, int innerZ, long long zos)
{
    __shared__ h16 t[32][33];
    const int z = blockIdx.z;
    const long long base = (long long)(z / innerZ) * zi0 + (long long)(z % innerZ) * zi1;
    const int c0 = blockIdx.x * 32, r0 = blockIdx.y * 32;
    const int tx = threadIdx.x, ty = threadIdx.y;
    #pragma unroll
    for (int i = 0; i < 4; i++)
        t[ty + i*8][tx] = in[base + (size_t)(r0 + ty + i*8) * ldin + c0 + tx];
    __syncthreads();
    #pragma unroll
    for (int i = 0; i < 4; i++)
        o[(size_t)z * zos + (size_t)(c0 + ty + i*8) * ldo + r0 + tx] = t[tx][ty + i*8];
}

#define SYM(p, s) cudaGetSymbolAddress((void**)&p, s)

extern "C" void kernel_launch(void* const* d_in, const int* in_sizes, int n_in,
                              void* d_out, int out_size)
{
    (void)in_sizes; (void)n_in; (void)out_size;
    const float* x   = (const float*)d_in[0];
    const float* g1  = (const float*)d_in[2];
    const float* b1  = (const float*)d_in[3];
    const float* Wq  = (const float*)d_in[4];
    const float* bq  = (const float*)d_in[5];
    const float* Wk  = (const float*)d_in[6];
    const float* bk  = (const float*)d_in[7];
    const float* Wv  = (const float*)d_in[8];
    const float* bv  = (const float*)d_in[9];
    const float* g2  = (const float*)d_in[10];
    const float* b2  = (const float*)d_in[11];
    const float* W1  = (const float*)d_in[12];
    const float* bw1 = (const float*)d_in[13];
    const float* W2  = (const float*)d_in[14];
    const float* bw2 = (const float*)d_in[15];
    float* out = (float*)d_out;

    h16 *xn,*xn2,*wqkv,*w1t,*w2t,*qkv,*vft,*ff;
    float *bqkv,*x1;
    SYM(xn,g_xn); SYM(xn2,g_xn2);
    SYM(wqkv,g_wqkv); SYM(bqkv,g_bqkv);
    SYM(w1t,g_W1T); SYM(w2t,g_W2T);
    SYM(qkv,g_qkv); SYM(vft,g_vfT);
    SYM(ff,g_ff); SYM(x1,g_x1);

    cudaFuncSetAttribute(gemm_hmma<0,0>, cudaFuncAttributeMaxDynamicSharedMemorySize, GSMEM);
    cudaFuncSetAttribute(gemm_hmma<0,1>, cudaFuncAttributeMaxDynamicSharedMemorySize, GSMEM);
    cudaFuncSetAttribute(gemm_hmma<1,1>, cudaFuncAttributeMaxDynamicSharedMemorySize, GSMEM);
    cudaFuncSetAttribute(flash_attn,     cudaFuncAttributeMaxDynamicSharedMemorySize, FA_SMEM);

    const dim3 tb(32, 8);
    const size_t DD = (size_t)Dc*Dc;

    // weight prep
    prep_bias<<<4, 256>>>(bq, bk, bv, bqkv);
    transpose_half<<<dim3(Dc/32, Dc/32), tb>>>(Wq, wqkv,      Dc, Dc);
    transpose_half<<<dim3(Dc/32, Dc/32), tb>>>(Wk, wqkv+DD,   Dc, Dc);
    fold_wv<<<dim3(32, 32), tb>>>(Wv, wqkv+2*DD);
    transpose_half<<<dim3(FFc/32, Dc/32), tb>>>(W1, w1t, FFc, Dc);
    transpose_half<<<dim3(Dc/32, FFc/32), tb>>>(W2, w2t, Dc,  FFc);

    // LN1
    ln_half<<<TOK, 256>>>(x, g1, b1, xn);

    // QKV(folded) fused: z=3 -> qkv [3][TOK][Dc] fp16
    gemm_hmma<0,1><<<dim3(Dc/128, TOK/128, 3), 256, GSMEM>>>(
        xn, wqkv, bqkv, nullptr, nullptr, qkv,
        Dc, Dc, Dc, Dc,
        0, 0, (long long)DD, 0, (long long)TOK*Dc, 0, 1, 1.0f, (long long)Dc);

    // vfold transpose per (b,h): [b, s, h*128+d8] -> [(b,h), d8, s]
    transpose_h16<<<dim3(DKc/32, Sc/32, Bc*Hc), tb>>>(
        qkv + (size_t)2*TOK*Dc, vft,
        Dc, Sc, (long long)Sc*Dc, (long long)DKc, Hc, (long long)DKc*Sc);

    // fused attention: x1 = x + softmax(qk^T/sqrt(128)) @ vf
    flash_attn<<<dim3(Sc/128, Bc*Hc), 256, FA_SMEM>>>(
        qkv, qkv + (size_t)TOK*Dc, vft, x, x1);

    // LN2
    ln_half<<<TOK, 256>>>(x1, g2, b2, xn2);

    // ff = gelu(xn2 @ W1 + bw1)
    gemm_hmma<1,1><<<dim3(FFc/128, TOK/128, 1), 256, GSMEM>>>(
        xn2, w1t, bw1, nullptr, nullptr, ff,
        Dc, Dc, Dc, FFc, 0,0,0,0,0,0, 1, 1.0f, 0);

    // out = ff @ W2 + bw2 + x1
    gemm_hmma<0,0><<<dim3(Dc/128, TOK/128, 1), 256, GSMEM>>>(
        ff, w2t, bw2, x1, out, nullptr,
        FFc, FFc, FFc, Dc, 0,0,0,0,0,0, 1, 1.0f, 0);
}

// round 8
// speedup vs baseline: 11.7287x; 1.1590x over previous
#include <cuda_runtime.h>
#include <cuda_fp16.h>
#include <cstdint>
#include <math.h>

#define Bc 4
#define Sc 1024
#define Dc 1024
#define Hc 8
#define DKc 128
#define FFc 4096
#define TOK (Bc*Sc)
typedef __half h16;

// ---- scratch ----
__device__ __align__(16) h16 g_xn [TOK*Dc];
__device__ __align__(16) h16 g_xn2[TOK*Dc];
__device__ __align__(16) h16 g_wqkv[(size_t)3*Dc*Dc];
__device__ __align__(16) float g_bqkv[3*Dc];
__device__ __align__(16) h16 g_W1T[(size_t)FFc*Dc];
__device__ __align__(16) h16 g_W2T[(size_t)Dc*FFc];
__device__ __align__(16) h16 g_qkv[(size_t)3*TOK*Dc];
__device__ __align__(16) h16 g_vfT[(size_t)Bc*Hc*DKc*Sc];
__device__ __align__(16) float g_x1[TOK*Dc];
__device__ __align__(16) h16 g_ff[(size_t)TOK*FFc];

// ---- helpers ----
__device__ __forceinline__ uint32_t smem_u32(const void* p) {
    uint32_t a;
    asm("{ .reg .u64 t; cvta.to.shared.u64 t, %1; cvt.u32.u64 %0, t; }" : "=r"(a) : "l"(p));
    return a;
}
#define CP16(dst, src) asm volatile("cp.async.cg.shared.global [%0], [%1], 16;" :: "r"(dst), "l"(src))
#define CP_COMMIT()    asm volatile("cp.async.commit_group;" ::: "memory")
#define CP_WAIT1()     asm volatile("cp.async.wait_group 1;" ::: "memory")

__device__ __forceinline__ void ldsm_x4(uint32_t& a0, uint32_t& a1, uint32_t& a2, uint32_t& a3, uint32_t addr) {
    asm volatile("ldmatrix.sync.aligned.m8n8.x4.shared.b16 {%0,%1,%2,%3}, [%4];"
                 : "=r"(a0), "=r"(a1), "=r"(a2), "=r"(a3) : "r"(addr));
}
__device__ __forceinline__ void ldsm_x2(uint32_t& b0, uint32_t& b1, uint32_t addr) {
    asm volatile("ldmatrix.sync.aligned.m8n8.x2.shared.b16 {%0,%1}, [%2];"
                 : "=r"(b0), "=r"(b1) : "r"(addr));
}
__device__ __forceinline__ void mma16816(float* c, uint32_t a0, uint32_t a1, uint32_t a2, uint32_t a3,
                                         uint32_t b0, uint32_t b1) {
    asm volatile("mma.sync.aligned.m16n8k16.row.col.f32.f16.f16.f32 "
                 "{%0,%1,%2,%3},{%4,%5,%6,%7},{%8,%9},{%0,%1,%2,%3};"
                 : "+f"(c[0]), "+f"(c[1]), "+f"(c[2]), "+f"(c[3])
                 : "r"(a0), "r"(a1), "r"(a2), "r"(a3), "r"(b0), "r"(b1));
}
__device__ __forceinline__ float gelu_exact(float v) {
    return 0.5f * v * (1.0f + erff(v * 0.70710678118654752f));
}

// ---- HMMA fp16 GEMM: 128x128 CTA tile, K-chunk 32, 3-stage cp.async, 2 CTA/SM ----
#define STAGE_B 16384
#define GSMEM   (3*STAGE_B)

template<int ACT, int OUTMODE>
__global__ void __launch_bounds__(256, 2)
gemm_hmma(const h16* __restrict__ Ah, const h16* __restrict__ Bh,
          const float* __restrict__ bias, const float* __restrict__ resid,
          float* __restrict__ C, h16* __restrict__ Ch,
          int K, int lda, int ldb, int ldc,
          long long sA0, long long sA1, long long sB0, long long sB1,
          long long sC0, long long sC1, int innerB, float alpha, long long biasStride)
{
    extern __shared__ char smem[];
    const uint32_t smb = smem_u32(smem);
    const int tid = threadIdx.x, lane = tid & 31, wid = tid >> 5;
    const int z = blockIdx.z, zo = z / innerB, zi = z - zo * innerB;
    const long long aoff = zo * sA0 + zi * sA1;
    const long long boff = zo * sB0 + zi * sB1;
    const long long coff = zo * sC0 + zi * sC1;
    if (bias) bias += (long long)z * biasStride;
    const int m0 = blockIdx.y * 128, n0 = blockIdx.x * 128;
    const int wm = (wid & 1) * 64, wn = (wid >> 1) * 32;

    const int row = tid >> 2;
    const int cch = tid & 3;

    float acc[4][4][4];
    #pragma unroll
    for (int i = 0; i < 4; i++)
        #pragma unroll
        for (int j = 0; j < 4; j++)
            #pragma unroll
            for (int t = 0; t < 4; t++) acc[i][j][t] = 0.f;

    const int nck = K >> 5;

    auto load_chunk = [&](int kk, int s) {
        const int k0 = kk << 5;
        const uint32_t st = smb + s * STAGE_B;
        #pragma unroll
        for (int rep = 0; rep < 2; rep++) {
            const int r = row + rep * 64;
            const uint32_t so = r * 64 + ((cch ^ (r & 3)) << 4);
            CP16(st + so,        Ah + (size_t)aoff + (size_t)(m0 + r) * lda + k0 + cch * 8);
            CP16(st + 8192 + so, Bh + (size_t)boff + (size_t)(n0 + r) * ldb + k0 + cch * 8);
        }
        CP_COMMIT();
    };

    load_chunk(0, 0);
    load_chunk(1, 1);

    for (int kk = 0; kk < nck; kk++) {
        CP_WAIT1();
        __syncthreads();
        if (kk + 2 < nck) load_chunk(kk + 2, (kk + 2) % 3);
        else CP_COMMIT();

        const uint32_t st = smb + (kk % 3) * STAGE_B;
        #pragma unroll
        for (int ks = 0; ks < 2; ks++) {
            uint32_t ah[4][4], bh[4][2];
            #pragma unroll
            for (int mf = 0; mf < 4; mf++) {
                const int r = wm + mf * 16 + (lane & 15);
                const int ch = ks * 2 + (lane >> 4);
                ldsm_x4(ah[mf][0], ah[mf][1], ah[mf][2], ah[mf][3],
                        st + r * 64 + ((ch ^ (r & 3)) << 4));
            }
            #pragma unroll
            for (int nf = 0; nf < 4; nf++) {
                const int r = wn + nf * 8 + (lane & 7);
                const int ch = ks * 2 + ((lane >> 3) & 1);
                ldsm_x2(bh[nf][0], bh[nf][1],
                        st + 8192 + r * 64 + ((ch ^ (r & 3)) << 4));
            }
            #pragma unroll
            for (int mf = 0; mf < 4; mf++)
                #pragma unroll
                for (int nf = 0; nf < 4; nf++)
                    mma16816(acc[mf][nf], ah[mf][0], ah[mf][1], ah[mf][2], ah[mf][3], bh[nf][0], bh[nf][1]);
        }
        __syncthreads();
    }

    #pragma unroll
    for (int mf = 0; mf < 4; mf++) {
        const int r0 = m0 + wm + mf * 16 + (lane >> 2);
        const int r1 = r0 + 8;
        #pragma unroll
        for (int nf = 0; nf < 4; nf++) {
            const int col = n0 + wn + nf * 8 + (lane & 3) * 2;
            float b0 = 0.f, b1 = 0.f;
            if (bias) { b0 = __ldg(bias + col); b1 = __ldg(bias + col + 1); }
            float v0 = acc[mf][nf][0] * alpha + b0;
            float v1 = acc[mf][nf][1] * alpha + b1;
            float v2 = acc[mf][nf][2] * alpha + b0;
            float v3 = acc[mf][nf][3] * alpha + b1;
            if (ACT == 1) {
                v0 = gelu_exact(v0); v1 = gelu_exact(v1);
                v2 = gelu_exact(v2); v3 = gelu_exact(v3);
            }
            const size_t i0 = (size_t)coff + (size_t)r0 * ldc + col;
            const size_t i1 = (size_t)coff + (size_t)r1 * ldc + col;
            if (OUTMODE == 0) {
                if (resid) {
                    float2 q0 = *(const float2*)(resid + i0);
                    float2 q1 = *(const float2*)(resid + i1);
                    v0 += q0.x; v1 += q0.y; v2 += q1.x; v3 += q1.y;
                }
                *(float2*)(C + i0) = make_float2(v0, v1);
                *(float2*)(C + i1) = make_float2(v2, v3);
            } else {
                __half2 p0 = __floats2half2_rn(v0, v1);
                __half2 p1 = __floats2half2_rn(v2, v3);
                *(__half2*)(Ch + i0) = p0;
                *(__half2*)(Ch + i1) = p1;
            }
        }
    }
}

// ---- fused flash attention ----
#define FA_STAGE 65536
#define FA_SMEM  (32768 + 3*FA_STAGE)

__global__ void __launch_bounds__(256, 1)
flash_attn(const h16* __restrict__ qg, const h16* __restrict__ kg,
           const h16* __restrict__ vfT, const float* __restrict__ x,
           float* __restrict__ x1)
{
    extern __shared__ char smem[];
    const uint32_t smb = smem_u32(smem);
    const int qt = blockIdx.x, z = blockIdx.y;
    const int b = z >> 3, h = z & 7;
    const int tid = threadIdx.x, lane = tid & 31, wid = tid >> 5;

    const size_t qkbase = (size_t)b * Sc * Dc + (size_t)h * DKc;
    const size_t vbase  = (size_t)z * DKc * Sc;

    const int row = tid >> 2;
    const int cch = tid & 3;

    {
        #pragma unroll
        for (int slab = 0; slab < 4; slab++)
            #pragma unroll
            for (int rep = 0; rep < 2; rep++) {
                const int r = row + rep * 64;
                const uint32_t so = slab * 8192 + r * 64 + ((cch ^ (r & 3)) << 4);
                CP16(smb + so, qg + qkbase + (size_t)(qt * 128 + r) * Dc + slab * 32 + cch * 8);
            }
    }
    auto load_kv = [&](int kt, int st) {
        const uint32_t sb = smb + 32768 + st * FA_STAGE;
        #pragma unroll
        for (int slab = 0; slab < 4; slab++)
            #pragma unroll
            for (int rep = 0; rep < 2; rep++) {
                const int r = row + rep * 64;
                const uint32_t so = slab * 8192 + r * 64 + ((cch ^ (r & 3)) << 4);
                CP16(sb + so,         kg  + qkbase + (size_t)(kt * 128 + r) * Dc + slab * 32 + cch * 8);
                CP16(sb + 32768 + so, vfT + vbase  + (size_t)r * Sc + kt * 128 + slab * 32 + cch * 8);
            }
        CP_COMMIT();
    };
    load_kv(0, 0);
    load_kv(1, 1);

    uint32_t aq[8][4];
    float acc_o[16][4];
    #pragma unroll
    for (int nf = 0; nf < 16; nf++)
        #pragma unroll
        for (int t = 0; t < 4; t++) acc_o[nf][t] = 0.f;
    float m0 = -1e30f, m1 = -1e30f, l0 = 0.f, l1 = 0.f;
    const float scale = 0.08838834764831845f;

    for (int kt = 0; kt < 8; kt++) {
        CP_WAIT1();
        __syncthreads();
        if (kt + 2 < 8) load_kv(kt + 2, (kt + 2) % 3);
        else CP_COMMIT();

        if (kt == 0) {
            #pragma unroll
            for (int kc = 0; kc < 8; kc++) {
                const int slab = kc >> 1, ks = kc & 1;
                const int r = wid * 16 + (lane & 15);
                const int ch = ks * 2 + (lane >> 4);
                ldsm_x4(aq[kc][0], aq[kc][1], aq[kc][2], aq[kc][3],
                        smb + slab * 8192 + r * 64 + ((ch ^ (r & 3)) << 4));
            }
        }

        const uint32_t sbk = smb + 32768 + (kt % 3) * FA_STAGE;
        const uint32_t sbv = sbk + 32768;

        float s_acc[16][4];
        #pragma unroll
        for (int nf = 0; nf < 16; nf++)
            #pragma unroll
            for (int t = 0; t < 4; t++) s_acc[nf][t] = 0.f;
        #pragma unroll
        for (int kc = 0; kc < 8; kc++) {
            const int slab = kc >> 1, ks = kc & 1;
            #pragma unroll
            for (int nf = 0; nf < 16; nf++) {
                const int r = nf * 8 + (lane & 7);
                const int ch = ks * 2 + ((lane >> 3) & 1);
                uint32_t b0, b1;
                ldsm_x2(b0, b1, sbk + slab * 8192 + r * 64 + ((ch ^ (r & 3)) << 4));
                mma16816(s_acc[nf], aq[kc][0], aq[kc][1], aq[kc][2], aq[kc][3], b0, b1);
            }
        }

        float mx0 = -1e30f, mx1 = -1e30f;
        #pragma unroll
        for (int nf = 0; nf < 16; nf++) {
            s_acc[nf][0] *= scale; s_acc[nf][1] *= scale;
            s_acc[nf][2] *= scale; s_acc[nf][3] *= scale;
            mx0 = fmaxf(mx0, fmaxf(s_acc[nf][0], s_acc[nf][1]));
            mx1 = fmaxf(mx1, fmaxf(s_acc[nf][2], s_acc[nf][3]));
        }
        mx0 = fmaxf(mx0, __shfl_xor_sync(~0u, mx0, 1));
        mx0 = fmaxf(mx0, __shfl_xor_sync(~0u, mx0, 2));
        mx1 = fmaxf(mx1, __shfl_xor_sync(~0u, mx1, 1));
        mx1 = fmaxf(mx1, __shfl_xor_sync(~0u, mx1, 2));
        const float mn0 = fmaxf(m0, mx0), mn1 = fmaxf(m1, mx1);
        const float a0 = __expf(m0 - mn0), a1 = __expf(m1 - mn1);
        m0 = mn0; m1 = mn1;

        float rs0 = 0.f, rs1 = 0.f;
        #pragma unroll
        for (int nf = 0; nf < 16; nf++) {
            s_acc[nf][0] = __expf(s_acc[nf][0] - mn0);
            s_acc[nf][1] = __expf(s_acc[nf][1] - mn0);
            s_acc[nf][2] = __expf(s_acc[nf][2] - mn1);
            s_acc[nf][3] = __expf(s_acc[nf][3] - mn1);
            rs0 += s_acc[nf][0] + s_acc[nf][1];
            rs1 += s_acc[nf][2] + s_acc[nf][3];
        }
        rs0 += __shfl_xor_sync(~0u, rs0, 1); rs0 += __shfl_xor_sync(~0u, rs0, 2);
        rs1 += __shfl_xor_sync(~0u, rs1, 1); rs1 += __shfl_xor_sync(~0u, rs1, 2);
        l0 = l0 * a0 + rs0; l1 = l1 * a1 + rs1;
        #pragma unroll
        for (int nf = 0; nf < 16; nf++) {
            acc_o[nf][0] *= a0; acc_o[nf][1] *= a0;
            acc_o[nf][2] *= a1; acc_o[nf][3] *= a1;
        }

        #pragma unroll
        for (int kc = 0; kc < 8; kc++) {
            const int slab = kc >> 1, ks = kc & 1;
            __half2 pa0 = __floats2half2_rn(s_acc[2*kc][0],   s_acc[2*kc][1]);
            __half2 pa1 = __floats2half2_rn(s_acc[2*kc][2],   s_acc[2*kc][3]);
            __half2 pa2 = __floats2half2_rn(s_acc[2*kc+1][0], s_acc[2*kc+1][1]);
            __half2 pa3 = __floats2half2_rn(s_acc[2*kc+1][2], s_acc[2*kc+1][3]);
            const uint32_t u0 = *(uint32_t*)&pa0, u1 = *(uint32_t*)&pa1;
            const uint32_t u2 = *(uint32_t*)&pa2, u3 = *(uint32_t*)&pa3;
            #pragma unroll
            for (int nf = 0; nf < 16; nf++) {
                const int r = nf * 8 + (lane & 7);
                const int ch = ks * 2 + ((lane >> 3) & 1);
                uint32_t b0, b1;
                ldsm_x2(b0, b1, sbv + slab * 8192 + r * 64 + ((ch ^ (r & 3)) << 4));
                mma16816(acc_o[nf], u0, u1, u2, u3, b0, b1);
            }
        }
        __syncthreads();
    }

    const float inv0 = 1.f / l0, inv1 = 1.f / l1;
    const size_t zbase = (size_t)z * Sc * DKc;
    const int gr0 = qt * 128 + wid * 16 + (lane >> 2);
    #pragma unroll
    for (int nf = 0; nf < 16; nf++) {
        const int col = nf * 8 + (lane & 3) * 2;
        const size_t i0 = zbase + (size_t)gr0 * DKc + col;
        const size_t i1 = i0 + 8 * DKc;
        float2 r0 = *(const float2*)(x + i0);
        float2 r1 = *(const float2*)(x + i1);
        *(float2*)(x1 + i0) = make_float2(acc_o[nf][0] * inv0 + r0.x, acc_o[nf][1] * inv0 + r0.y);
        *(float2*)(x1 + i1) = make_float2(acc_o[nf][2] * inv1 + r1.x, acc_o[nf][3] * inv1 + r1.y);
    }
}

// ---- layernorm -> fp16 ----
__global__ void __launch_bounds__(256)
ln_half(const float* __restrict__ x, const float* __restrict__ g,
        const float* __restrict__ b, h16* __restrict__ o)
{
    const long long row = blockIdx.x;
    const int tid = threadIdx.x;
    float4 v = *(const float4*)(x + row * Dc + tid * 4);
    float s = v.x+v.y+v.z+v.w, ss = v.x*v.x+v.y*v.y+v.z*v.z+v.w*v.w;
    __shared__ float shs[8], shq[8];
    #pragma unroll
    for (int o2 = 16; o2; o2 >>= 1) { s += __shfl_xor_sync(~0u,s,o2); ss += __shfl_xor_sync(~0u,ss,o2); }
    if ((tid & 31) == 0) { shs[tid>>5] = s; shq[tid>>5] = ss; }
    __syncthreads();
    float st=0.f, qt=0.f;
    #pragma unroll
    for (int i = 0; i < 8; i++) { st += shs[i]; qt += shq[i]; }
    const float m = st * (1.f/Dc), inv = rsqrtf(qt*(1.f/Dc) - m*m + 1e-5f);
    float4 gv = *(const float4*)(g + tid*4);
    float4 bv = *(const float4*)(b + tid*4);
    __half2 h0 = __floats2half2_rn((v.x-m)*inv*gv.x+bv.x, (v.y-m)*inv*gv.y+bv.y);
    __half2 h1 = __floats2half2_rn((v.z-m)*inv*gv.z+bv.z, (v.w-m)*inv*gv.w+bv.w);
    uint2 pk; pk.x = *(uint32_t*)&h0; pk.y = *(uint32_t*)&h1;
    *(uint2*)(o + row*Dc + tid*4) = pk;
}

// ---- fp32 transpose -> fp16 ----
__global__ void __launch_bounds__(256)
transpose_half(const float* __restrict__ in, h16* __restrict__ o, int ldin, int ldo)
{
    __shared__ float t[32][33];
    const int c0 = blockIdx.x * 32, r0 = blockIdx.y * 32;
    const int tx = threadIdx.x, ty = threadIdx.y;
    #pragma unroll
    for (int i = 0; i < 4; i++)
        t[ty + i*8][tx] = in[(size_t)(r0 + ty + i*8) * ldin + c0 + tx];
    __syncthreads();
    #pragma unroll
    for (int i = 0; i < 4; i++)
        o[(size_t)(c0 + ty + i*8) * ldo + r0 + tx] = __float2half_rn(t[tx][ty + i*8]);
}

// ---- fold Wv ----
__global__ void __launch_bounds__(256)
fold_wv(const float* __restrict__ Wv, h16* __restrict__ o)
{
    __shared__ float sf[32][33];
    const int k0 = blockIdx.x * 32, nf0 = blockIdx.y * 32;
    const int tx = threadIdx.x, ty = threadIdx.y;
    #pragma unroll
    for (int rep = 0; rep < 4; rep++) {
        const int row = ty + rep * 8;
        const float* src = Wv + (size_t)(k0 + row) * (Hc*Dc) + (size_t)(nf0 + tx) * 8;
        float4 a = *(const float4*)src;
        float4 b = *(const float4*)(src + 4);
        sf[row][tx] = a.x + a.y + a.z + a.w + b.x + b.y + b.z + b.w;
    }
    __syncthreads();
    #pragma unroll
    for (int rep = 0; rep < 4; rep++) {
        const int nf = ty + rep * 8;
        o[(size_t)(nf0 + nf) * Dc + k0 + tx] = __float2half_rn(sf[tx][nf]);
    }
}

// ---- bias prep ----
__global__ void prep_bias(const float* __restrict__ bq, const float* __restrict__ bk,
                          const float* __restrict__ bv, float* __restrict__ bqkv)
{
    const int i = blockIdx.x * blockDim.x + threadIdx.x;
    bqkv[i] = bq[i];
    bqkv[Dc + i] = bk[i];
    const float* s = bv + (size_t)i * 8;
    float t = 0.f;
    #pragma unroll
    for (int j = 0; j < 8; j++) t += s[j];
    bqkv[2*Dc + i] = t;
}

// ---- fp16 batched transpose ----
__global__ void __launch_bounds__(256)
transpose_h16(const h16* __restrict__ in, h16* __restrict__ o,
              int ldin, int ldo, long long zi0, long long zi1, int innerZ, long long zos)
{
    __shared__ h16 t[32][33];
    const int z = blockIdx.z;
    const long long base = (long long)(z / innerZ) * zi0 + (long long)(z % innerZ) * zi1;
    const int c0 = blockIdx.x * 32, r0 = blockIdx.y * 32;
    const int tx = threadIdx.x, ty = threadIdx.y;
    #pragma unroll
    for (int i = 0; i < 4; i++)
        t[ty + i*8][tx] = in[base + (size_t)(r0 + ty + i*8) * ldin + c0 + tx];
    __syncthreads();
    #pragma unroll
    for (int i = 0; i < 4; i++)
        o[(size_t)z * zos + (size_t)(c0 + ty + i*8) * ldo + r0 + tx] = t[tx][ty + i*8];
}

#define SYM(p, s) cudaGetSymbolAddress((void**)&p, s)

extern "C" void kernel_launch(void* const* d_in, const int* in_sizes, int n_in,
                              void* d_out, int out_size)
{
    (void)in_sizes; (void)n_in; (void)out_size;
    const float* x   = (const float*)d_in[0];
    const float* g1  = (const float*)d_in[2];
    const float* b1  = (const float*)d_in[3];
    const float* Wq  = (const float*)d_in[4];
    const float* bq  = (const float*)d_in[5];
    const float* Wk  = (const float*)d_in[6];
    const float* bk  = (const float*)d_in[7];
    const float* Wv  = (const float*)d_in[8];
    const float* bv  = (const float*)d_in[9];
    const float* g2  = (const float*)d_in[10];
    const float* b2  = (const float*)d_in[11];
    const float* W1  = (const float*)d_in[12];
    const float* bw1 = (const float*)d_in[13];
    const float* W2  = (const float*)d_in[14];
    const float* bw2 = (const float*)d_in[15];
    float* out = (float*)d_out;

    h16 *xn,*xn2,*wqkv,*w1t,*w2t,*qkv,*vft,*ff;
    float *bqkv,*x1;
    SYM(xn,g_xn); SYM(xn2,g_xn2);
    SYM(wqkv,g_wqkv); SYM(bqkv,g_bqkv);
    SYM(w1t,g_W1T); SYM(w2t,g_W2T);
    SYM(qkv,g_qkv); SYM(vft,g_vfT);
    SYM(ff,g_ff); SYM(x1,g_x1);

    cudaFuncSetAttribute(gemm_hmma<0,0>, cudaFuncAttributeMaxDynamicSharedMemorySize, GSMEM);
    cudaFuncSetAttribute(gemm_hmma<0,1>, cudaFuncAttributeMaxDynamicSharedMemorySize, GSMEM);
    cudaFuncSetAttribute(gemm_hmma<1,1>, cudaFuncAttributeMaxDynamicSharedMemorySize, GSMEM);
    cudaFuncSetAttribute(flash_attn,     cudaFuncAttributeMaxDynamicSharedMemorySize, FA_SMEM);

    const dim3 tb(32, 8);
    const size_t DD = (size_t)Dc*Dc;

    prep_bias<<<4, 256>>>(bq, bk, bv, bqkv);
    transpose_half<<<dim3(Dc/32, Dc/32), tb>>>(Wq, wqkv,      Dc, Dc);
    transpose_half<<<dim3(Dc/32, Dc/32), tb>>>(Wk, wqkv+DD,   Dc, Dc);
    fold_wv<<<dim3(32, 32), tb>>>(Wv, wqkv+2*DD);
    transpose_half<<<dim3(FFc/32, Dc/32), tb>>>(W1, w1t, FFc, Dc);
    transpose_half<<<dim3(Dc/32, FFc/32), tb>>>(W2, w2t, Dc,  FFc);

    ln_half<<<TOK, 256>>>(x, g1, b1, xn);

    gemm_hmma<0,1><<<dim3(Dc/128, TOK/128, 3), 256, GSMEM>>>(
        xn, wqkv, bqkv, nullptr, nullptr, qkv,
        Dc, Dc, Dc, Dc,
        0, 0, (long long)DD, 0, (long long)TOK*Dc, 0, 1, 1.0f, (long long)Dc);

    transpose_h16<<<dim3(DKc/32, Sc/32, Bc*Hc), tb>>>(
        qkv + (size_t)2*TOK*Dc, vft,
        Dc, Sc, (long long)Sc*Dc, (long long)DKc, Hc, (long long)DKc*Sc);

    flash_attn<<<dim3(Sc/128, Bc*Hc), 256, FA_SMEM>>>(
        qkv, qkv + (size_t)TOK*Dc, vft, x, x1);

    ln_half<<<TOK, 256>>>(x1, g2, b2, xn2);

    gemm_hmma<1,1><<<dim3(FFc/128, TOK/128, 1), 256, GSMEM>>>(
        xn2, w1t, bw1, nullptr, nullptr, ff,
        Dc, Dc, Dc, FFc, 0,0,0,0,0,0, 1, 1.0f, 0);

    gemm_hmma<0,0><<<dim3(Dc/128, TOK/128, 1), 256, GSMEM>>>(
        ff, w2t, bw2, x1, out, nullptr,
        FFc, FFc, FFc, Dc, 0,0,0,0,0,0, 1, 1.0f, 0);
}

// round 9
// speedup vs baseline: 15.0530x; 1.2834x over previous
#include <cuda_runtime.h>
#include <cuda_fp16.h>
#include <cstdint>
#include <math.h>

#define Bc 4
#define Sc 1024
#define Dc 1024
#define Hc 8
#define DKc 128
#define FFc 4096
#define TOK (Bc*Sc)
typedef __half h16;

// ---- scratch ----
__device__ __align__(16) h16 g_xn [TOK*Dc];
__device__ __align__(16) h16 g_xn2[TOK*Dc];
__device__ __align__(16) h16 g_wqkv[(size_t)3*Dc*Dc];
__device__ __align__(16) float g_bqkv[3*Dc];
__device__ __align__(16) h16 g_W1T[(size_t)FFc*Dc];
__device__ __align__(16) h16 g_W2T[(size_t)Dc*FFc];
__device__ __align__(16) h16 g_qkv[(size_t)3*TOK*Dc];
__device__ __align__(16) h16 g_vfT[(size_t)Bc*Hc*DKc*Sc];
__device__ __align__(16) float g_x1[TOK*Dc];
__device__ __align__(16) h16 g_ff[(size_t)TOK*FFc];

// ---- helpers ----
__device__ __forceinline__ uint32_t smem_u32(const void* p) {
    uint32_t a;
    asm("{ .reg .u64 t; cvta.to.shared.u64 t, %1; cvt.u32.u64 %0, t; }" : "=r"(a) : "l"(p));
    return a;
}
#define CP16(dst, src) asm volatile("cp.async.cg.shared.global [%0], [%1], 16;" :: "r"(dst), "l"(src))
#define CP_COMMIT()    asm volatile("cp.async.commit_group;" ::: "memory")
#define CP_WAIT1()     asm volatile("cp.async.wait_group 1;" ::: "memory")

__device__ __forceinline__ void ldsm_x4(uint32_t& a0, uint32_t& a1, uint32_t& a2, uint32_t& a3, uint32_t addr) {
    asm volatile("ldmatrix.sync.aligned.m8n8.x4.shared.b16 {%0,%1,%2,%3}, [%4];"
                 : "=r"(a0), "=r"(a1), "=r"(a2), "=r"(a3) : "r"(addr));
}
__device__ __forceinline__ void ldsm_x2(uint32_t& b0, uint32_t& b1, uint32_t addr) {
    asm volatile("ldmatrix.sync.aligned.m8n8.x2.shared.b16 {%0,%1}, [%2];"
                 : "=r"(b0), "=r"(b1) : "r"(addr));
}
__device__ __forceinline__ void mma16816(float* c, uint32_t a0, uint32_t a1, uint32_t a2, uint32_t a3,
                                         uint32_t b0, uint32_t b1) {
    asm volatile("mma.sync.aligned.m16n8k16.row.col.f32.f16.f16.f32 "
                 "{%0,%1,%2,%3},{%4,%5,%6,%7},{%8,%9},{%0,%1,%2,%3};"
                 : "+f"(c[0]), "+f"(c[1]), "+f"(c[2]), "+f"(c[3])
                 : "r"(a0), "r"(a1), "r"(a2), "r"(a3), "r"(b0), "r"(b1));
}
__device__ __forceinline__ float gelu_exact(float v) {
    return 0.5f * v * (1.0f + erff(v * 0.70710678118654752f));
}

// ---- HMMA fp16 GEMM: 128x128 CTA tile, K-chunk 64, 3-stage cp.async, 2 CTA/SM ----
// Stage: A 128x64 (16KB) at +0, B 128x64 (16KB) at +16384. Rows are 128B (8x16B chunks),
// swizzled by chunk ^ (row & 7).
#define STAGE_B 32768
#define GSMEM   (3*STAGE_B)

template<int ACT, int OUTMODE>
__global__ void __launch_bounds__(256, 2)
gemm_hmma(const h16* __restrict__ Ah, const h16* __restrict__ Bh,
          const float* __restrict__ bias, const float* __restrict__ resid,
          float* __restrict__ C, h16* __restrict__ Ch,
          int K, int lda, int ldb, int ldc,
          long long sA0, long long sA1, long long sB0, long long sB1,
          long long sC0, long long sC1, int innerB, float alpha, long long biasStride)
{
    extern __shared__ char smem[];
    const uint32_t smb = smem_u32(smem);
    const int tid = threadIdx.x, lane = tid & 31, wid = tid >> 5;
    const int z = blockIdx.z, zo = z / innerB, zi = z - zo * innerB;
    const long long aoff = zo * sA0 + zi * sA1;
    const long long boff = zo * sB0 + zi * sB1;
    const long long coff = zo * sC0 + zi * sC1;
    if (bias) bias += (long long)z * biasStride;
    const int m0 = blockIdx.y * 128, n0 = blockIdx.x * 128;
    const int wm = (wid & 1) * 64, wn = (wid >> 1) * 32;

    const int lrow = tid >> 3;       // 0..31 (4 reps of 32 rows)
    const int cch  = tid & 7;        // 16B chunk within 128B row

    float acc[4][4][4];
    #pragma unroll
    for (int i = 0; i < 4; i++)
        #pragma unroll
        for (int j = 0; j < 4; j++)
            #pragma unroll
            for (int t = 0; t < 4; t++) acc[i][j][t] = 0.f;

    const int nck = K >> 6;

    auto load_chunk = [&](int kk, int s) {
        const int k0 = kk << 6;
        const uint32_t st = smb + s * STAGE_B;
        #pragma unroll
        for (int rep = 0; rep < 4; rep++) {
            const int r = lrow + rep * 32;
            const uint32_t so = r * 128 + ((cch ^ (r & 7)) << 4);
            CP16(st + so,         Ah + (size_t)aoff + (size_t)(m0 + r) * lda + k0 + cch * 8);
            CP16(st + 16384 + so, Bh + (size_t)boff + (size_t)(n0 + r) * ldb + k0 + cch * 8);
        }
        CP_COMMIT();
    };

    load_chunk(0, 0);
    load_chunk(1, 1);

    for (int kk = 0; kk < nck; kk++) {
        CP_WAIT1();
        __syncthreads();
        if (kk + 2 < nck) load_chunk(kk + 2, (kk + 2) % 3);
        else CP_COMMIT();

        const uint32_t st = smb + (kk % 3) * STAGE_B;
        #pragma unroll
        for (int ks = 0; ks < 4; ks++) {
            uint32_t ah[4][4], bh[4][2];
            #pragma unroll
            for (int mf = 0; mf < 4; mf++) {
                const int r = wm + mf * 16 + (lane & 15);
                const int ch = ks * 2 + (lane >> 4);
                ldsm_x4(ah[mf][0], ah[mf][1], ah[mf][2], ah[mf][3],
                        st + r * 128 + ((ch ^ (r & 7)) << 4));
            }
            #pragma unroll
            for (int nf = 0; nf < 4; nf++) {
                const int r = wn + nf * 8 + (lane & 7);
                const int ch = ks * 2 + ((lane >> 3) & 1);
                ldsm_x2(bh[nf][0], bh[nf][1],
                        st + 16384 + r * 128 + ((ch ^ (r & 7)) << 4));
            }
            #pragma unroll
            for (int mf = 0; mf < 4; mf++)
                #pragma unroll
                for (int nf = 0; nf < 4; nf++)
                    mma16816(acc[mf][nf], ah[mf][0], ah[mf][1], ah[mf][2], ah[mf][3], bh[nf][0], bh[nf][1]);
        }
        __syncthreads();
    }

    #pragma unroll
    for (int mf = 0; mf < 4; mf++) {
        const int r0 = m0 + wm + mf * 16 + (lane >> 2);
        const int r1 = r0 + 8;
        #pragma unroll
        for (int nf = 0; nf < 4; nf++) {
            const int col = n0 + wn + nf * 8 + (lane & 3) * 2;
            float b0 = 0.f, b1 = 0.f;
            if (bias) { b0 = __ldg(bias + col); b1 = __ldg(bias + col + 1); }
            float v0 = acc[mf][nf][0] * alpha + b0;
            float v1 = acc[mf][nf][1] * alpha + b1;
            float v2 = acc[mf][nf][2] * alpha + b0;
            float v3 = acc[mf][nf][3] * alpha + b1;
            if (ACT == 1) {
                v0 = gelu_exact(v0); v1 = gelu_exact(v1);
                v2 = gelu_exact(v2); v3 = gelu_exact(v3);
            }
            const size_t i0 = (size_t)coff + (size_t)r0 * ldc + col;
            const size_t i1 = (size_t)coff + (size_t)r1 * ldc + col;
            if (OUTMODE == 0) {
                if (resid) {
                    float2 q0 = *(const float2*)(resid + i0);
                    float2 q1 = *(const float2*)(resid + i1);
                    v0 += q0.x; v1 += q0.y; v2 += q1.x; v3 += q1.y;
                }
                *(float2*)(C + i0) = make_float2(v0, v1);
                *(float2*)(C + i1) = make_float2(v2, v3);
            } else {
                __half2 p0 = __floats2half2_rn(v0, v1);
                __half2 p1 = __floats2half2_rn(v2, v3);
                *(__half2*)(Ch + i0) = p0;
                *(__half2*)(Ch + i1) = p1;
            }
        }
    }
}

// ---- fused flash attention (unchanged layout: 64B rows, chunk ^ (row&3)) ----
#define FA_STAGE 65536
#define FA_SMEM  (32768 + 3*FA_STAGE)

__global__ void __launch_bounds__(256, 1)
flash_attn(const h16* __restrict__ qg, const h16* __restrict__ kg,
           const h16* __restrict__ vfT, const float* __restrict__ x,
           float* __restrict__ x1)
{
    extern __shared__ char smem[];
    const uint32_t smb = smem_u32(smem);
    const int qt = blockIdx.x, z = blockIdx.y;
    const int b = z >> 3, h = z & 7;
    const int tid = threadIdx.x, lane = tid & 31, wid = tid >> 5;

    const size_t qkbase = (size_t)b * Sc * Dc + (size_t)h * DKc;
    const size_t vbase  = (size_t)z * DKc * Sc;

    const int row = tid >> 2;
    const int cch = tid & 3;

    {
        #pragma unroll
        for (int slab = 0; slab < 4; slab++)
            #pragma unroll
            for (int rep = 0; rep < 2; rep++) {
                const int r = row + rep * 64;
                const uint32_t so = slab * 8192 + r * 64 + ((cch ^ (r & 3)) << 4);
                CP16(smb + so, qg + qkbase + (size_t)(qt * 128 + r) * Dc + slab * 32 + cch * 8);
            }
    }
    auto load_kv = [&](int kt, int st) {
        const uint32_t sb = smb + 32768 + st * FA_STAGE;
        #pragma unroll
        for (int slab = 0; slab < 4; slab++)
            #pragma unroll
            for (int rep = 0; rep < 2; rep++) {
                const int r = row + rep * 64;
                const uint32_t so = slab * 8192 + r * 64 + ((cch ^ (r & 3)) << 4);
                CP16(sb + so,         kg  + qkbase + (size_t)(kt * 128 + r) * Dc + slab * 32 + cch * 8);
                CP16(sb + 32768 + so, vfT + vbase  + (size_t)r * Sc + kt * 128 + slab * 32 + cch * 8);
            }
        CP_COMMIT();
    };
    load_kv(0, 0);
    load_kv(1, 1);

    uint32_t aq[8][4];
    float acc_o[16][4];
    #pragma unroll
    for (int nf = 0; nf < 16; nf++)
        #pragma unroll
        for (int t = 0; t < 4; t++) acc_o[nf][t] = 0.f;
    float m0 = -1e30f, m1 = -1e30f, l0 = 0.f, l1 = 0.f;
    const float scale = 0.08838834764831845f;

    for (int kt = 0; kt < 8; kt++) {
        CP_WAIT1();
        __syncthreads();
        if (kt + 2 < 8) load_kv(kt + 2, (kt + 2) % 3);
        else CP_COMMIT();

        if (kt == 0) {
            #pragma unroll
            for (int kc = 0; kc < 8; kc++) {
                const int slab = kc >> 1, ks = kc & 1;
                const int r = wid * 16 + (lane & 15);
                const int ch = ks * 2 + (lane >> 4);
                ldsm_x4(aq[kc][0], aq[kc][1], aq[kc][2], aq[kc][3],
                        smb + slab * 8192 + r * 64 + ((ch ^ (r & 3)) << 4));
            }
        }

        const uint32_t sbk = smb + 32768 + (kt % 3) * FA_STAGE;
        const uint32_t sbv = sbk + 32768;

        float s_acc[16][4];
        #pragma unroll
        for (int nf = 0; nf < 16; nf++)
            #pragma unroll
            for (int t = 0; t < 4; t++) s_acc[nf][t] = 0.f;
        #pragma unroll
        for (int kc = 0; kc < 8; kc++) {
            const int slab = kc >> 1, ks = kc & 1;
            #pragma unroll
            for (int nf = 0; nf < 16; nf++) {
                const int r = nf * 8 + (lane & 7);
                const int ch = ks * 2 + ((lane >> 3) & 1);
                uint32_t b0, b1;
                ldsm_x2(b0, b1, sbk + slab * 8192 + r * 64 + ((ch ^ (r & 3)) << 4));
                mma16816(s_acc[nf], aq[kc][0], aq[kc][1], aq[kc][2], aq[kc][3], b0, b1);
            }
        }

        float mx0 = -1e30f, mx1 = -1e30f;
        #pragma unroll
        for (int nf = 0; nf < 16; nf++) {
            s_acc[nf][0] *= scale; s_acc[nf][1] *= scale;
            s_acc[nf][2] *= scale; s_acc[nf][3] *= scale;
            mx0 = fmaxf(mx0, fmaxf(s_acc[nf][0], s_acc[nf][1]));
            mx1 = fmaxf(mx1, fmaxf(s_acc[nf][2], s_acc[nf][3]));
        }
        mx0 = fmaxf(mx0, __shfl_xor_sync(~0u, mx0, 1));
        mx0 = fmaxf(mx0, __shfl_xor_sync(~0u, mx0, 2));
        mx1 = fmaxf(mx1, __shfl_xor_sync(~0u, mx1, 1));
        mx1 = fmaxf(mx1, __shfl_xor_sync(~0u, mx1, 2));
        const float mn0 = fmaxf(m0, mx0), mn1 = fmaxf(m1, mx1);
        const float a0 = __expf(m0 - mn0), a1 = __expf(m1 - mn1);
        m0 = mn0; m1 = mn1;

        float rs0 = 0.f, rs1 = 0.f;
        #pragma unroll
        for (int nf = 0; nf < 16; nf++) {
            s_acc[nf][0] = __expf(s_acc[nf][0] - mn0);
            s_acc[nf][1] = __expf(s_acc[nf][1] - mn0);
            s_acc[nf][2] = __expf(s_acc[nf][2] - mn1);
            s_acc[nf][3] = __expf(s_acc[nf][3] - mn1);
            rs0 += s_acc[nf][0] + s_acc[nf][1];
            rs1 += s_acc[nf][2] + s_acc[nf][3];
        }
        rs0 += __shfl_xor_sync(~0u, rs0, 1); rs0 += __shfl_xor_sync(~0u, rs0, 2);
        rs1 += __shfl_xor_sync(~0u, rs1, 1); rs1 += __shfl_xor_sync(~0u, rs1, 2);
        l0 = l0 * a0 + rs0; l1 = l1 * a1 + rs1;
        #pragma unroll
        for (int nf = 0; nf < 16; nf++) {
            acc_o[nf][0] *= a0; acc_o[nf][1] *= a0;
            acc_o[nf][2] *= a1; acc_o[nf][3] *= a1;
        }

        #pragma unroll
        for (int kc = 0; kc < 8; kc++) {
            const int slab = kc >> 1, ks = kc & 1;
            __half2 pa0 = __floats2half2_rn(s_acc[2*kc][0],   s_acc[2*kc][1]);
            __half2 pa1 = __floats2half2_rn(s_acc[2*kc][2],   s_acc[2*kc][3]);
            __half2 pa2 = __floats2half2_rn(s_acc[2*kc+1][0], s_acc[2*kc+1][1]);
            __half2 pa3 = __floats2half2_rn(s_acc[2*kc+1][2], s_acc[2*kc+1][3]);
            const uint32_t u0 = *(uint32_t*)&pa0, u1 = *(uint32_t*)&pa1;
            const uint32_t u2 = *(uint32_t*)&pa2, u3 = *(uint32_t*)&pa3;
            #pragma unroll
            for (int nf = 0; nf < 16; nf++) {
                const int r = nf * 8 + (lane & 7);
                const int ch = ks * 2 + ((lane >> 3) & 1);
                uint32_t b0, b1;
                ldsm_x2(b0, b1, sbv + slab * 8192 + r * 64 + ((ch ^ (r & 3)) << 4));
                mma16816(acc_o[nf], u0, u1, u2, u3, b0, b1);
            }
        }
        __syncthreads();
    }

    const float inv0 = 1.f / l0, inv1 = 1.f / l1;
    const size_t zbase = (size_t)z * Sc * DKc;
    const int gr0 = qt * 128 + wid * 16 + (lane >> 2);
    #pragma unroll
    for (int nf = 0; nf < 16; nf++) {
        const int col = nf * 8 + (lane & 3) * 2;
        const size_t i0 = zbase + (size_t)gr0 * DKc + col;
        const size_t i1 = i0 + 8 * DKc;
        float2 r0 = *(const float2*)(x + i0);
        float2 r1 = *(const float2*)(x + i1);
        *(float2*)(x1 + i0) = make_float2(acc_o[nf][0] * inv0 + r0.x, acc_o[nf][1] * inv0 + r0.y);
        *(float2*)(x1 + i1) = make_float2(acc_o[nf][2] * inv1 + r1.x, acc_o[nf][3] * inv1 + r1.y);
    }
}

// ---- layernorm -> fp16 ----
__global__ void __launch_bounds__(256)
ln_half(const float* __restrict__ x, const float* __restrict__ g,
        const float* __restrict__ b, h16* __restrict__ o)
{
    const long long row = blockIdx.x;
    const int tid = threadIdx.x;
    float4 v = *(const float4*)(x + row * Dc + tid * 4);
    float s = v.x+v.y+v.z+v.w, ss = v.x*v.x+v.y*v.y+v.z*v.z+v.w*v.w;
    __shared__ float shs[8], shq[8];
    #pragma unroll
    for (int o2 = 16; o2; o2 >>= 1) { s += __shfl_xor_sync(~0u,s,o2); ss += __shfl_xor_sync(~0u,ss,o2); }
    if ((tid & 31) == 0) { shs[tid>>5] = s; shq[tid>>5] = ss; }
    __syncthreads();
    float st=0.f, qt=0.f;
    #pragma unroll
    for (int i = 0; i < 8; i++) { st += shs[i]; qt += shq[i]; }
    const float m = st * (1.f/Dc), inv = rsqrtf(qt*(1.f/Dc) - m*m + 1e-5f);
    float4 gv = *(const float4*)(g + tid*4);
    float4 bv = *(const float4*)(b + tid*4);
    __half2 h0 = __floats2half2_rn((v.x-m)*inv*gv.x+bv.x, (v.y-m)*inv*gv.y+bv.y);
    __half2 h1 = __floats2half2_rn((v.z-m)*inv*gv.z+bv.z, (v.w-m)*inv*gv.w+bv.w);
    uint2 pk; pk.x = *(uint32_t*)&h0; pk.y = *(uint32_t*)&h1;
    *(uint2*)(o + row*Dc + tid*4) = pk;
}

// ---- fp32 transpose -> fp16 ----
__global__ void __launch_bounds__(256)
transpose_half(const float* __restrict__ in, h16* __restrict__ o, int ldin, int ldo)
{
    __shared__ float t[32][33];
    const int c0 = blockIdx.x * 32, r0 = blockIdx.y * 32;
    const int tx = threadIdx.x, ty = threadIdx.y;
    #pragma unroll
    for (int i = 0; i < 4; i++)
        t[ty + i*8][tx] = in[(size_t)(r0 + ty + i*8) * ldin + c0 + tx];
    __syncthreads();
    #pragma unroll
    for (int i = 0; i < 4; i++)
        o[(size_t)(c0 + ty + i*8) * ldo + r0 + tx] = __float2half_rn(t[tx][ty + i*8]);
}

// ---- fold Wv ----
__global__ void __launch_bounds__(256)
fold_wv(const float* __restrict__ Wv, h16* __restrict__ o)
{
    __shared__ float sf[32][33];
    const int k0 = blockIdx.x * 32, nf0 = blockIdx.y * 32;
    const int tx = threadIdx.x, ty = threadIdx.y;
    #pragma unroll
    for (int rep = 0; rep < 4; rep++) {
        const int row = ty + rep * 8;
        const float* src = Wv + (size_t)(k0 + row) * (Hc*Dc) + (size_t)(nf0 + tx) * 8;
        float4 a = *(const float4*)src;
        float4 b = *(const float4*)(src + 4);
        sf[row][tx] = a.x + a.y + a.z + a.w + b.x + b.y + b.z + b.w;
    }
    __syncthreads();
    #pragma unroll
    for (int rep = 0; rep < 4; rep++) {
        const int nf = ty + rep * 8;
        o[(size_t)(nf0 + nf) * Dc + k0 + tx] = __float2half_rn(sf[tx][nf]);
    }
}

// ---- bias prep ----
__global__ void prep_bias(const float* __restrict__ bq, const float* __restrict__ bk,
                          const float* __restrict__ bv, float* __restrict__ bqkv)
{
    const int i = blockIdx.x * blockDim.x + threadIdx.x;
    bqkv[i] = bq[i];
    bqkv[Dc + i] = bk[i];
    const float* s = bv + (size_t)i * 8;
    float t = 0.f;
    #pragma unroll
    for (int j = 0; j < 8; j++) t += s[j];
    bqkv[2*Dc + i] = t;
}

// ---- fp16 batched transpose ----
__global__ void __launch_bounds__(256)
transpose_h16(const h16* __restrict__ in, h16* __restrict__ o,
              int ldin, int ldo, long long zi0, long long zi1, int innerZ, long long zos)
{
    __shared__ h16 t[32][33];
    const int z = blockIdx.z;
    const long long base = (long long)(z / innerZ) * zi0 + (long long)(z % innerZ) * zi1;
    const int c0 = blockIdx.x * 32, r0 = blockIdx.y * 32;
    const int tx = threadIdx.x, ty = threadIdx.y;
    #pragma unroll
    for (int i = 0; i < 4; i++)
        t[ty + i*8][tx] = in[base + (size_t)(r0 + ty + i*8) * ldin + c0 + tx];
    __syncthreads();
    #pragma unroll
    for (int i = 0; i < 4; i++)
        o[(size_t)z * zos + (size_t)(c0 + ty + i*8) * ldo + r0 + tx] = t[tx][ty + i*8];
}

#define SYM(p, s) cudaGetSymbolAddress((void**)&p, s)

extern "C" void kernel_launch(void* const* d_in, const int* in_sizes, int n_in,
                              void* d_out, int out_size)
{
    (void)in_sizes; (void)n_in; (void)out_size;
    const float* x   = (const float*)d_in[0];
    const float* g1  = (const float*)d_in[2];
    const float* b1  = (const float*)d_in[3];
    const float* Wq  = (const float*)d_in[4];
    const float* bq  = (const float*)d_in[5];
    const float* Wk  = (const float*)d_in[6];
    const float* bk  = (const float*)d_in[7];
    const float* Wv  = (const float*)d_in[8];
    const float* bv  = (const float*)d_in[9];
    const float* g2  = (const float*)d_in[10];
    const float* b2  = (const float*)d_in[11];
    const float* W1  = (const float*)d_in[12];
    const float* bw1 = (const float*)d_in[13];
    const float* W2  = (const float*)d_in[14];
    const float* bw2 = (const float*)d_in[15];
    float* out = (float*)d_out;

    h16 *xn,*xn2,*wqkv,*w1t,*w2t,*qkv,*vft,*ff;
    float *bqkv,*x1;
    SYM(xn,g_xn); SYM(xn2,g_xn2);
    SYM(wqkv,g_wqkv); SYM(bqkv,g_bqkv);
    SYM(w1t,g_W1T); SYM(w2t,g_W2T);
    SYM(qkv,g_qkv); SYM(vft,g_vfT);
    SYM(ff,g_ff); SYM(x1,g_x1);

    cudaFuncSetAttribute(gemm_hmma<0,0>, cudaFuncAttributeMaxDynamicSharedMemorySize, GSMEM);
    cudaFuncSetAttribute(gemm_hmma<0,1>, cudaFuncAttributeMaxDynamicSharedMemorySize, GSMEM);
    cudaFuncSetAttribute(gemm_hmma<1,1>, cudaFuncAttributeMaxDynamicSharedMemorySize, GSMEM);
    cudaFuncSetAttribute(flash_attn,     cudaFuncAttributeMaxDynamicSharedMemorySize, FA_SMEM);

    const dim3 tb(32, 8);
    const size_t DD = (size_t)Dc*Dc;

    prep_bias<<<4, 256>>>(bq, bk, bv, bqkv);
    transpose_half<<<dim3(Dc/32, Dc/32), tb>>>(Wq, wqkv,      Dc, Dc);
    transpose_half<<<dim3(Dc/32, Dc/32), tb>>>(Wk, wqkv+DD,   Dc, Dc);
    fold_wv<<<dim3(32, 32), tb>>>(Wv, wqkv+2*DD);
    transpose_half<<<dim3(FFc/32, Dc/32), tb>>>(W1, w1t, FFc, Dc);
    transpose_half<<<dim3(Dc/32, FFc/32), tb>>>(W2, w2t, Dc,  FFc);

    ln_half<<<TOK, 256>>>(x, g1, b1, xn);

    gemm_hmma<0,1><<<dim3(Dc/128, TOK/128, 3), 256, GSMEM>>>(
        xn, wqkv, bqkv, nullptr, nullptr, qkv,
        Dc, Dc, Dc, Dc,
        0, 0, (long long)DD, 0, (long long)TOK*Dc, 0, 1, 1.0f, (long long)Dc);

    transpose_h16<<<dim3(DKc/32, Sc/32, Bc*Hc), tb>>>(
        qkv + (size_t)2*TOK*Dc, vft,
        Dc, Sc, (long long)Sc*Dc, (long long)DKc, Hc, (long long)DKc*Sc);

    flash_attn<<<dim3(Sc/128, Bc*Hc), 256, FA_SMEM>>>(
        qkv, qkv + (size_t)TOK*Dc, vft, x, x1);

    ln_half<<<TOK, 256>>>(x1, g2, b2, xn2);

    gemm_hmma<1,1><<<dim3(FFc/128, TOK/128, 1), 256, GSMEM>>>(
        xn2, w1t, bw1, nullptr, nullptr, ff,
        Dc, Dc, Dc, FFc, 0,0,0,0,0,0, 1, 1.0f, 0);

    gemm_hmma<0,0><<<dim3(Dc/128, TOK/128, 1), 256, GSMEM>>>(
        ff, w2t, bw2, x1, out, nullptr,
        FFc, FFc, FFc, Dc, 0,0,0,0,0,0, 1, 1.0f, 0);
}

// round 10
// speedup vs baseline: 15.3298x; 1.0184x over previous
#include <cuda_runtime.h>
#include <cuda_fp16.h>
#include <cstdint>
#include <math.h>

#define Bc 4
#define Sc 1024
#define Dc 1024
#define Hc 8
#define DKc 128
#define FFc 4096
#define TOK (Bc*Sc)
typedef __half h16;

// ---- scratch ----
__device__ __align__(16) h16 g_xn [TOK*Dc];
__device__ __align__(16) h16 g_xn2[TOK*Dc];
__device__ __align__(16) h16 g_wqkv[(size_t)3*Dc*Dc];
__device__ __align__(16) float g_bqkv[3*Dc];
__device__ __align__(16) h16 g_W1T[(size_t)FFc*Dc];
__device__ __align__(16) h16 g_W2T[(size_t)Dc*FFc];
__device__ __align__(16) h16 g_qkv[(size_t)3*TOK*Dc];
__device__ __align__(16) h16 g_vfT[(size_t)Bc*Hc*DKc*Sc];
__device__ __align__(16) float g_x1[TOK*Dc];
__device__ __align__(16) h16 g_ff[(size_t)TOK*FFc];

// ---- helpers ----
__device__ __forceinline__ uint32_t smem_u32(const void* p) {
    uint32_t a;
    asm("{ .reg .u64 t; cvta.to.shared.u64 t, %1; cvt.u32.u64 %0, t; }" : "=r"(a) : "l"(p));
    return a;
}
#define CP16(dst, src) asm volatile("cp.async.cg.shared.global [%0], [%1], 16;" :: "r"(dst), "l"(src))
#define CP_COMMIT()    asm volatile("cp.async.commit_group;" ::: "memory")
#define CP_WAIT1()     asm volatile("cp.async.wait_group 1;" ::: "memory")

__device__ __forceinline__ void ldsm_x4(uint32_t& a0, uint32_t& a1, uint32_t& a2, uint32_t& a3, uint32_t addr) {
    asm volatile("ldmatrix.sync.aligned.m8n8.x4.shared.b16 {%0,%1,%2,%3}, [%4];"
                 : "=r"(a0), "=r"(a1), "=r"(a2), "=r"(a3) : "r"(addr));
}
__device__ __forceinline__ void mma16816(float* c, uint32_t a0, uint32_t a1, uint32_t a2, uint32_t a3,
                                         uint32_t b0, uint32_t b1) {
    asm volatile("mma.sync.aligned.m16n8k16.row.col.f32.f16.f16.f32 "
                 "{%0,%1,%2,%3},{%4,%5,%6,%7},{%8,%9},{%0,%1,%2,%3};"
                 : "+f"(c[0]), "+f"(c[1]), "+f"(c[2]), "+f"(c[3])
                 : "r"(a0), "r"(a1), "r"(a2), "r"(a3), "r"(b0), "r"(b1));
}
__device__ __forceinline__ float gelu_exact(float v) {
    return 0.5f * v * (1.0f + erff(v * 0.70710678118654752f));
}

// ---- HMMA fp16 GEMM: 128x128 CTA tile, K-chunk 64, 3-stage cp.async, 2 CTA/SM ----
#define STAGE_B 32768
#define GSMEM   (3*STAGE_B)

template<int ACT, int OUTMODE>
__global__ void __launch_bounds__(256, 2)
gemm_hmma(const h16* __restrict__ Ah, const h16* __restrict__ Bh,
          const float* __restrict__ bias, const float* __restrict__ resid,
          float* __restrict__ C, h16* __restrict__ Ch,
          int K, int lda, int ldb, int ldc,
          long long sA0, long long sA1, long long sB0, long long sB1,
          long long sC0, long long sC1, int innerB, float alpha, long long biasStride)
{
    extern __shared__ char smem[];
    const uint32_t smb = smem_u32(smem);
    const int tid = threadIdx.x, lane = tid & 31, wid = tid >> 5;
    const int z = blockIdx.z, zo = z / innerB, zi = z - zo * innerB;
    const long long aoff = zo * sA0 + zi * sA1;
    const long long boff = zo * sB0 + zi * sB1;
    const long long coff = zo * sC0 + zi * sC1;
    if (bias) bias += (long long)z * biasStride;
    const int m0 = blockIdx.y * 128, n0 = blockIdx.x * 128;
    const int wm = (wid & 1) * 64, wn = (wid >> 1) * 32;

    const int lrow = tid >> 3;
    const int cch  = tid & 7;

    float acc[4][4][4];
    #pragma unroll
    for (int i = 0; i < 4; i++)
        #pragma unroll
        for (int j = 0; j < 4; j++)
            #pragma unroll
            for (int t = 0; t < 4; t++) acc[i][j][t] = 0.f;

    const int nck = K >> 6;

    auto load_chunk = [&](int kk, int s) {
        const int k0 = kk << 6;
        const uint32_t st = smb + s * STAGE_B;
        #pragma unroll
        for (int rep = 0; rep < 4; rep++) {
            const int r = lrow + rep * 32;
            const uint32_t so = r * 128 + ((cch ^ (r & 7)) << 4);
            CP16(st + so,         Ah + (size_t)aoff + (size_t)(m0 + r) * lda + k0 + cch * 8);
            CP16(st + 16384 + so, Bh + (size_t)boff + (size_t)(n0 + r) * ldb + k0 + cch * 8);
        }
        CP_COMMIT();
    };

    load_chunk(0, 0);
    load_chunk(1, 1);

    for (int kk = 0; kk < nck; kk++) {
        CP_WAIT1();
        __syncthreads();
        if (kk + 2 < nck) load_chunk(kk + 2, (kk + 2) % 3);
        else CP_COMMIT();

        const uint32_t st = smb + (kk % 3) * STAGE_B;
        #pragma unroll
        for (int ks = 0; ks < 4; ks++) {
            uint32_t ah[4][4], bh[4][2];
            #pragma unroll
            for (int mf = 0; mf < 4; mf++) {
                const int r = wm + mf * 16 + (lane & 15);
                const int ch = ks * 2 + (lane >> 4);
                ldsm_x4(ah[mf][0], ah[mf][1], ah[mf][2], ah[mf][3],
                        st + r * 128 + ((ch ^ (r & 7)) << 4));
            }
            // B: one x4 fetches two adjacent n-fragments (both k-halves)
            #pragma unroll
            for (int nf2 = 0; nf2 < 2; nf2++) {
                const int r = wn + nf2 * 16 + ((lane >> 4) & 1) * 8 + (lane & 7);
                const int ch = ks * 2 + ((lane >> 3) & 1);
                ldsm_x4(bh[2*nf2][0], bh[2*nf2][1], bh[2*nf2+1][0], bh[2*nf2+1][1],
                        st + 16384 + r * 128 + ((ch ^ (r & 7)) << 4));
            }
            #pragma unroll
            for (int mf = 0; mf < 4; mf++)
                #pragma unroll
                for (int nf = 0; nf < 4; nf++)
                    mma16816(acc[mf][nf], ah[mf][0], ah[mf][1], ah[mf][2], ah[mf][3], bh[nf][0], bh[nf][1]);
        }
        __syncthreads();
    }

    #pragma unroll
    for (int mf = 0; mf < 4; mf++) {
        const int r0 = m0 + wm + mf * 16 + (lane >> 2);
        const int r1 = r0 + 8;
        #pragma unroll
        for (int nf = 0; nf < 4; nf++) {
            const int col = n0 + wn + nf * 8 + (lane & 3) * 2;
            float b0 = 0.f, b1 = 0.f;
            if (bias) { b0 = __ldg(bias + col); b1 = __ldg(bias + col + 1); }
            float v0 = acc[mf][nf][0] * alpha + b0;
            float v1 = acc[mf][nf][1] * alpha + b1;
            float v2 = acc[mf][nf][2] * alpha + b0;
            float v3 = acc[mf][nf][3] * alpha + b1;
            if (ACT == 1) {
                v0 = gelu_exact(v0); v1 = gelu_exact(v1);
                v2 = gelu_exact(v2); v3 = gelu_exact(v3);
            }
            const size_t i0 = (size_t)coff + (size_t)r0 * ldc + col;
            const size_t i1 = (size_t)coff + (size_t)r1 * ldc + col;
            if (OUTMODE == 0) {
                if (resid) {
                    float2 q0 = *(const float2*)(resid + i0);
                    float2 q1 = *(const float2*)(resid + i1);
                    v0 += q0.x; v1 += q0.y; v2 += q1.x; v3 += q1.y;
                }
                *(float2*)(C + i0) = make_float2(v0, v1);
                *(float2*)(C + i1) = make_float2(v2, v3);
            } else {
                __half2 p0 = __floats2half2_rn(v0, v1);
                __half2 p1 = __floats2half2_rn(v2, v3);
                *(__half2*)(Ch + i0) = p0;
                *(__half2*)(Ch + i1) = p1;
            }
        }
    }
}

// ---- fused flash attention ----
#define FA_STAGE 65536
#define FA_SMEM  (32768 + 3*FA_STAGE)

__global__ void __launch_bounds__(256, 1)
flash_attn(const h16* __restrict__ qg, const h16* __restrict__ kg,
           const h16* __restrict__ vfT, const float* __restrict__ x,
           float* __restrict__ x1)
{
    extern __shared__ char smem[];
    const uint32_t smb = smem_u32(smem);
    const int qt = blockIdx.x, z = blockIdx.y;
    const int b = z >> 3, h = z & 7;
    const int tid = threadIdx.x, lane = tid & 31, wid = tid >> 5;

    const size_t qkbase = (size_t)b * Sc * Dc + (size_t)h * DKc;
    const size_t vbase  = (size_t)z * DKc * Sc;

    const int row = tid >> 2;
    const int cch = tid & 3;

    {
        #pragma unroll
        for (int slab = 0; slab < 4; slab++)
            #pragma unroll
            for (int rep = 0; rep < 2; rep++) {
                const int r = row + rep * 64;
                const uint32_t so = slab * 8192 + r * 64 + ((cch ^ (r & 3)) << 4);
                CP16(smb + so, qg + qkbase + (size_t)(qt * 128 + r) * Dc + slab * 32 + cch * 8);
            }
    }
    auto load_kv = [&](int kt, int st) {
        const uint32_t sb = smb + 32768 + st * FA_STAGE;
        #pragma unroll
        for (int slab = 0; slab < 4; slab++)
            #pragma unroll
            for (int rep = 0; rep < 2; rep++) {
                const int r = row + rep * 64;
                const uint32_t so = slab * 8192 + r * 64 + ((cch ^ (r & 3)) << 4);
                CP16(sb + so,         kg  + qkbase + (size_t)(kt * 128 + r) * Dc + slab * 32 + cch * 8);
                CP16(sb + 32768 + so, vfT + vbase  + (size_t)r * Sc + kt * 128 + slab * 32 + cch * 8);
            }
        CP_COMMIT();
    };
    load_kv(0, 0);
    load_kv(1, 1);

    uint32_t aq[8][4];
    float acc_o[16][4];
    #pragma unroll
    for (int nf = 0; nf < 16; nf++)
        #pragma unroll
        for (int t = 0; t < 4; t++) acc_o[nf][t] = 0.f;
    float m0 = -1e30f, m1 = -1e30f, l0 = 0.f, l1 = 0.f;
    const float scale = 0.08838834764831845f;

    for (int kt = 0; kt < 8; kt++) {
        CP_WAIT1();
        __syncthreads();
        if (kt + 2 < 8) load_kv(kt + 2, (kt + 2) % 3);
        else CP_COMMIT();

        if (kt == 0) {
            #pragma unroll
            for (int kc = 0; kc < 8; kc++) {
                const int slab = kc >> 1, ks = kc & 1;
                const int r = wid * 16 + (lane & 15);
                const int ch = ks * 2 + (lane >> 4);
                ldsm_x4(aq[kc][0], aq[kc][1], aq[kc][2], aq[kc][3],
                        smb + slab * 8192 + r * 64 + ((ch ^ (r & 3)) << 4));
            }
        }

        const uint32_t sbk = smb + 32768 + (kt % 3) * FA_STAGE;
        const uint32_t sbv = sbk + 32768;

        float s_acc[16][4];
        #pragma unroll
        for (int nf = 0; nf < 16; nf++)
            #pragma unroll
            for (int t = 0; t < 4; t++) s_acc[nf][t] = 0.f;
        #pragma unroll
        for (int kc = 0; kc < 8; kc++) {
            const int slab = kc >> 1, ks = kc & 1;
            #pragma unroll
            for (int nf2 = 0; nf2 < 8; nf2++) {
                const int r = nf2 * 16 + ((lane >> 4) & 1) * 8 + (lane & 7);
                const int ch = ks * 2 + ((lane >> 3) & 1);
                uint32_t b0, b1, b2, b3;
                ldsm_x4(b0, b1, b2, b3, sbk + slab * 8192 + r * 64 + ((ch ^ (r & 3)) << 4));
                mma16816(s_acc[2*nf2],   aq[kc][0], aq[kc][1], aq[kc][2], aq[kc][3], b0, b1);
                mma16816(s_acc[2*nf2+1], aq[kc][0], aq[kc][1], aq[kc][2], aq[kc][3], b2, b3);
            }
        }

        float mx0 = -1e30f, mx1 = -1e30f;
        #pragma unroll
        for (int nf = 0; nf < 16; nf++) {
            s_acc[nf][0] *= scale; s_acc[nf][1] *= scale;
            s_acc[nf][2] *= scale; s_acc[nf][3] *= scale;
            mx0 = fmaxf(mx0, fmaxf(s_acc[nf][0], s_acc[nf][1]));
            mx1 = fmaxf(mx1, fmaxf(s_acc[nf][2], s_acc[nf][3]));
        }
        mx0 = fmaxf(mx0, __shfl_xor_sync(~0u, mx0, 1));
        mx0 = fmaxf(mx0, __shfl_xor_sync(~0u, mx0, 2));
        mx1 = fmaxf(mx1, __shfl_xor_sync(~0u, mx1, 1));
        mx1 = fmaxf(mx1, __shfl_xor_sync(~0u, mx1, 2));
        const float mn0 = fmaxf(m0, mx0), mn1 = fmaxf(m1, mx1);
        const float a0 = __expf(m0 - mn0), a1 = __expf(m1 - mn1);
        m0 = mn0; m1 = mn1;

        float rs0 = 0.f, rs1 = 0.f;
        #pragma unroll
        for (int nf = 0; nf < 16; nf++) {
            s_acc[nf][0] = __expf(s_acc[nf][0] - mn0);
            s_acc[nf][1] = __expf(s_acc[nf][1] - mn0);
            s_acc[nf][2] = __expf(s_acc[nf][2] - mn1);
            s_acc[nf][3] = __expf(s_acc[nf][3] - mn1);
            rs0 += s_acc[nf][0] + s_acc[nf][1];
            rs1 += s_acc[nf][2] + s_acc[nf][3];
        }
        rs0 += __shfl_xor_sync(~0u, rs0, 1); rs0 += __shfl_xor_sync(~0u, rs0, 2);
        rs1 += __shfl_xor_sync(~0u, rs1, 1); rs1 += __shfl_xor_sync(~0u, rs1, 2);
        l0 = l0 * a0 + rs0; l1 = l1 * a1 + rs1;
        #pragma unroll
        for (int nf = 0; nf < 16; nf++) {
            acc_o[nf][0] *= a0; acc_o[nf][1] *= a0;
            acc_o[nf][2] *= a1; acc_o[nf][3] *= a1;
        }

        #pragma unroll
        for (int kc = 0; kc < 8; kc++) {
            const int slab = kc >> 1, ks = kc & 1;
            __half2 pa0 = __floats2half2_rn(s_acc[2*kc][0],   s_acc[2*kc][1]);
            __half2 pa1 = __floats2half2_rn(s_acc[2*kc][2],   s_acc[2*kc][3]);
            __half2 pa2 = __floats2half2_rn(s_acc[2*kc+1][0], s_acc[2*kc+1][1]);
            __half2 pa3 = __floats2half2_rn(s_acc[2*kc+1][2], s_acc[2*kc+1][3]);
            const uint32_t u0 = *(uint32_t*)&pa0, u1 = *(uint32_t*)&pa1;
            const uint32_t u2 = *(uint32_t*)&pa2, u3 = *(uint32_t*)&pa3;
            #pragma unroll
            for (int nf2 = 0; nf2 < 8; nf2++) {
                const int r = nf2 * 16 + ((lane >> 4) & 1) * 8 + (lane & 7);
                const int ch = ks * 2 + ((lane >> 3) & 1);
                uint32_t b0, b1, b2, b3;
                ldsm_x4(b0, b1, b2, b3, sbv + slab * 8192 + r * 64 + ((ch ^ (r & 3)) << 4));
                mma16816(acc_o[2*nf2],   u0, u1, u2, u3, b0, b1);
                mma16816(acc_o[2*nf2+1], u0, u1, u2, u3, b2, b3);
            }
        }
        __syncthreads();
    }

    const float inv0 = 1.f / l0, inv1 = 1.f / l1;
    const size_t zbase = (size_t)z * Sc * DKc;
    const int gr0 = qt * 128 + wid * 16 + (lane >> 2);
    #pragma unroll
    for (int nf = 0; nf < 16; nf++) {
        const int col = nf * 8 + (lane & 3) * 2;
        const size_t i0 = zbase + (size_t)gr0 * DKc + col;
        const size_t i1 = i0 + 8 * DKc;
        float2 r0 = *(const float2*)(x + i0);
        float2 r1 = *(const float2*)(x + i1);
        *(float2*)(x1 + i0) = make_float2(acc_o[nf][0] * inv0 + r0.x, acc_o[nf][1] * inv0 + r0.y);
        *(float2*)(x1 + i1) = make_float2(acc_o[nf][2] * inv1 + r1.x, acc_o[nf][3] * inv1 + r1.y);
    }
}

// ---- layernorm -> fp16 ----
__global__ void __launch_bounds__(256)
ln_half(const float* __restrict__ x, const float* __restrict__ g,
        const float* __restrict__ b, h16* __restrict__ o)
{
    const long long row = blockIdx.x;
    const int tid = threadIdx.x;
    float4 v = *(const float4*)(x + row * Dc + tid * 4);
    float s = v.x+v.y+v.z+v.w, ss = v.x*v.x+v.y*v.y+v.z*v.z+v.w*v.w;
    __shared__ float shs[8], shq[8];
    #pragma unroll
    for (int o2 = 16; o2; o2 >>= 1) { s += __shfl_xor_sync(~0u,s,o2); ss += __shfl_xor_sync(~0u,ss,o2); }
    if ((tid & 31) == 0) { shs[tid>>5] = s; shq[tid>>5] = ss; }
    __syncthreads();
    float st=0.f, qt=0.f;
    #pragma unroll
    for (int i = 0; i < 8; i++) { st += shs[i]; qt += shq[i]; }
    const float m = st * (1.f/Dc), inv = rsqrtf(qt*(1.f/Dc) - m*m + 1e-5f);
    float4 gv = *(const float4*)(g + tid*4);
    float4 bv = *(const float4*)(b + tid*4);
    __half2 h0 = __floats2half2_rn((v.x-m)*inv*gv.x+bv.x, (v.y-m)*inv*gv.y+bv.y);
    __half2 h1 = __floats2half2_rn((v.z-m)*inv*gv.z+bv.z, (v.w-m)*inv*gv.w+bv.w);
    uint2 pk; pk.x = *(uint32_t*)&h0; pk.y = *(uint32_t*)&h1;
    *(uint2*)(o + row*Dc + tid*4) = pk;
}

// ---- fp32 transpose -> fp16 ----
__global__ void __launch_bounds__(256)
transpose_half(const float* __restrict__ in, h16* __restrict__ o, int ldin, int ldo)
{
    __shared__ float t[32][33];
    const int c0 = blockIdx.x * 32, r0 = blockIdx.y * 32;
    const int tx = threadIdx.x, ty = threadIdx.y;
    #pragma unroll
    for (int i = 0; i < 4; i++)
        t[ty + i*8][tx] = in[(size_t)(r0 + ty + i*8) * ldin + c0 + tx];
    __syncthreads();
    #pragma unroll
    for (int i = 0; i < 4; i++)
        o[(size_t)(c0 + ty + i*8) * ldo + r0 + tx] = __float2half_rn(t[tx][ty + i*8]);
}

// ---- fold Wv ----
__global__ void __launch_bounds__(256)
fold_wv(const float* __restrict__ Wv, h16* __restrict__ o)
{
    __shared__ float sf[32][33];
    const int k0 = blockIdx.x * 32, nf0 = blockIdx.y * 32;
    const int tx = threadIdx.x, ty = threadIdx.y;
    #pragma unroll
    for (int rep = 0; rep < 4; rep++) {
        const int row = ty + rep * 8;
        const float* src = Wv + (size_t)(k0 + row) * (Hc*Dc) + (size_t)(nf0 + tx) * 8;
        float4 a = *(const float4*)src;
        float4 b = *(const float4*)(src + 4);
        sf[row][tx] = a.x + a.y + a.z + a.w + b.x + b.y + b.z + b.w;
    }
    __syncthreads();
    #pragma unroll
    for (int rep = 0; rep < 4; rep++) {
        const int nf = ty + rep * 8;
        o[(size_t)(nf0 + nf) * Dc + k0 + tx] = __float2half_rn(sf[tx][nf]);
    }
}

// ---- bias prep ----
__global__ void prep_bias(const float* __restrict__ bq, const float* __restrict__ bk,
                          const float* __restrict__ bv, float* __restrict__ bqkv)
{
    const int i = blockIdx.x * blockDim.x + threadIdx.x;
    bqkv[i] = bq[i];
    bqkv[Dc + i] = bk[i];
    const float* s = bv + (size_t)i * 8;
    float t = 0.f;
    #pragma unroll
    for (int j = 0; j < 8; j++) t += s[j];
    bqkv[2*Dc + i] = t;
}

// ---- fp16 batched transpose ----
__global__ void __launch_bounds__(256)
transpose_h16(const h16* __restrict__ in, h16* __restrict__ o,
              int ldin, int ldo, long long zi0, long long zi1, int innerZ, long long zos)
{
    __shared__ h16 t[32][33];
    const int z = blockIdx.z;
    const long long base = (long long)(z / innerZ) * zi0 + (long long)(z % innerZ) * zi1;
    const int c0 = blockIdx.x * 32, r0 = blockIdx.y * 32;
    const int tx = threadIdx.x, ty = threadIdx.y;
    #pragma unroll
    for (int i = 0; i < 4; i++)
        t[ty + i*8][tx] = in[base + (size_t)(r0 + ty + i*8) * ldin + c0 + tx];
    __syncthreads();
    #pragma unroll
    for (int i = 0; i < 4; i++)
        o[(size_t)z * zos + (size_t)(c0 + ty + i*8) * ldo + r0 + tx] = t[tx][ty + i*8];
}

#define SYM(p, s) cudaGetSymbolAddress((void**)&p, s)

extern "C" void kernel_launch(void* const* d_in, const int* in_sizes, int n_in,
                              void* d_out, int out_size)
{
    (void)in_sizes; (void)n_in; (void)out_size;
    const float* x   = (const float*)d_in[0];
    const float* g1  = (const float*)d_in[2];
    const float* b1  = (const float*)d_in[3];
    const float* Wq  = (const float*)d_in[4];
    const float* bq  = (const float*)d_in[5];
    const float* Wk  = (const float*)d_in[6];
    const float* bk  = (const float*)d_in[7];
    const float* Wv  = (const float*)d_in[8];
    const float* bv  = (const float*)d_in[9];
    const float* g2  = (const float*)d_in[10];
    const float* b2  = (const float*)d_in[11];
    const float* W1  = (const float*)d_in[12];
    const float* bw1 = (const float*)d_in[13];
    const float* W2  = (const float*)d_in[14];
    const float* bw2 = (const float*)d_in[15];
    float* out = (float*)d_out;

    h16 *xn,*xn2,*wqkv,*w1t,*w2t,*qkv,*vft,*ff;
    float *bqkv,*x1;
    SYM(xn,g_xn); SYM(xn2,g_xn2);
    SYM(wqkv,g_wqkv); SYM(bqkv,g_bqkv);
    SYM(w1t,g_W1T); SYM(w2t,g_W2T);
    SYM(qkv,g_qkv); SYM(vft,g_vfT);
    SYM(ff,g_ff); SYM(x1,g_x1);

    cudaFuncSetAttribute(gemm_hmma<0,0>, cudaFuncAttributeMaxDynamicSharedMemorySize, GSMEM);
    cudaFuncSetAttribute(gemm_hmma<0,1>, cudaFuncAttributeMaxDynamicSharedMemorySize, GSMEM);
    cudaFuncSetAttribute(gemm_hmma<1,1>, cudaFuncAttributeMaxDynamicSharedMemorySize, GSMEM);
    cudaFuncSetAttribute(flash_attn,     cudaFuncAttributeMaxDynamicSharedMemorySize, FA_SMEM);

    const dim3 tb(32, 8);
    const size_t DD = (size_t)Dc*Dc;

    prep_bias<<<4, 256>>>(bq, bk, bv, bqkv);
    transpose_half<<<dim3(Dc/32, Dc/32), tb>>>(Wq, wqkv,      Dc, Dc);
    transpose_half<<<dim3(Dc/32, Dc/32), tb>>>(Wk, wqkv+DD,   Dc, Dc);
    fold_wv<<<dim3(32, 32), tb>>>(Wv, wqkv+2*DD);
    transpose_half<<<dim3(FFc/32, Dc/32), tb>>>(W1, w1t, FFc, Dc);
    transpose_half<<<dim3(Dc/32, FFc/32), tb>>>(W2, w2t, Dc,  FFc);

    ln_half<<<TOK, 256>>>(x, g1, b1, xn);

    gemm_hmma<0,1><<<dim3(Dc/128, TOK/128, 3), 256, GSMEM>>>(
        xn, wqkv, bqkv, nullptr, nullptr, qkv,
        Dc, Dc, Dc, Dc,
        0, 0, (long long)DD, 0, (long long)TOK*Dc, 0, 1, 1.0f, (long long)Dc);

    transpose_h16<<<dim3(DKc/32, Sc/32, Bc*Hc), tb>>>(
        qkv + (size_t)2*TOK*Dc, vft,
        Dc, Sc, (long long)Sc*Dc, (long long)DKc, Hc, (long long)DKc*Sc);

    flash_attn<<<dim3(Sc/128, Bc*Hc), 256, FA_SMEM>>>(
        qkv, qkv + (size_t)TOK*Dc, vft, x, x1);

    ln_half<<<TOK, 256>>>(x1, g2, b2, xn2);

    gemm_hmma<1,1><<<dim3(FFc/128, TOK/128, 1), 256, GSMEM>>>(
        xn2, w1t, bw1, nullptr, nullptr, ff,
        Dc, Dc, Dc, FFc, 0,0,0,0,0,0, 1, 1.0f, 0);

    gemm_hmma<0,0><<<dim3(Dc/128, TOK/128, 1), 256, GSMEM>>>(
        ff, w2t, bw2, x1, out, nullptr,
        FFc, FFc, FFc, Dc, 0,0,0,0,0,0, 1, 1.0f, 0);
}